// round 11
// baseline (speedup 1.0000x reference)
#include <cuda_runtime.h>
#include <cuda_bf16.h>
#include <cuda_fp16.h>
#include <math.h>
#include <stdint.h>

#define Bq   8
#define Nn   1024
#define Dm   896
#define Hh   14
#define Dh   64
#define BN   (Bq*Nn)
#define KCAT 2688
#define EPITCH 132
#define STG  20480

__device__ __align__(128) __nv_bfloat16 g_xcat[(size_t)BN*KCAT];
__device__ __align__(128) __nv_bfloat16 g_wqkv[(size_t)KCAT*KCAT];
__device__ __align__(128) __nv_bfloat16 g_wocat[(size_t)Dm*KCAT];
__device__ __align__(128) __nv_bfloat16 g_aocat[(size_t)BN*KCAT];
__device__ __align__(128) __nv_bfloat16 g_Qc[(size_t)Bq*Hh*Nn*128];
__device__ __align__(128) __nv_bfloat16 g_Kc[(size_t)Bq*Hh*Nn*128];
__device__ __align__(128) __nv_bfloat16 g_Vc[(size_t)Bq*Hh*Nn*128];
__device__ __half g_bias[(size_t)Bq*Hh*Nn*Nn];   // masked wind bias, f16
__device__ float g_cos[Nn*32];
__device__ float g_sin[Nn*32];

__device__ __forceinline__ uint32_t smem_u32(const void* p) {
    uint32_t a;
    asm("{ .reg .u64 t; cvta.to.shared.u64 t, %1; cvt.u32.u64 %0, t; }" : "=r"(a) : "l"(p));
    return a;
}
__device__ __forceinline__ void cp_async16(uint32_t dst, const void* src) {
    asm volatile("cp.async.cg.shared.global [%0], [%1], 16;" :: "r"(dst), "l"(src));
}
#define CP_COMMIT() asm volatile("cp.async.commit_group;" ::: "memory")
#define CP_WAIT0()  asm volatile("cp.async.wait_group 0;" ::: "memory")
#define CP_WAIT1()  asm volatile("cp.async.wait_group 1;" ::: "memory")

__device__ __forceinline__ void ldsm_x4(uint32_t a, uint32_t* r) {
    asm volatile("ldmatrix.sync.aligned.m8n8.x4.shared.b16 {%0,%1,%2,%3}, [%4];"
                 : "=r"(r[0]), "=r"(r[1]), "=r"(r[2]), "=r"(r[3]) : "r"(a));
}
__device__ __forceinline__ void ldsm_x2(uint32_t a, uint32_t* r) {
    asm volatile("ldmatrix.sync.aligned.m8n8.x2.shared.b16 {%0,%1}, [%2];"
                 : "=r"(r[0]), "=r"(r[1]) : "r"(a));
}
__device__ __forceinline__ void ldsm_x4t(uint32_t a, uint32_t* r) {
    asm volatile("ldmatrix.sync.aligned.m8n8.x4.trans.shared.b16 {%0,%1,%2,%3}, [%4];"
                 : "=r"(r[0]), "=r"(r[1]), "=r"(r[2]), "=r"(r[3]) : "r"(a));
}
__device__ __forceinline__ void mma16816(float* c, const uint32_t* a, const uint32_t* b) {
    asm volatile("mma.sync.aligned.m16n8k16.row.col.f32.bf16.bf16.f32 "
                 "{%0,%1,%2,%3},{%4,%5,%6,%7},{%8,%9},{%0,%1,%2,%3};"
                 : "+f"(c[0]), "+f"(c[1]), "+f"(c[2]), "+f"(c[3])
                 : "r"(a[0]), "r"(a[1]), "r"(a[2]), "r"(a[3]), "r"(b[0]), "r"(b[1]));
}
__device__ __forceinline__ uint32_t packbf(float lo, float hi) {
    uint32_t r; asm("cvt.rn.bf16x2.f32 %0, %1, %2;" : "=r"(r) : "f"(hi), "f"(lo)); return r;
}

__device__ __forceinline__ float fexp(float x) {
    x = fmaxf(x, -80.f);
    float y = x * 1.442695041f;
    float n = rintf(y);
    float f = y - n;
    float p =            1.8775767e-3f;
    p = fmaf(p, f, 8.9893397e-3f);
    p = fmaf(p, f, 5.5826318e-2f);
    p = fmaf(p, f, 2.4015361e-1f);
    p = fmaf(p, f, 6.9315308e-1f);
    p = fmaf(p, f, 9.9999994e-1f);
    return __int_as_float(__float_as_int(p) + ((int)n << 23));
}
__device__ __forceinline__ float ftanh(float x) {
    float ax = fabsf(x);
    float e = fexp(-2.f * ax);
    float d = 1.f + e;
    float r = fmaf(-0.5f, d, 1.4571f);
    r = r * fmaf(-d, r, 2.f);
    r = r * fmaf(-d, r, 2.f);
    r = r * fmaf(-d, r, 2.f);
    float t = (1.f - e) * r;
    return (x >= 0.f) ? t : -t;
}
__device__ __forceinline__ void split3(__nv_bfloat16* p, float v) {
    __nv_bfloat16 hi = __float2bfloat16(v);
    __nv_bfloat16 lo = __float2bfloat16(v - __bfloat162float(hi));
    p[0] = hi; p[Dm] = hi; p[2*Dm] = lo;
}
__device__ __forceinline__ void psplit(float x, float y, uint32_t& hi, uint32_t& lo) {
    float hx = __bfloat162float(__float2bfloat16(x));
    float hy = __bfloat162float(__float2bfloat16(y));
    hi = packbf(x, y);
    lo = packbf(x - hx, y - hy);
}

// -------- prep: weight packs + rope tables + layernorm(split) --------
#define NB_WQKV 28224
#define NB_WO   9408
#define NB_ROPE 128
__global__ void prep_kernel(const float* __restrict__ Wq, const float* __restrict__ Wk,
                            const float* __restrict__ Wv, const float* __restrict__ Wo,
                            const float* __restrict__ x, const float* __restrict__ lng,
                            const float* __restrict__ lnb,
                            __nv_bfloat16* __restrict__ wqkv, __nv_bfloat16* __restrict__ wocat,
                            float* __restrict__ cc, float* __restrict__ ss,
                            __nv_bfloat16* __restrict__ y)
{
    int bid = blockIdx.x, tid = threadIdx.x;
    if (bid < NB_WQKV) {
        size_t idx = (size_t)bid * 256 + tid;
        int k = (int)(idx % KCAT), n = (int)(idx / KCAT);
        const float* W = (n < Dm) ? Wq : ((n < 2*Dm) ? Wk : Wv);
        int c = n % Dm, kr = k % Dm, blk = k / Dm;
        float w = W[(size_t)kr * Dm + c];
        __nv_bfloat16 hi = __float2bfloat16(w);
        wqkv[idx] = (blk == 1) ? __float2bfloat16(w - __bfloat162float(hi)) : hi;
    } else if (bid < NB_WQKV + NB_WO) {
        size_t idx = (size_t)(bid - NB_WQKV) * 256 + tid;
        int k = (int)(idx % KCAT), n = (int)(idx / KCAT);
        int kr = k % Dm, blk = k / Dm;
        float w = Wo[(size_t)kr * Dm + n];
        __nv_bfloat16 hi = __float2bfloat16(w);
        wocat[idx] = (blk == 1) ? __float2bfloat16(w - __bfloat162float(hi)) : hi;
    } else if (bid < NB_WQKV + NB_WO + NB_ROPE) {
        int i = (bid - NB_WQKV - NB_WO) * 256 + tid;
        int n = i >> 5, d = i & 31;
        float freq = (float)n * powf(10000.f, -(float)(2*d) / 64.f);
        cc[i] = cosf(freq);
        ss[i] = sinf(freq);
    } else {
        int row = bid - (NB_WQKV + NB_WO + NB_ROPE);
        const float* xr = x + (size_t)row * Dm;
        float s = 0.f, s2 = 0.f;
        for (int i = tid; i < Dm; i += 256) { float v = xr[i]; s += v; s2 += v*v; }
        #pragma unroll
        for (int o = 16; o; o >>= 1) { s += __shfl_xor_sync(~0u, s, o); s2 += __shfl_xor_sync(~0u, s2, o); }
        __shared__ float ws[8], ws2[8];
        int w = tid >> 5;
        if ((tid & 31) == 0) { ws[w] = s; ws2[w] = s2; }
        __syncthreads();
        if (tid < 32) {
            s  = (tid < 8) ? ws[tid]  : 0.f;
            s2 = (tid < 8) ? ws2[tid] : 0.f;
            #pragma unroll
            for (int o = 4; o; o >>= 1) { s += __shfl_xor_sync(~0u, s, o); s2 += __shfl_xor_sync(~0u, s2, o); }
            if (tid == 0) { ws[0] = s; ws2[0] = s2; }
        }
        __syncthreads();
        float mu  = ws[0] * (1.f/Dm);
        float var = ws2[0] * (1.f/Dm) - mu*mu;
        float inv = rsqrtf(var + 1e-5f);
        __nv_bfloat16* yr = y + (size_t)row * KCAT;
        for (int i = tid; i < Dm; i += 256) {
            float v = (xr[i] - mu) * inv * lng[i] + lnb[i];
            split3(yr + i, v);
        }
    }
}

// -------- bias precompute (f16 output) --------
__global__ void bias_kernel(const float* __restrict__ bear, const float* __restrict__ wd,
                            const float* __restrict__ adj, const float* __restrict__ ww,
                            const float* __restrict__ wbv, __half* __restrict__ bias)
{
    int t = blockIdx.x;
    int b = blockIdx.y;
    int q0 = (t >> 5) * 32, k0 = (t & 31) * 32;
    __shared__ float tile[32][33];
    __shared__ float w0s[Hh], w1s[Hh], wbs[Hh];
    int tid = threadIdx.x;
    int j = tid & 31, i = tid >> 5;
    if (tid < Hh) { w0s[tid] = ww[tid]; w1s[tid] = ww[Hh + tid]; wbs[tid] = wbv[tid]; }
    #pragma unroll
    for (int p = 0; p < 4; p++)
        tile[i + p*8][j] = bear[(size_t)(k0 + i + p*8) * Nn + q0 + j];
    __syncthreads();
    #pragma unroll
    for (int p = 0; p < 4; p++) {
        int qi = i + p*8;
        int q = q0 + qi, k = k0 + j;
        float rb = fmodf(tile[j][qi] + 180.f, 360.f);
        float av = cosf((wd[b*Nn + q] - rb) * 0.017453292519943295f);
        float a  = adj[(size_t)q * Nn + k];
        bool on = (a > 0.f);
        size_t base = ((size_t)q << 10) + k;
        #pragma unroll
        for (int h = 0; h < Hh; h++) {
            float bv = on ? ftanh(fmaf(av, w0s[h], fmaf(a, w1s[h], wbs[h]))) : -1e30f;
            bias[(((size_t)(b*Hh + h)) << 20) + base] = __float2half(bv);
        }
    }
}

// -------- gemm stage loader --------
__device__ __forceinline__ void load_stage(uint32_t abase, uint32_t bbase,
                                           const __nv_bfloat16* __restrict__ A,
                                           const __nv_bfloat16* __restrict__ Bw,
                                           int m0, int n0, int k0)
{
    int tid = threadIdx.x;
    #pragma unroll
    for (int p = 0; p < 2; p++) {
        int e = p * 256 + tid;
        int r = e >> 2, seg = e & 3;
        cp_async16(abase + r * 80 + seg * 16, A + (size_t)(m0 + r) * KCAT + k0 + seg * 8);
    }
    #pragma unroll
    for (int p = 0; p < 2; p++) {
        int e = p * 256 + tid;
        int r = e >> 2, seg = e & 3;
        cp_async16(bbase + r * 80 + seg * 16, Bw + (size_t)(n0 + r) * KCAT + k0 + seg * 8);
    }
}

// -------- mma GEMM --------
template<int MODE>
__global__ void __launch_bounds__(256, 2)
gemm_mma(const __nv_bfloat16* __restrict__ A, const __nv_bfloat16* __restrict__ Bw,
         const float* __restrict__ cosp, const float* __restrict__ sinp,
         const float* __restrict__ res, void* outQ, void* outK, void* outV)
{
    extern __shared__ char dsm[];
    uint32_t sb = smem_u32(dsm);
    float* sep = (float*)dsm;

    int tid = threadIdx.x, wid = tid >> 5, lane = tid & 31;
    int wm = wid >> 2, wn = wid & 3;
    int m0 = blockIdx.y * 128, n0 = blockIdx.x * 128;

    float acc[4][4][4];
    #pragma unroll
    for (int i = 0; i < 4; i++)
        #pragma unroll
        for (int j = 0; j < 4; j++)
            #pragma unroll
            for (int r = 0; r < 4; r++) acc[i][j][r] = 0.f;

    int gq = lane >> 3, lr = lane & 7;
    uint32_t a_off = (uint32_t)((wm*64 + lr + (gq & 1)*8) * 80 + (gq >> 1)*16);
    uint32_t b_off = (uint32_t)((wn*32 + lr) * 80 + ((lane & 8) ? 16 : 0));

    load_stage(sb + 0*STG, sb + 0*STG + 10240, A, Bw, m0, n0, 0);
    CP_COMMIT();
    load_stage(sb + 1*STG, sb + 1*STG + 10240, A, Bw, m0, n0, 32);
    CP_COMMIT();

    const int NT = KCAT / 32;
    int slot = 0;
    for (int i = 0; i < NT; i++) {
        if (i + 1 < NT) CP_WAIT1(); else CP_WAIT0();
        __syncthreads();
        uint32_t ab = sb + slot * STG, bb = ab + 10240;
        #pragma unroll
        for (int ks = 0; ks < 2; ks++) {
            uint32_t afr[4][4], bfr[4][2];
            #pragma unroll
            for (int mt = 0; mt < 4; mt++) ldsm_x4(ab + a_off + mt*(16*80) + ks*32, afr[mt]);
            #pragma unroll
            for (int nt = 0; nt < 4; nt++) ldsm_x2(bb + b_off + nt*(8*80) + ks*32, bfr[nt]);
            #pragma unroll
            for (int mt = 0; mt < 4; mt++)
                #pragma unroll
                for (int nt = 0; nt < 4; nt++)
                    mma16816(acc[mt][nt], afr[mt], bfr[nt]);
        }
        if (i + 2 < NT) {
            int ns = slot + 2; if (ns >= 3) ns -= 3;
            uint32_t nb = sb + ns * STG;
            load_stage(nb, nb + 10240, A, Bw, m0, n0, (i + 2) * 32);
            CP_COMMIT();
        }
        slot++; if (slot == 3) slot = 0;
    }
    __syncthreads();

    #pragma unroll
    for (int half = 0; half < 2; half++) {
        if (wm == half) {
            #pragma unroll
            for (int mt = 0; mt < 4; mt++)
                #pragma unroll
                for (int nt = 0; nt < 4; nt++)
                    #pragma unroll
                    for (int ri = 0; ri < 4; ri++) {
                        int r = mt*16 + (lane >> 2) + ((ri >> 1) * 8);
                        int n = wn*32 + nt*8 + ((lane & 3) * 2) + (ri & 1);
                        sep[r * EPITCH + n] = acc[mt][nt][ri];
                    }
        }
        __syncthreads();

        if (MODE == 0) {
            int tile = blockIdx.x;
            int region = tile / 7;
            int cbase = (tile % 7) * 128;
            __nv_bfloat16* base = (region == 0) ? (__nv_bfloat16*)outQ
                                : (region == 1) ? (__nv_bfloat16*)outK
                                                : (__nv_bfloat16*)outV;
            for (int idx = tid; idx < 64*128; idx += 256) {
                int r = idx >> 7, c = idx & 127;
                int m = m0 + half*64 + r;
                int bqi = m >> 10, n = m & 1023;
                int ccx = cbase + c;
                int head = ccx >> 6, d = ccx & 63;
                float val;
                if (region < 2) {
                    if (d < 32) {
                        float x1 = sep[r*EPITCH + c], x2 = sep[r*EPITCH + c + 32];
                        val = x1 * cosp[n*32 + d] - x2 * sinp[n*32 + d];
                    } else {
                        float x2 = sep[r*EPITCH + c], x1 = sep[r*EPITCH + c - 32];
                        int dd = d - 32;
                        val = x2 * cosp[n*32 + dd] + x1 * sinp[n*32 + dd];
                    }
                } else {
                    val = sep[r*EPITCH + c];
                }
                __nv_bfloat16 hv = __float2bfloat16(val);
                __nv_bfloat16 lv = __float2bfloat16(val - __bfloat162float(hv));
                size_t row = ((size_t)bqi * Hh + head) * Nn + n;
                base[row*128 + d]      = hv;
                base[row*128 + 64 + d] = lv;
            }
        } else {
            float* outp = (float*)outQ;
            for (int idx = tid; idx < 64*128; idx += 256) {
                int r = idx >> 7, c = idx & 127;
                int m = m0 + half*64 + r;
                size_t o = (size_t)m * Dm + n0 + c;
                outp[o] = sep[r*EPITCH + c] + res[o];
            }
        }
        __syncthreads();
    }
}

// -------- flash attn chunk loader: 128 rows x 256B, pitch 272, 512 threads --------
__device__ __forceinline__ void ld_chunk128(uint32_t dst, const __nv_bfloat16* __restrict__ src,
                                            int tok0)
{
    #pragma unroll
    for (int p = 0; p < 4; p++) {
        int e = p * 512 + threadIdx.x;
        int r = e >> 4, s = e & 15;
        cp_async16(dst + r * 272 + s * 16, src + (size_t)(tok0 + r) * 128 + s * 8);
    }
}

// -------- single-pass flash attention: block (b,h,32q), 512 threads, occ 2 --------
// warp: qh = wid>>3 (16-query half), tw = wid&7 (16-token window within 128-chunk)
// smem: Q 32x272 (8704) | bufA 128x272 (34816) | bufB 128x272 | mrow[256] srow[256] Sfin[32]
__global__ void __launch_bounds__(512, 2)
attn_flash(const __nv_bfloat16* __restrict__ Qc, const __nv_bfloat16* __restrict__ Kc,
           const __nv_bfloat16* __restrict__ Vc, const __half* __restrict__ bias,
           __nv_bfloat16* __restrict__ out)
{
    extern __shared__ char dsm[];
    uint32_t sb = smem_u32(dsm);
    uint32_t qs = sb;
    uint32_t bufA = sb + 8704;
    uint32_t bufB = bufA + 34816;
    float* part = (float*)dsm;                           // overlays everything at merge
    float* mrow = (float*)(dsm + 8704 + 2*34816);        // [16][16]
    float* srow = mrow + 256;                            // [16][16]
    float* Sfin = srow + 256;                            // [32]

    int tid = threadIdx.x, wid = tid >> 5, lane = tid & 31;
    int qh = wid >> 3, tw = wid & 7;
    int h = blockIdx.y, b = blockIdx.z;
    int q0 = blockIdx.x * 32;
    size_t bh = ((size_t)b * Hh + h) * Nn;
    const __nv_bfloat16* Kbh = Kc + bh * 128;
    const __nv_bfloat16* Vbh = Vc + bh * 128;
    const __half* biasbh = bias + (((size_t)(b*Hh + h)) << 20);

    {   // Q tile: 32 rows x 16 segs = 512 transfers
        int r = tid >> 4, s = tid & 15;
        cp_async16(qs + r*272 + s*16, Qc + (bh + q0 + r) * 128 + s * 8);
    }
    CP_COMMIT();
    ld_chunk128(bufA, Kbh, 0); CP_COMMIT();   // K0
    ld_chunk128(bufB, Vbh, 0); CP_COMMIT();   // V0

    int r_ = lane >> 2, cl = 2*(lane & 3);

    // bias pointers: this warp's (q-half rows, token window)
    const __half* bb0 = biasbh + (((size_t)(q0 + qh*16 + r_))     << 10) + tw*16;
    const __half* bb1 = biasbh + (((size_t)(q0 + qh*16 + r_ + 8)) << 10) + tw*16;
    __half2 nb00 = *(const __half2*)(bb0 + cl);
    __half2 nb01 = *(const __half2*)(bb0 + cl + 8);
    __half2 nb10 = *(const __half2*)(bb1 + cl);
    __half2 nb11 = *(const __half2*)(bb1 + cl + 8);

    float m0 = -1e30f, m1 = -1e30f, sum0 = 0.f, sum1 = 0.f;
    float acc[8][4];
    #pragma unroll
    for (int i = 0; i < 8; i++)
        #pragma unroll
        for (int r = 0; r < 4; r++) acc[i][r] = 0.f;
    uint32_t afr[8][4];

    for (int c = 0; c < 8; c++) {
        float2 u00 = __half22float2(nb00), u01 = __half22float2(nb01);
        float2 u10 = __half22float2(nb10), u11 = __half22float2(nb11);
        if (c < 7) {
            int o = (c + 1) * 128;
            nb00 = *(const __half2*)(bb0 + o + cl);
            nb01 = *(const __half2*)(bb0 + o + cl + 8);
            nb10 = *(const __half2*)(bb1 + o + cl);
            nb11 = *(const __half2*)(bb1 + o + cl + 8);
        }
        CP_WAIT1();              // K_c done (V_c pending)
        __syncthreads();
        if (c == 0) {            // hoist Q fragments (this warp's q-half)
            int gq = lane >> 3, lr = lane & 7;
            uint32_t a_off = qs + (uint32_t)((qh*16 + lr + (gq & 1)*8) * 272 + (gq >> 1)*16);
            #pragma unroll
            for (int kt = 0; kt < 8; kt++) ldsm_x4(a_off + kt*32, afr[kt]);
        }

        // ---- scores S (16x16) for this warp's (q-half, token window) ----
        float dd0[4] = {0.f,0.f,0.f,0.f}, dd1[4] = {0.f,0.f,0.f,0.f};
        #pragma unroll
        for (int nt = 0; nt < 2; nt++) {
            uint32_t base = bufA + (uint32_t)((tw*16 + nt*8 + (lane & 7)) * 272
                                              + ((lane >> 3) & 1) * 16);
            uint32_t kfh[8], kfl[8];
            #pragma unroll
            for (int j = 0; j < 4; j++) ldsm_x2(base + j*32, kfh + 2*j);
            #pragma unroll
            for (int j = 0; j < 4; j++) ldsm_x2(base + 128 + j*32, kfl + 2*j);
            float* d = nt ? dd1 : dd0;
            #pragma unroll
            for (int t = 0; t < 4; t++) mma16816(d, afr[t],   kfh + 2*t);
            #pragma unroll
            for (int t = 0; t < 4; t++) mma16816(d, afr[t],   kfl + 2*t);
            #pragma unroll
            for (int t = 0; t < 4; t++) mma16816(d, afr[4+t], kfh + 2*t);
        }
        dd0[0] = fmaf(dd0[0], 0.125f, u00.x); dd0[1] = fmaf(dd0[1], 0.125f, u00.y);
        dd0[2] = fmaf(dd0[2], 0.125f, u10.x); dd0[3] = fmaf(dd0[3], 0.125f, u10.y);
        dd1[0] = fmaf(dd1[0], 0.125f, u01.x); dd1[1] = fmaf(dd1[1], 0.125f, u01.y);
        dd1[2] = fmaf(dd1[2], 0.125f, u11.x); dd1[3] = fmaf(dd1[3], 0.125f, u11.y);

        // ---- online softmax ----
        float rm0 = fmaxf(fmaxf(dd0[0], dd0[1]), fmaxf(dd1[0], dd1[1]));
        float rm1 = fmaxf(fmaxf(dd0[2], dd0[3]), fmaxf(dd1[2], dd1[3]));
        rm0 = fmaxf(rm0, __shfl_xor_sync(~0u, rm0, 1));
        rm0 = fmaxf(rm0, __shfl_xor_sync(~0u, rm0, 2));
        rm1 = fmaxf(rm1, __shfl_xor_sync(~0u, rm1, 1));
        rm1 = fmaxf(rm1, __shfl_xor_sync(~0u, rm1, 2));
        float M0 = fmaxf(m0, rm0), M1 = fmaxf(m1, rm1);
        float sc0 = fexp(m0 - M0), sc1 = fexp(m1 - M1);
        dd0[0] = fexp(dd0[0] - M0); dd0[1] = fexp(dd0[1] - M0);
        dd0[2] = fexp(dd0[2] - M1); dd0[3] = fexp(dd0[3] - M1);
        dd1[0] = fexp(dd1[0] - M0); dd1[1] = fexp(dd1[1] - M0);
        dd1[2] = fexp(dd1[2] - M1); dd1[3] = fexp(dd1[3] - M1);
        float ps0 = dd0[0] + dd0[1] + dd1[0] + dd1[1];
        float ps1 = dd0[2] + dd0[3] + dd1[2] + dd1[3];
        ps0 += __shfl_xor_sync(~0u, ps0, 1); ps0 += __shfl_xor_sync(~0u, ps0, 2);
        ps1 += __shfl_xor_sync(~0u, ps1, 1); ps1 += __shfl_xor_sync(~0u, ps1, 2);
        sum0 = sum0 * sc0 + ps0;
        sum1 = sum1 * sc1 + ps1;
        m0 = M0; m1 = M1;
        #pragma unroll
        for (int i = 0; i < 8; i++) {
            acc[i][0] *= sc0; acc[i][1] *= sc0;
            acc[i][2] *= sc1; acc[i][3] *= sc1;
        }
        uint32_t phi[4], plo[4];
        psplit(dd0[0], dd0[1], phi[0], plo[0]);
        psplit(dd0[2], dd0[3], phi[1], plo[1]);
        psplit(dd1[0], dd1[1], phi[2], plo[2]);
        psplit(dd1[2], dd1[3], phi[3], plo[3]);

        __syncthreads();                                   // done reading bufA (K_c)
        if (c < 7) { ld_chunk128(bufA, Kbh, (c + 1) * 128); CP_COMMIT(); CP_WAIT1(); }
        else       { CP_WAIT0(); }                         // V_c done
        __syncthreads();

        // ---- PV from bufB (this warp's token window) ----
        #pragma unroll
        for (int hd = 0; hd < 2; hd++) {
            uint32_t vaddr = bufB + (uint32_t)((tw*16 + ((lane >> 3) & 1)*8 + (lane & 7)) * 272
                                               + ((lane >> 4) & 1) * 16 + hd*64);
            uint32_t vfh[4][2], vfl[4][2];
            #pragma unroll
            for (int p = 0; p < 2; p++) {
                uint32_t r4[4];
                ldsm_x4t(vaddr + p*32, r4);
                vfh[2*p][0] = r4[0]; vfh[2*p][1] = r4[1];
                vfh[2*p+1][0] = r4[2]; vfh[2*p+1][1] = r4[3];
                ldsm_x4t(vaddr + 128 + p*32, r4);
                vfl[2*p][0] = r4[0]; vfl[2*p][1] = r4[1];
                vfl[2*p+1][0] = r4[2]; vfl[2*p+1][1] = r4[3];
            }
            #pragma unroll
            for (int nt = 0; nt < 4; nt++) {
                mma16816(acc[hd*4 + nt], phi, vfh[nt]);
                mma16816(acc[hd*4 + nt], phi, vfl[nt]);
                mma16816(acc[hd*4 + nt], plo, vfh[nt]);
            }
        }
        __syncthreads();                                   // done reading bufB (V_c)
        if (c < 7) { ld_chunk128(bufB, Vbh, (c + 1) * 128); CP_COMMIT(); }
    }

    // ---- flash merge: 8 warps per q-half ----
    if ((lane & 3) == 0) {
        mrow[wid*16 + r_]     = m0;  srow[wid*16 + r_]     = sum0;
        mrow[wid*16 + r_ + 8] = m1;  srow[wid*16 + r_ + 8] = sum1;
    }
    __syncthreads();
    int wbase = qh * 8;
    float M0g = -1e30f, M1g = -1e30f;
    #pragma unroll
    for (int w = 0; w < 8; w++) {
        M0g = fmaxf(M0g, mrow[(wbase + w)*16 + r_]);
        M1g = fmaxf(M1g, mrow[(wbase + w)*16 + r_ + 8]);
    }
    float S0g = 0.f, S1g = 0.f;
    #pragma unroll
    for (int w = 0; w < 8; w++) {
        S0g += srow[(wbase + w)*16 + r_]     * fexp(mrow[(wbase + w)*16 + r_]     - M0g);
        S1g += srow[(wbase + w)*16 + r_ + 8] * fexp(mrow[(wbase + w)*16 + r_ + 8] - M1g);
    }
    float f0 = fexp(m0 - M0g), f1 = fexp(m1 - M1g);
    __syncthreads();                      // all reads of mrow/srow + K/V/Q smem done
    if (tw == 0 && (lane & 3) == 0) { Sfin[qh*16 + r_] = S0g; Sfin[qh*16 + r_ + 8] = S1g; }
    // scaled partials: part[wid][16][64] (64 KB, overlays Q+bufA+bufB)
    #pragma unroll
    for (int i = 0; i < 8; i++) {
        int hd = i >> 2, nt = i & 3;
        int d = hd*32 + nt*8 + cl;
        *(float2*)(part + wid*1024 + r_*64 + d) =
            make_float2(acc[i][0] * f0, acc[i][1] * f0);
        *(float2*)(part + wid*1024 + (r_+8)*64 + d) =
            make_float2(acc[i][2] * f1, acc[i][3] * f1);
    }
    __syncthreads();
    for (int o = tid; o < 2048; o += 512) {
        int ql = o >> 6, d = o & 63;
        int qhh = ql >> 4, rl = ql & 15;
        float s = 0.f;
        #pragma unroll
        for (int w = 0; w < 8; w++) s += part[(qhh*8 + w)*1024 + rl*64 + d];
        s /= Sfin[ql];
        int col = h * 64 + d;
        split3(out + (size_t)(b * Nn + q0 + ql) * KCAT + col, s);
    }
}

// -------------------- launch --------------------
extern "C" void kernel_launch(void* const* d_in, const int* in_sizes, int n_in,
                              void* d_out, int out_size)
{
    const float* node = (const float*)d_in[0];
    const float* adj  = (const float*)d_in[1];
    const float* wd   = (const float*)d_in[2];
    const float* bear = (const float*)d_in[3];
    const float* Wq   = (const float*)d_in[4];
    const float* Wk   = (const float*)d_in[5];
    const float* Wv   = (const float*)d_in[6];
    const float* Wo   = (const float*)d_in[7];
    const float* lng  = (const float*)d_in[8];
    const float* lnb  = (const float*)d_in[9];
    const float* ww   = (const float*)d_in[10];
    const float* wbv  = (const float*)d_in[11];
    float* out = (float*)d_out;

    __nv_bfloat16 *xcat, *wqkv, *wocat, *aocat, *Qc, *Kc, *Vc;
    __half* biasp;
    float *cosp, *sinp;
    cudaGetSymbolAddress((void**)&xcat,  g_xcat);
    cudaGetSymbolAddress((void**)&wqkv,  g_wqkv);
    cudaGetSymbolAddress((void**)&wocat, g_wocat);
    cudaGetSymbolAddress((void**)&aocat, g_aocat);
    cudaGetSymbolAddress((void**)&Qc,    g_Qc);
    cudaGetSymbolAddress((void**)&Kc,    g_Kc);
    cudaGetSymbolAddress((void**)&Vc,    g_Vc);
    cudaGetSymbolAddress((void**)&biasp, g_bias);
    cudaGetSymbolAddress((void**)&cosp,  g_cos);
    cudaGetSymbolAddress((void**)&sinp,  g_sin);

    const int SMEM_GEMM = 3 * STG;
    const int SMEM_ATTN = 8704 + 2*34816 + (256 + 256 + 32) * 4;  // 80512 -> occ 2 @512thr
    cudaFuncSetAttribute(gemm_mma<0>, cudaFuncAttributeMaxDynamicSharedMemorySize, SMEM_GEMM);
    cudaFuncSetAttribute(gemm_mma<1>, cudaFuncAttributeMaxDynamicSharedMemorySize, SMEM_GEMM);
    cudaFuncSetAttribute(attn_flash,  cudaFuncAttributeMaxDynamicSharedMemorySize, SMEM_ATTN);

    prep_kernel<<<NB_WQKV + NB_WO + NB_ROPE + BN, 256>>>(Wq, Wk, Wv, Wo, node, lng, lnb,
                                                         wqkv, wocat, cosp, sinp, xcat);
    bias_kernel<<<dim3(1024, Bq), 256>>>(bear, wd, adj, ww, wbv, biasp);
    gemm_mma<0><<<dim3(KCAT/128, BN/128), 256, SMEM_GEMM>>>(xcat, wqkv, cosp, sinp,
                                                            nullptr, Qc, Kc, Vc);
    attn_flash<<<dim3(Nn/32, Hh, Bq), 512, SMEM_ATTN>>>(Qc, Kc, Vc, biasp, aocat);
    gemm_mma<1><<<dim3(Dm/128, BN/128), 256, SMEM_GEMM>>>(aocat, wocat, cosp, sinp,
                                                          node, out, nullptr, nullptr);
}

// round 12
// speedup vs baseline: 1.3047x; 1.3047x over previous
#include <cuda_runtime.h>
#include <cuda_bf16.h>
#include <cuda_fp16.h>
#include <math.h>
#include <stdint.h>

#define Bq   8
#define Nn   1024
#define Dm   896
#define Hh   14
#define Dh   64
#define BN   (Bq*Nn)
#define KCAT 2688
#define EPITCH 132
#define STG  20480

__device__ __align__(128) __nv_bfloat16 g_xcat[(size_t)BN*KCAT];
__device__ __align__(128) __nv_bfloat16 g_wqkv[(size_t)KCAT*KCAT];
__device__ __align__(128) __nv_bfloat16 g_wocat[(size_t)Dm*KCAT];
__device__ __align__(128) __nv_bfloat16 g_aocat[(size_t)BN*KCAT];
__device__ __align__(128) __nv_bfloat16 g_Qc[(size_t)Bq*Hh*Nn*128];
__device__ __align__(128) __nv_bfloat16 g_Kc[(size_t)Bq*Hh*Nn*128];
__device__ __align__(128) __nv_bfloat16 g_Vc[(size_t)Bq*Hh*Nn*128];
__device__ __half g_bias[(size_t)Bq*Hh*Nn*Nn];   // masked wind bias, f16
__device__ float g_cos[Nn*32];
__device__ float g_sin[Nn*32];

__device__ __forceinline__ uint32_t smem_u32(const void* p) {
    uint32_t a;
    asm("{ .reg .u64 t; cvta.to.shared.u64 t, %1; cvt.u32.u64 %0, t; }" : "=r"(a) : "l"(p));
    return a;
}
__device__ __forceinline__ void cp_async16(uint32_t dst, const void* src) {
    asm volatile("cp.async.cg.shared.global [%0], [%1], 16;" :: "r"(dst), "l"(src));
}
#define CP_COMMIT() asm volatile("cp.async.commit_group;" ::: "memory")
#define CP_WAIT0()  asm volatile("cp.async.wait_group 0;" ::: "memory")
#define CP_WAIT1()  asm volatile("cp.async.wait_group 1;" ::: "memory")

__device__ __forceinline__ void ldsm_x4(uint32_t a, uint32_t* r) {
    asm volatile("ldmatrix.sync.aligned.m8n8.x4.shared.b16 {%0,%1,%2,%3}, [%4];"
                 : "=r"(r[0]), "=r"(r[1]), "=r"(r[2]), "=r"(r[3]) : "r"(a));
}
__device__ __forceinline__ void ldsm_x2(uint32_t a, uint32_t* r) {
    asm volatile("ldmatrix.sync.aligned.m8n8.x2.shared.b16 {%0,%1}, [%2];"
                 : "=r"(r[0]), "=r"(r[1]) : "r"(a));
}
__device__ __forceinline__ void ldsm_x4t(uint32_t a, uint32_t* r) {
    asm volatile("ldmatrix.sync.aligned.m8n8.x4.trans.shared.b16 {%0,%1,%2,%3}, [%4];"
                 : "=r"(r[0]), "=r"(r[1]), "=r"(r[2]), "=r"(r[3]) : "r"(a));
}
__device__ __forceinline__ void mma16816(float* c, const uint32_t* a, const uint32_t* b) {
    asm volatile("mma.sync.aligned.m16n8k16.row.col.f32.bf16.bf16.f32 "
                 "{%0,%1,%2,%3},{%4,%5,%6,%7},{%8,%9},{%0,%1,%2,%3};"
                 : "+f"(c[0]), "+f"(c[1]), "+f"(c[2]), "+f"(c[3])
                 : "r"(a[0]), "r"(a[1]), "r"(a[2]), "r"(a[3]), "r"(b[0]), "r"(b[1]));
}
__device__ __forceinline__ uint32_t packbf(float lo, float hi) {
    uint32_t r; asm("cvt.rn.bf16x2.f32 %0, %1, %2;" : "=r"(r) : "f"(hi), "f"(lo)); return r;
}

__device__ __forceinline__ float fexp(float x) {
    x = fmaxf(x, -80.f);
    float y = x * 1.442695041f;
    float n = rintf(y);
    float f = y - n;
    float p =            1.8775767e-3f;
    p = fmaf(p, f, 8.9893397e-3f);
    p = fmaf(p, f, 5.5826318e-2f);
    p = fmaf(p, f, 2.4015361e-1f);
    p = fmaf(p, f, 6.9315308e-1f);
    p = fmaf(p, f, 9.9999994e-1f);
    return __int_as_float(__float_as_int(p) + ((int)n << 23));
}
__device__ __forceinline__ float ftanh(float x) {
    float ax = fabsf(x);
    float e = fexp(-2.f * ax);
    float d = 1.f + e;
    float r = fmaf(-0.5f, d, 1.4571f);
    r = r * fmaf(-d, r, 2.f);
    r = r * fmaf(-d, r, 2.f);
    r = r * fmaf(-d, r, 2.f);
    float t = (1.f - e) * r;
    return (x >= 0.f) ? t : -t;
}
__device__ __forceinline__ void split3(__nv_bfloat16* p, float v) {
    __nv_bfloat16 hi = __float2bfloat16(v);
    __nv_bfloat16 lo = __float2bfloat16(v - __bfloat162float(hi));
    p[0] = hi; p[Dm] = hi; p[2*Dm] = lo;
}
__device__ __forceinline__ void psplit(float x, float y, uint32_t& hi, uint32_t& lo) {
    float hx = __bfloat162float(__float2bfloat16(x));
    float hy = __bfloat162float(__float2bfloat16(y));
    hi = packbf(x, y);
    lo = packbf(x - hx, y - hy);
}

// -------- prep: weight packs + rope tables + layernorm(split) --------
#define NB_WQKV 28224
#define NB_WO   9408
#define NB_ROPE 128
__global__ void prep_kernel(const float* __restrict__ Wq, const float* __restrict__ Wk,
                            const float* __restrict__ Wv, const float* __restrict__ Wo,
                            const float* __restrict__ x, const float* __restrict__ lng,
                            const float* __restrict__ lnb,
                            __nv_bfloat16* __restrict__ wqkv, __nv_bfloat16* __restrict__ wocat,
                            float* __restrict__ cc, float* __restrict__ ss,
                            __nv_bfloat16* __restrict__ y)
{
    int bid = blockIdx.x, tid = threadIdx.x;
    if (bid < NB_WQKV) {
        size_t idx = (size_t)bid * 256 + tid;
        int k = (int)(idx % KCAT), n = (int)(idx / KCAT);
        const float* W = (n < Dm) ? Wq : ((n < 2*Dm) ? Wk : Wv);
        int c = n % Dm, kr = k % Dm, blk = k / Dm;
        float w = W[(size_t)kr * Dm + c];
        __nv_bfloat16 hi = __float2bfloat16(w);
        wqkv[idx] = (blk == 1) ? __float2bfloat16(w - __bfloat162float(hi)) : hi;
    } else if (bid < NB_WQKV + NB_WO) {
        size_t idx = (size_t)(bid - NB_WQKV) * 256 + tid;
        int k = (int)(idx % KCAT), n = (int)(idx / KCAT);
        int kr = k % Dm, blk = k / Dm;
        float w = Wo[(size_t)kr * Dm + n];
        __nv_bfloat16 hi = __float2bfloat16(w);
        wocat[idx] = (blk == 1) ? __float2bfloat16(w - __bfloat162float(hi)) : hi;
    } else if (bid < NB_WQKV + NB_WO + NB_ROPE) {
        int i = (bid - NB_WQKV - NB_WO) * 256 + tid;
        int n = i >> 5, d = i & 31;
        float freq = (float)n * powf(10000.f, -(float)(2*d) / 64.f);
        cc[i] = cosf(freq);
        ss[i] = sinf(freq);
    } else {
        int row = bid - (NB_WQKV + NB_WO + NB_ROPE);
        const float* xr = x + (size_t)row * Dm;
        float s = 0.f, s2 = 0.f;
        for (int i = tid; i < Dm; i += 256) { float v = xr[i]; s += v; s2 += v*v; }
        #pragma unroll
        for (int o = 16; o; o >>= 1) { s += __shfl_xor_sync(~0u, s, o); s2 += __shfl_xor_sync(~0u, s2, o); }
        __shared__ float ws[8], ws2[8];
        int w = tid >> 5;
        if ((tid & 31) == 0) { ws[w] = s; ws2[w] = s2; }
        __syncthreads();
        if (tid < 32) {
            s  = (tid < 8) ? ws[tid]  : 0.f;
            s2 = (tid < 8) ? ws2[tid] : 0.f;
            #pragma unroll
            for (int o = 4; o; o >>= 1) { s += __shfl_xor_sync(~0u, s, o); s2 += __shfl_xor_sync(~0u, s2, o); }
            if (tid == 0) { ws[0] = s; ws2[0] = s2; }
        }
        __syncthreads();
        float mu  = ws[0] * (1.f/Dm);
        float var = ws2[0] * (1.f/Dm) - mu*mu;
        float inv = rsqrtf(var + 1e-5f);
        __nv_bfloat16* yr = y + (size_t)row * KCAT;
        for (int i = tid; i < Dm; i += 256) {
            float v = (xr[i] - mu) * inv * lng[i] + lnb[i];
            split3(yr + i, v);
        }
    }
}

// -------- bias precompute (f16 output) --------
__global__ void bias_kernel(const float* __restrict__ bear, const float* __restrict__ wd,
                            const float* __restrict__ adj, const float* __restrict__ ww,
                            const float* __restrict__ wbv, __half* __restrict__ bias)
{
    int t = blockIdx.x;
    int b = blockIdx.y;
    int q0 = (t >> 5) * 32, k0 = (t & 31) * 32;
    __shared__ float tile[32][33];
    __shared__ float w0s[Hh], w1s[Hh], wbs[Hh];
    int tid = threadIdx.x;
    int j = tid & 31, i = tid >> 5;
    if (tid < Hh) { w0s[tid] = ww[tid]; w1s[tid] = ww[Hh + tid]; wbs[tid] = wbv[tid]; }
    #pragma unroll
    for (int p = 0; p < 4; p++)
        tile[i + p*8][j] = bear[(size_t)(k0 + i + p*8) * Nn + q0 + j];
    __syncthreads();
    #pragma unroll
    for (int p = 0; p < 4; p++) {
        int qi = i + p*8;
        int q = q0 + qi, k = k0 + j;
        float rb = fmodf(tile[j][qi] + 180.f, 360.f);
        float av = cosf((wd[b*Nn + q] - rb) * 0.017453292519943295f);
        float a  = adj[(size_t)q * Nn + k];
        bool on = (a > 0.f);
        size_t base = ((size_t)q << 10) + k;
        #pragma unroll
        for (int h = 0; h < Hh; h++) {
            float bv = on ? ftanh(fmaf(av, w0s[h], fmaf(a, w1s[h], wbs[h]))) : -1e30f;
            bias[(((size_t)(b*Hh + h)) << 20) + base] = __float2half(bv);
        }
    }
}

// -------- gemm stage loader --------
__device__ __forceinline__ void load_stage(uint32_t abase, uint32_t bbase,
                                           const __nv_bfloat16* __restrict__ A,
                                           const __nv_bfloat16* __restrict__ Bw,
                                           int m0, int n0, int k0)
{
    int tid = threadIdx.x;
    #pragma unroll
    for (int p = 0; p < 2; p++) {
        int e = p * 256 + tid;
        int r = e >> 2, seg = e & 3;
        cp_async16(abase + r * 80 + seg * 16, A + (size_t)(m0 + r) * KCAT + k0 + seg * 8);
    }
    #pragma unroll
    for (int p = 0; p < 2; p++) {
        int e = p * 256 + tid;
        int r = e >> 2, seg = e & 3;
        cp_async16(bbase + r * 80 + seg * 16, Bw + (size_t)(n0 + r) * KCAT + k0 + seg * 8);
    }
}

// -------- mma GEMM --------
template<int MODE>
__global__ void __launch_bounds__(256, 2)
gemm_mma(const __nv_bfloat16* __restrict__ A, const __nv_bfloat16* __restrict__ Bw,
         const float* __restrict__ cosp, const float* __restrict__ sinp,
         const float* __restrict__ res, void* outQ, void* outK, void* outV)
{
    extern __shared__ char dsm[];
    uint32_t sb = smem_u32(dsm);
    float* sep = (float*)dsm;

    int tid = threadIdx.x, wid = tid >> 5, lane = tid & 31;
    int wm = wid >> 2, wn = wid & 3;
    int m0 = blockIdx.y * 128, n0 = blockIdx.x * 128;

    float acc[4][4][4];
    #pragma unroll
    for (int i = 0; i < 4; i++)
        #pragma unroll
        for (int j = 0; j < 4; j++)
            #pragma unroll
            for (int r = 0; r < 4; r++) acc[i][j][r] = 0.f;

    int gq = lane >> 3, lr = lane & 7;
    uint32_t a_off = (uint32_t)((wm*64 + lr + (gq & 1)*8) * 80 + (gq >> 1)*16);
    uint32_t b_off = (uint32_t)((wn*32 + lr) * 80 + ((lane & 8) ? 16 : 0));

    load_stage(sb + 0*STG, sb + 0*STG + 10240, A, Bw, m0, n0, 0);
    CP_COMMIT();
    load_stage(sb + 1*STG, sb + 1*STG + 10240, A, Bw, m0, n0, 32);
    CP_COMMIT();

    const int NT = KCAT / 32;
    int slot = 0;
    for (int i = 0; i < NT; i++) {
        if (i + 1 < NT) CP_WAIT1(); else CP_WAIT0();
        __syncthreads();
        uint32_t ab = sb + slot * STG, bb = ab + 10240;
        #pragma unroll
        for (int ks = 0; ks < 2; ks++) {
            uint32_t afr[4][4], bfr[4][2];
            #pragma unroll
            for (int mt = 0; mt < 4; mt++) ldsm_x4(ab + a_off + mt*(16*80) + ks*32, afr[mt]);
            #pragma unroll
            for (int nt = 0; nt < 4; nt++) ldsm_x2(bb + b_off + nt*(8*80) + ks*32, bfr[nt]);
            #pragma unroll
            for (int mt = 0; mt < 4; mt++)
                #pragma unroll
                for (int nt = 0; nt < 4; nt++)
                    mma16816(acc[mt][nt], afr[mt], bfr[nt]);
        }
        if (i + 2 < NT) {
            int ns = slot + 2; if (ns >= 3) ns -= 3;
            uint32_t nb = sb + ns * STG;
            load_stage(nb, nb + 10240, A, Bw, m0, n0, (i + 2) * 32);
            CP_COMMIT();
        }
        slot++; if (slot == 3) slot = 0;
    }
    __syncthreads();

    #pragma unroll
    for (int half = 0; half < 2; half++) {
        if (wm == half) {
            #pragma unroll
            for (int mt = 0; mt < 4; mt++)
                #pragma unroll
                for (int nt = 0; nt < 4; nt++)
                    #pragma unroll
                    for (int ri = 0; ri < 4; ri++) {
                        int r = mt*16 + (lane >> 2) + ((ri >> 1) * 8);
                        int n = wn*32 + nt*8 + ((lane & 3) * 2) + (ri & 1);
                        sep[r * EPITCH + n] = acc[mt][nt][ri];
                    }
        }
        __syncthreads();

        if (MODE == 0) {
            int tile = blockIdx.x;
            int region = tile / 7;
            int cbase = (tile % 7) * 128;
            __nv_bfloat16* base = (region == 0) ? (__nv_bfloat16*)outQ
                                : (region == 1) ? (__nv_bfloat16*)outK
                                                : (__nv_bfloat16*)outV;
            for (int idx = tid; idx < 64*128; idx += 256) {
                int r = idx >> 7, c = idx & 127;
                int m = m0 + half*64 + r;
                int bqi = m >> 10, n = m & 1023;
                int ccx = cbase + c;
                int head = ccx >> 6, d = ccx & 63;
                float val;
                if (region < 2) {
                    if (d < 32) {
                        float x1 = sep[r*EPITCH + c], x2 = sep[r*EPITCH + c + 32];
                        val = x1 * cosp[n*32 + d] - x2 * sinp[n*32 + d];
                    } else {
                        float x2 = sep[r*EPITCH + c], x1 = sep[r*EPITCH + c - 32];
                        int dd = d - 32;
                        val = x2 * cosp[n*32 + dd] + x1 * sinp[n*32 + dd];
                    }
                } else {
                    val = sep[r*EPITCH + c];
                }
                __nv_bfloat16 hv = __float2bfloat16(val);
                __nv_bfloat16 lv = __float2bfloat16(val - __bfloat162float(hv));
                size_t row = ((size_t)bqi * Hh + head) * Nn + n;
                base[row*128 + d]      = hv;
                base[row*128 + 64 + d] = lv;
            }
        } else {
            float* outp = (float*)outQ;
            for (int idx = tid; idx < 64*128; idx += 256) {
                int r = idx >> 7, c = idx & 127;
                int m = m0 + half*64 + r;
                size_t o = (size_t)m * Dm + n0 + c;
                outp[o] = sep[r*EPITCH + c] + res[o];
            }
        }
        __syncthreads();
    }
}

// -------- flash attn chunk loader: 128 rows x 256B, pitch 272, 256 threads --------
__device__ __forceinline__ void ld_chunk128(uint32_t dst, const __nv_bfloat16* __restrict__ src,
                                            int tok0)
{
    #pragma unroll
    for (int p = 0; p < 8; p++) {
        int e = p * 256 + threadIdx.x;
        int r = e >> 4, s = e & 15;
        cp_async16(dst + r * 272 + s * 16, src + (size_t)(tok0 + r) * 128 + s * 8);
    }
}

// -------- single-pass flash attention: block (b,h,16q), 256 threads, occ 2 --------
// smem: Q 16x272 (4352) | bufA 128x272 (34816) | bufB 128x272 | mrow[128] srow[128] Sfin[16]
__global__ void __launch_bounds__(256, 2)
attn_flash(const __nv_bfloat16* __restrict__ Qc, const __nv_bfloat16* __restrict__ Kc,
           const __nv_bfloat16* __restrict__ Vc, const __half* __restrict__ bias,
           __nv_bfloat16* __restrict__ out)
{
    extern __shared__ char dsm[];
    uint32_t sb = smem_u32(dsm);
    uint32_t qs = sb;
    uint32_t bufA = sb + 4352;
    uint32_t bufB = bufA + 34816;
    float* part = (float*)(dsm + 4352);                  // overlays bufA at merge
    float* mrow = (float*)(dsm + 4352 + 2*34816);        // [8][16]
    float* srow = mrow + 128;                            // [8][16]
    float* Sfin = srow + 128;                            // [16]

    int tid = threadIdx.x, wid = tid >> 5, lane = tid & 31;
    int h = blockIdx.y, b = blockIdx.z;
    int q0 = blockIdx.x * 16;
    size_t bh = ((size_t)b * Hh + h) * Nn;
    const __nv_bfloat16* Kbh = Kc + bh * 128;
    const __nv_bfloat16* Vbh = Vc + bh * 128;
    const __half* biasbh = bias + (((size_t)(b*Hh + h)) << 20);

    {   // Q tile (group 0)
        int r = tid >> 4, s = tid & 15;
        cp_async16(qs + r*272 + s*16, Qc + (bh + q0 + r) * 128 + s * 8);
    }
    CP_COMMIT();
    ld_chunk128(bufA, Kbh, 0); CP_COMMIT();   // K0
    ld_chunk128(bufB, Vbh, 0); CP_COMMIT();   // V0

    int r_ = lane >> 2, cl = 2*(lane & 3);

    // bias pointers: this warp's token window base
    const __half* bb0 = biasbh + (((size_t)(q0 + r_))     << 10) + wid*16;
    const __half* bb1 = biasbh + (((size_t)(q0 + r_ + 8)) << 10) + wid*16;
    __half2 nb00 = *(const __half2*)(bb0 + cl);
    __half2 nb01 = *(const __half2*)(bb0 + cl + 8);
    __half2 nb10 = *(const __half2*)(bb1 + cl);
    __half2 nb11 = *(const __half2*)(bb1 + cl + 8);

    float m0 = -1e30f, m1 = -1e30f, sum0 = 0.f, sum1 = 0.f;
    float acc[8][4];
    #pragma unroll
    for (int i = 0; i < 8; i++)
        #pragma unroll
        for (int r = 0; r < 4; r++) acc[i][r] = 0.f;
    uint32_t afr[8][4];

    for (int c = 0; c < 8; c++) {
        float2 u00 = __half22float2(nb00), u01 = __half22float2(nb01);
        float2 u10 = __half22float2(nb10), u11 = __half22float2(nb11);
        if (c < 7) {
            int o = (c + 1) * 128;
            nb00 = *(const __half2*)(bb0 + o + cl);
            nb01 = *(const __half2*)(bb0 + o + cl + 8);
            nb10 = *(const __half2*)(bb1 + o + cl);
            nb11 = *(const __half2*)(bb1 + o + cl + 8);
        }
        CP_WAIT1();              // K_c done (V_c pending)
        __syncthreads();
        if (c == 0) {            // hoist Q fragments
            int gq = lane >> 3, lr = lane & 7;
            uint32_t a_off = qs + (uint32_t)((lr + (gq & 1)*8) * 272 + (gq >> 1)*16);
            #pragma unroll
            for (int kt = 0; kt < 8; kt++) ldsm_x4(a_off + kt*32, afr[kt]);
        }

        // ---- scores S (16x16) for this warp's token window ----
        float dd0[4] = {0.f,0.f,0.f,0.f}, dd1[4] = {0.f,0.f,0.f,0.f};
        #pragma unroll
        for (int nt = 0; nt < 2; nt++) {
            uint32_t base = bufA + (uint32_t)((wid*16 + nt*8 + (lane & 7)) * 272
                                              + ((lane >> 3) & 1) * 16);
            uint32_t kfh[8], kfl[8];
            #pragma unroll
            for (int j = 0; j < 4; j++) ldsm_x2(base + j*32, kfh + 2*j);
            #pragma unroll
            for (int j = 0; j < 4; j++) ldsm_x2(base + 128 + j*32, kfl + 2*j);
            float* d = nt ? dd1 : dd0;
            #pragma unroll
            for (int t = 0; t < 4; t++) mma16816(d, afr[t],   kfh + 2*t);
            #pragma unroll
            for (int t = 0; t < 4; t++) mma16816(d, afr[t],   kfl + 2*t);
            #pragma unroll
            for (int t = 0; t < 4; t++) mma16816(d, afr[4+t], kfh + 2*t);
        }
        dd0[0] = fmaf(dd0[0], 0.125f, u00.x); dd0[1] = fmaf(dd0[1], 0.125f, u00.y);
        dd0[2] = fmaf(dd0[2], 0.125f, u10.x); dd0[3] = fmaf(dd0[3], 0.125f, u10.y);
        dd1[0] = fmaf(dd1[0], 0.125f, u01.x); dd1[1] = fmaf(dd1[1], 0.125f, u01.y);
        dd1[2] = fmaf(dd1[2], 0.125f, u11.x); dd1[3] = fmaf(dd1[3], 0.125f, u11.y);

        // ---- online softmax ----
        float rm0 = fmaxf(fmaxf(dd0[0], dd0[1]), fmaxf(dd1[0], dd1[1]));
        float rm1 = fmaxf(fmaxf(dd0[2], dd0[3]), fmaxf(dd1[2], dd1[3]));
        rm0 = fmaxf(rm0, __shfl_xor_sync(~0u, rm0, 1));
        rm0 = fmaxf(rm0, __shfl_xor_sync(~0u, rm0, 2));
        rm1 = fmaxf(rm1, __shfl_xor_sync(~0u, rm1, 1));
        rm1 = fmaxf(rm1, __shfl_xor_sync(~0u, rm1, 2));
        float M0 = fmaxf(m0, rm0), M1 = fmaxf(m1, rm1);
        float sc0 = fexp(m0 - M0), sc1 = fexp(m1 - M1);
        dd0[0] = fexp(dd0[0] - M0); dd0[1] = fexp(dd0[1] - M0);
        dd0[2] = fexp(dd0[2] - M1); dd0[3] = fexp(dd0[3] - M1);
        dd1[0] = fexp(dd1[0] - M0); dd1[1] = fexp(dd1[1] - M0);
        dd1[2] = fexp(dd1[2] - M1); dd1[3] = fexp(dd1[3] - M1);
        float ps0 = dd0[0] + dd0[1] + dd1[0] + dd1[1];
        float ps1 = dd0[2] + dd0[3] + dd1[2] + dd1[3];
        ps0 += __shfl_xor_sync(~0u, ps0, 1); ps0 += __shfl_xor_sync(~0u, ps0, 2);
        ps1 += __shfl_xor_sync(~0u, ps1, 1); ps1 += __shfl_xor_sync(~0u, ps1, 2);
        sum0 = sum0 * sc0 + ps0;
        sum1 = sum1 * sc1 + ps1;
        m0 = M0; m1 = M1;
        #pragma unroll
        for (int i = 0; i < 8; i++) {
            acc[i][0] *= sc0; acc[i][1] *= sc0;
            acc[i][2] *= sc1; acc[i][3] *= sc1;
        }
        uint32_t phi[4], plo[4];
        psplit(dd0[0], dd0[1], phi[0], plo[0]);
        psplit(dd0[2], dd0[3], phi[1], plo[1]);
        psplit(dd1[0], dd1[1], phi[2], plo[2]);
        psplit(dd1[2], dd1[3], phi[3], plo[3]);

        __syncthreads();                                   // done reading bufA (K_c)
        if (c < 7) { ld_chunk128(bufA, Kbh, (c + 1) * 128); CP_COMMIT(); CP_WAIT1(); }
        else       { CP_WAIT0(); }                         // V_c done
        __syncthreads();

        // ---- PV from bufB ----
        #pragma unroll
        for (int hd = 0; hd < 2; hd++) {
            uint32_t vaddr = bufB + (uint32_t)((wid*16 + ((lane >> 3) & 1)*8 + (lane & 7)) * 272
                                               + ((lane >> 4) & 1) * 16 + hd*64);
            uint32_t vfh[4][2], vfl[4][2];
            #pragma unroll
            for (int p = 0; p < 2; p++) {
                uint32_t r4[4];
                ldsm_x4t(vaddr + p*32, r4);
                vfh[2*p][0] = r4[0]; vfh[2*p][1] = r4[1];
                vfh[2*p+1][0] = r4[2]; vfh[2*p+1][1] = r4[3];
                ldsm_x4t(vaddr + 128 + p*32, r4);
                vfl[2*p][0] = r4[0]; vfl[2*p][1] = r4[1];
                vfl[2*p+1][0] = r4[2]; vfl[2*p+1][1] = r4[3];
            }
            #pragma unroll
            for (int nt = 0; nt < 4; nt++) {
                mma16816(acc[hd*4 + nt], phi, vfh[nt]);
                mma16816(acc[hd*4 + nt], phi, vfl[nt]);
                mma16816(acc[hd*4 + nt], plo, vfh[nt]);
            }
        }
        __syncthreads();                                   // done reading bufB (V_c)
        if (c < 7) { ld_chunk128(bufB, Vbh, (c + 1) * 128); CP_COMMIT(); }
    }

    // ---- flash merge across 8 warps ----
    if ((lane & 3) == 0) {
        mrow[wid*16 + r_]     = m0;  srow[wid*16 + r_]     = sum0;
        mrow[wid*16 + r_ + 8] = m1;  srow[wid*16 + r_ + 8] = sum1;
    }
    __syncthreads();
    float M0g = -1e30f, M1g = -1e30f;
    #pragma unroll
    for (int w = 0; w < 8; w++) {
        M0g = fmaxf(M0g, mrow[w*16 + r_]);
        M1g = fmaxf(M1g, mrow[w*16 + r_ + 8]);
    }
    float S0g = 0.f, S1g = 0.f;
    #pragma unroll
    for (int w = 0; w < 8; w++) {
        S0g += srow[w*16 + r_]     * fexp(mrow[w*16 + r_]     - M0g);
        S1g += srow[w*16 + r_ + 8] * fexp(mrow[w*16 + r_ + 8] - M1g);
    }
    if (wid == 0 && (lane & 3) == 0) { Sfin[r_] = S0g; Sfin[r_ + 8] = S1g; }
    float f0 = fexp(m0 - M0g), f1 = fexp(m1 - M1g);
    // scaled partials into part[wid][16][64] (overlays bufA; last bufA read was S7, synced)
    #pragma unroll
    for (int i = 0; i < 8; i++) {
        int hd = i >> 2, nt = i & 3;
        int d = hd*32 + nt*8 + cl;
        *(float2*)(part + wid*1024 + r_*64 + d) =
            make_float2(acc[i][0] * f0, acc[i][1] * f0);
        *(float2*)(part + wid*1024 + (r_+8)*64 + d) =
            make_float2(acc[i][2] * f1, acc[i][3] * f1);
    }
    __syncthreads();
    for (int o = tid; o < 1024; o += 256) {
        float s = 0.f;
        #pragma unroll
        for (int w = 0; w < 8; w++) s += part[w*1024 + o];
        int qi = o >> 6, d = o & 63;
        s /= Sfin[qi];
        int col = h * 64 + d;
        split3(out + (size_t)(b * Nn + q0 + qi) * KCAT + col, s);
    }
}

// -------------------- launch --------------------
extern "C" void kernel_launch(void* const* d_in, const int* in_sizes, int n_in,
                              void* d_out, int out_size)
{
    const float* node = (const float*)d_in[0];
    const float* adj  = (const float*)d_in[1];
    const float* wd   = (const float*)d_in[2];
    const float* bear = (const float*)d_in[3];
    const float* Wq   = (const float*)d_in[4];
    const float* Wk   = (const float*)d_in[5];
    const float* Wv   = (const float*)d_in[6];
    const float* Wo   = (const float*)d_in[7];
    const float* lng  = (const float*)d_in[8];
    const float* lnb  = (const float*)d_in[9];
    const float* ww   = (const float*)d_in[10];
    const float* wbv  = (const float*)d_in[11];
    float* out = (float*)d_out;

    __nv_bfloat16 *xcat, *wqkv, *wocat, *aocat, *Qc, *Kc, *Vc;
    __half* biasp;
    float *cosp, *sinp;
    cudaGetSymbolAddress((void**)&xcat,  g_xcat);
    cudaGetSymbolAddress((void**)&wqkv,  g_wqkv);
    cudaGetSymbolAddress((void**)&wocat, g_wocat);
    cudaGetSymbolAddress((void**)&aocat, g_aocat);
    cudaGetSymbolAddress((void**)&Qc,    g_Qc);
    cudaGetSymbolAddress((void**)&Kc,    g_Kc);
    cudaGetSymbolAddress((void**)&Vc,    g_Vc);
    cudaGetSymbolAddress((void**)&biasp, g_bias);
    cudaGetSymbolAddress((void**)&cosp,  g_cos);
    cudaGetSymbolAddress((void**)&sinp,  g_sin);

    const int SMEM_GEMM = 3 * STG;
    const int SMEM_ATTN = 4352 + 2*34816 + (128 + 128 + 16) * 4;  // 75136
    cudaFuncSetAttribute(gemm_mma<0>, cudaFuncAttributeMaxDynamicSharedMemorySize, SMEM_GEMM);
    cudaFuncSetAttribute(gemm_mma<1>, cudaFuncAttributeMaxDynamicSharedMemorySize, SMEM_GEMM);
    cudaFuncSetAttribute(attn_flash,  cudaFuncAttributeMaxDynamicSharedMemorySize, SMEM_ATTN);

    prep_kernel<<<NB_WQKV + NB_WO + NB_ROPE + BN, 256>>>(Wq, Wk, Wv, Wo, node, lng, lnb,
                                                         wqkv, wocat, cosp, sinp, xcat);
    bias_kernel<<<dim3(1024, Bq), 256>>>(bear, wd, adj, ww, wbv, biasp);
    gemm_mma<0><<<dim3(KCAT/128, BN/128), 256, SMEM_GEMM>>>(xcat, wqkv, cosp, sinp,
                                                            nullptr, Qc, Kc, Vc);
    attn_flash<<<dim3(Nn/16, Hh, Bq), 256, SMEM_ATTN>>>(Qc, Kc, Vc, biasp, aocat);
    gemm_mma<1><<<dim3(Dm/128, BN/128), 256, SMEM_GEMM>>>(aocat, wocat, cosp, sinp,
                                                          node, out, nullptr, nullptr);
}

// round 13
// speedup vs baseline: 1.3441x; 1.0302x over previous
#include <cuda_runtime.h>
#include <cuda_bf16.h>
#include <cuda_fp16.h>
#include <math.h>
#include <stdint.h>

#define Bq   8
#define Nn   1024
#define Dm   896
#define Hh   14
#define Dh   64
#define BN   (Bq*Nn)
#define KCAT 2688
#define EPITCH 132
#define APITCH 144          // gemm stage row pitch (64 bf16 + 16B pad)
#define STG   36864         // stage bytes: A 128*144 + B 128*144

__device__ __align__(128) __nv_bfloat16 g_xcat[(size_t)BN*KCAT];
__device__ __align__(128) __nv_bfloat16 g_wqkv[(size_t)KCAT*KCAT];
__device__ __align__(128) __nv_bfloat16 g_wocat[(size_t)Dm*KCAT];
__device__ __align__(128) __nv_bfloat16 g_aocat[(size_t)BN*KCAT];
__device__ __align__(128) __nv_bfloat16 g_Qc[(size_t)Bq*Hh*Nn*128];
__device__ __align__(128) __nv_bfloat16 g_Kc[(size_t)Bq*Hh*Nn*128];
__device__ __align__(128) __nv_bfloat16 g_Vc[(size_t)Bq*Hh*Nn*128];
__device__ __half g_bias[(size_t)Bq*Hh*Nn*Nn];
__device__ float g_cos[Nn*32];
__device__ float g_sin[Nn*32];

__device__ __forceinline__ uint32_t smem_u32(const void* p) {
    uint32_t a;
    asm("{ .reg .u64 t; cvta.to.shared.u64 t, %1; cvt.u32.u64 %0, t; }" : "=r"(a) : "l"(p));
    return a;
}
__device__ __forceinline__ void cp_async16(uint32_t dst, const void* src) {
    asm volatile("cp.async.cg.shared.global [%0], [%1], 16;" :: "r"(dst), "l"(src));
}
#define CP_COMMIT() asm volatile("cp.async.commit_group;" ::: "memory")
#define CP_WAIT0()  asm volatile("cp.async.wait_group 0;" ::: "memory")
#define CP_WAIT1()  asm volatile("cp.async.wait_group 1;" ::: "memory")

__device__ __forceinline__ void ldsm_x4(uint32_t a, uint32_t* r) {
    asm volatile("ldmatrix.sync.aligned.m8n8.x4.shared.b16 {%0,%1,%2,%3}, [%4];"
                 : "=r"(r[0]), "=r"(r[1]), "=r"(r[2]), "=r"(r[3]) : "r"(a));
}
__device__ __forceinline__ void ldsm_x2(uint32_t a, uint32_t* r) {
    asm volatile("ldmatrix.sync.aligned.m8n8.x2.shared.b16 {%0,%1}, [%2];"
                 : "=r"(r[0]), "=r"(r[1]) : "r"(a));
}
__device__ __forceinline__ void ldsm_x4t(uint32_t a, uint32_t* r) {
    asm volatile("ldmatrix.sync.aligned.m8n8.x4.trans.shared.b16 {%0,%1,%2,%3}, [%4];"
                 : "=r"(r[0]), "=r"(r[1]), "=r"(r[2]), "=r"(r[3]) : "r"(a));
}
__device__ __forceinline__ void mma16816(float* c, const uint32_t* a, const uint32_t* b) {
    asm volatile("mma.sync.aligned.m16n8k16.row.col.f32.bf16.bf16.f32 "
                 "{%0,%1,%2,%3},{%4,%5,%6,%7},{%8,%9},{%0,%1,%2,%3};"
                 : "+f"(c[0]), "+f"(c[1]), "+f"(c[2]), "+f"(c[3])
                 : "r"(a[0]), "r"(a[1]), "r"(a[2]), "r"(a[3]), "r"(b[0]), "r"(b[1]));
}
__device__ __forceinline__ uint32_t packbf(float lo, float hi) {
    uint32_t r; asm("cvt.rn.bf16x2.f32 %0, %1, %2;" : "=r"(r) : "f"(hi), "f"(lo)); return r;
}

__device__ __forceinline__ float fexp(float x) {
    x = fmaxf(x, -80.f);
    float y = x * 1.442695041f;
    float n = rintf(y);
    float f = y - n;
    float p =            1.8775767e-3f;
    p = fmaf(p, f, 8.9893397e-3f);
    p = fmaf(p, f, 5.5826318e-2f);
    p = fmaf(p, f, 2.4015361e-1f);
    p = fmaf(p, f, 6.9315308e-1f);
    p = fmaf(p, f, 9.9999994e-1f);
    return __int_as_float(__float_as_int(p) + ((int)n << 23));
}
// tanh for f16-precision target: 2 Newton steps suffice (~1e-6)
__device__ __forceinline__ float ftanh(float x) {
    float ax = fabsf(x);
    float e = fexp(-2.f * ax);
    float d = 1.f + e;
    float r = fmaf(-0.5f, d, 1.4571f);
    r = r * fmaf(-d, r, 2.f);
    r = r * fmaf(-d, r, 2.f);
    float t = (1.f - e) * r;
    return (x >= 0.f) ? t : -t;
}
__device__ __forceinline__ void split3(__nv_bfloat16* p, float v) {
    __nv_bfloat16 hi = __float2bfloat16(v);
    __nv_bfloat16 lo = __float2bfloat16(v - __bfloat162float(hi));
    p[0] = hi; p[Dm] = hi; p[2*Dm] = lo;
}
__device__ __forceinline__ void psplit(float x, float y, uint32_t& hi, uint32_t& lo) {
    float hx = __bfloat162float(__float2bfloat16(x));
    float hy = __bfloat162float(__float2bfloat16(y));
    hi = packbf(x, y);
    lo = packbf(x - hx, y - hy);
}

// -------- prep: weight packs + rope tables + layernorm(split) --------
#define NB_WQKV 28224
#define NB_WO   9408
#define NB_ROPE 128
__global__ void prep_kernel(const float* __restrict__ Wq, const float* __restrict__ Wk,
                            const float* __restrict__ Wv, const float* __restrict__ Wo,
                            const float* __restrict__ x, const float* __restrict__ lng,
                            const float* __restrict__ lnb,
                            __nv_bfloat16* __restrict__ wqkv, __nv_bfloat16* __restrict__ wocat,
                            float* __restrict__ cc, float* __restrict__ ss,
                            __nv_bfloat16* __restrict__ y)
{
    int bid = blockIdx.x, tid = threadIdx.x;
    if (bid < NB_WQKV) {
        size_t idx = (size_t)bid * 256 + tid;
        int k = (int)(idx % KCAT), n = (int)(idx / KCAT);
        const float* W = (n < Dm) ? Wq : ((n < 2*Dm) ? Wk : Wv);
        int c = n % Dm, kr = k % Dm, blk = k / Dm;
        float w = W[(size_t)kr * Dm + c];
        __nv_bfloat16 hi = __float2bfloat16(w);
        wqkv[idx] = (blk == 1) ? __float2bfloat16(w - __bfloat162float(hi)) : hi;
    } else if (bid < NB_WQKV + NB_WO) {
        size_t idx = (size_t)(bid - NB_WQKV) * 256 + tid;
        int k = (int)(idx % KCAT), n = (int)(idx / KCAT);
        int kr = k % Dm, blk = k / Dm;
        float w = Wo[(size_t)kr * Dm + n];
        __nv_bfloat16 hi = __float2bfloat16(w);
        wocat[idx] = (blk == 1) ? __float2bfloat16(w - __bfloat162float(hi)) : hi;
    } else if (bid < NB_WQKV + NB_WO + NB_ROPE) {
        int i = (bid - NB_WQKV - NB_WO) * 256 + tid;
        int n = i >> 5, d = i & 31;
        float freq = (float)n * powf(10000.f, -(float)(2*d) / 64.f);
        cc[i] = cosf(freq);
        ss[i] = sinf(freq);
    } else {
        int row = bid - (NB_WQKV + NB_WO + NB_ROPE);
        const float* xr = x + (size_t)row * Dm;
        float s = 0.f, s2 = 0.f;
        for (int i = tid; i < Dm; i += 256) { float v = xr[i]; s += v; s2 += v*v; }
        #pragma unroll
        for (int o = 16; o; o >>= 1) { s += __shfl_xor_sync(~0u, s, o); s2 += __shfl_xor_sync(~0u, s2, o); }
        __shared__ float ws[8], ws2[8];
        int w = tid >> 5;
        if ((tid & 31) == 0) { ws[w] = s; ws2[w] = s2; }
        __syncthreads();
        if (tid < 32) {
            s  = (tid < 8) ? ws[tid]  : 0.f;
            s2 = (tid < 8) ? ws2[tid] : 0.f;
            #pragma unroll
            for (int o = 4; o; o >>= 1) { s += __shfl_xor_sync(~0u, s, o); s2 += __shfl_xor_sync(~0u, s2, o); }
            if (tid == 0) { ws[0] = s; ws2[0] = s2; }
        }
        __syncthreads();
        float mu  = ws[0] * (1.f/Dm);
        float var = ws2[0] * (1.f/Dm) - mu*mu;
        float inv = rsqrtf(var + 1e-5f);
        __nv_bfloat16* yr = y + (size_t)row * KCAT;
        for (int i = tid; i < Dm; i += 256) {
            float v = (xr[i] - mu) * inv * lng[i] + lnb[i];
            split3(yr + i, v);
        }
    }
}

// -------- bias precompute (f16 output) --------
__global__ void bias_kernel(const float* __restrict__ bear, const float* __restrict__ wd,
                            const float* __restrict__ adj, const float* __restrict__ ww,
                            const float* __restrict__ wbv, __half* __restrict__ bias)
{
    int t = blockIdx.x;
    int b = blockIdx.y;
    int q0 = (t >> 5) * 32, k0 = (t & 31) * 32;
    __shared__ float tile[32][33];
    __shared__ float w0s[Hh], w1s[Hh], wbs[Hh];
    int tid = threadIdx.x;
    int j = tid & 31, i = tid >> 5;
    if (tid < Hh) { w0s[tid] = ww[tid]; w1s[tid] = ww[Hh + tid]; wbs[tid] = wbv[tid]; }
    #pragma unroll
    for (int p = 0; p < 4; p++)
        tile[i + p*8][j] = bear[(size_t)(k0 + i + p*8) * Nn + q0 + j];
    __syncthreads();
    #pragma unroll
    for (int p = 0; p < 4; p++) {
        int qi = i + p*8;
        int q = q0 + qi, k = k0 + j;
        float rb = fmodf(tile[j][qi] + 180.f, 360.f);
        float av = cosf((wd[b*Nn + q] - rb) * 0.017453292519943295f);
        float a  = adj[(size_t)q * Nn + k];
        bool on = (a > 0.f);
        size_t base = ((size_t)q << 10) + k;
        #pragma unroll
        for (int h = 0; h < Hh; h++) {
            float bv = on ? ftanh(fmaf(av, w0s[h], fmaf(a, w1s[h], wbs[h]))) : -1e30f;
            bias[(((size_t)(b*Hh + h)) << 20) + base] = __float2half(bv);
        }
    }
}

// -------- gemm stage loader: A 128x64, B 128x64 bf16 (pitch 144B) --------
__device__ __forceinline__ void load_stage(uint32_t abase,
                                           const __nv_bfloat16* __restrict__ A,
                                           const __nv_bfloat16* __restrict__ Bw,
                                           int m0, int n0, int k0)
{
    int tid = threadIdx.x;
    uint32_t bbase = abase + 128 * APITCH;
    #pragma unroll
    for (int p = 0; p < 4; p++) {
        int e = p * 256 + tid;
        int r = e >> 3, seg = e & 7;
        cp_async16(abase + r * APITCH + seg * 16, A + (size_t)(m0 + r) * KCAT + k0 + seg * 8);
    }
    #pragma unroll
    for (int p = 0; p < 4; p++) {
        int e = p * 256 + tid;
        int r = e >> 3, seg = e & 7;
        cp_async16(bbase + r * APITCH + seg * 16, Bw + (size_t)(n0 + r) * KCAT + k0 + seg * 8);
    }
}

// -------- mma GEMM, 128x128 tile, K-chunk 64, 3-stage, occ 2 --------
template<int MODE>
__global__ void __launch_bounds__(256, 2)
gemm_mma(const __nv_bfloat16* __restrict__ A, const __nv_bfloat16* __restrict__ Bw,
         const float* __restrict__ cosp, const float* __restrict__ sinp,
         const float* __restrict__ res, void* outQ, void* outK, void* outV)
{
    extern __shared__ char dsm[];
    uint32_t sb = smem_u32(dsm);
    float* sep = (float*)dsm;

    int tid = threadIdx.x, wid = tid >> 5, lane = tid & 31;
    int wm = wid >> 2, wn = wid & 3;
    int m0 = blockIdx.y * 128, n0 = blockIdx.x * 128;

    float acc[4][4][4];
    #pragma unroll
    for (int i = 0; i < 4; i++)
        #pragma unroll
        for (int j = 0; j < 4; j++)
            #pragma unroll
            for (int r = 0; r < 4; r++) acc[i][j][r] = 0.f;

    int gq = lane >> 3, lr = lane & 7;
    uint32_t a_off = (uint32_t)((wm*64 + lr + (gq & 1)*8) * APITCH + (gq >> 1)*16);
    uint32_t b_off = (uint32_t)((wn*32 + lr) * APITCH + ((lane & 8) ? 16 : 0) + 128*APITCH);

    load_stage(sb + 0*STG, A, Bw, m0, n0, 0);
    CP_COMMIT();
    load_stage(sb + 1*STG, A, Bw, m0, n0, 64);
    CP_COMMIT();

    const int NT = KCAT / 64;   // 42
    int slot = 0;
    for (int i = 0; i < NT; i++) {
        if (i + 1 < NT) CP_WAIT1(); else CP_WAIT0();
        __syncthreads();
        uint32_t stg = sb + slot * STG;
        #pragma unroll
        for (int ks = 0; ks < 4; ks++) {
            uint32_t afr[4][4], bfr[4][2];
            #pragma unroll
            for (int mt = 0; mt < 4; mt++) ldsm_x4(stg + a_off + mt*(16*APITCH) + ks*32, afr[mt]);
            #pragma unroll
            for (int nt = 0; nt < 4; nt++) ldsm_x2(stg + b_off + nt*(8*APITCH) + ks*32, bfr[nt]);
            #pragma unroll
            for (int mt = 0; mt < 4; mt++)
                #pragma unroll
                for (int nt = 0; nt < 4; nt++)
                    mma16816(acc[mt][nt], afr[mt], bfr[nt]);
        }
        if (i + 2 < NT) {
            int ns = slot + 2; if (ns >= 3) ns -= 3;
            load_stage(sb + ns * STG, A, Bw, m0, n0, (i + 2) * 64);
            CP_COMMIT();
        }
        slot++; if (slot == 3) slot = 0;
    }
    __syncthreads();

    #pragma unroll
    for (int half = 0; half < 2; half++) {
        if (wm == half) {
            #pragma unroll
            for (int mt = 0; mt < 4; mt++)
                #pragma unroll
                for (int nt = 0; nt < 4; nt++)
                    #pragma unroll
                    for (int ri = 0; ri < 4; ri++) {
                        int r = mt*16 + (lane >> 2) + ((ri >> 1) * 8);
                        int n = wn*32 + nt*8 + ((lane & 3) * 2) + (ri & 1);
                        sep[r * EPITCH + n] = acc[mt][nt][ri];
                    }
        }
        __syncthreads();

        if (MODE == 0) {
            int tile = blockIdx.x;
            int region = tile / 7;
            int cbase = (tile % 7) * 128;
            __nv_bfloat16* base = (region == 0) ? (__nv_bfloat16*)outQ
                                : (region == 1) ? (__nv_bfloat16*)outK
                                                : (__nv_bfloat16*)outV;
            for (int idx = tid; idx < 64*128; idx += 256) {
                int r = idx >> 7, c = idx & 127;
                int m = m0 + half*64 + r;
                int bqi = m >> 10, n = m & 1023;
                int ccx = cbase + c;
                int head = ccx >> 6, d = ccx & 63;
                float val;
                if (region < 2) {
                    if (d < 32) {
                        float x1 = sep[r*EPITCH + c], x2 = sep[r*EPITCH + c + 32];
                        val = x1 * cosp[n*32 + d] - x2 * sinp[n*32 + d];
                    } else {
                        float x2 = sep[r*EPITCH + c], x1 = sep[r*EPITCH + c - 32];
                        int dd = d - 32;
                        val = x2 * cosp[n*32 + dd] + x1 * sinp[n*32 + dd];
                    }
                } else {
                    val = sep[r*EPITCH + c];
                }
                __nv_bfloat16 hv = __float2bfloat16(val);
                __nv_bfloat16 lv = __float2bfloat16(val - __bfloat162float(hv));
                size_t row = ((size_t)bqi * Hh + head) * Nn + n;
                base[row*128 + d]      = hv;
                base[row*128 + 64 + d] = lv;
            }
        } else {
            float* outp = (float*)outQ;
            for (int idx = tid; idx < 64*128; idx += 256) {
                int r = idx >> 7, c = idx & 127;
                int m = m0 + half*64 + r;
                size_t o = (size_t)m * Dm + n0 + c;
                outp[o] = sep[r*EPITCH + c] + res[o];
            }
        }
        __syncthreads();
    }
}

// -------- flash attn chunk loader: 128 rows x 256B, pitch 272, 256 threads --------
__device__ __forceinline__ void ld_chunk128(uint32_t dst, const __nv_bfloat16* __restrict__ src,
                                            int tok0)
{
    #pragma unroll
    for (int p = 0; p < 8; p++) {
        int e = p * 256 + threadIdx.x;
        int r = e >> 4, s = e & 15;
        cp_async16(dst + r * 272 + s * 16, src + (size_t)(tok0 + r) * 128 + s * 8);
    }
}

// -------- single-pass flash attention: block (b,h,16q), 256 threads, occ 2 --------
__global__ void __launch_bounds__(256, 2)
attn_flash(const __nv_bfloat16* __restrict__ Qc, const __nv_bfloat16* __restrict__ Kc,
           const __nv_bfloat16* __restrict__ Vc, const __half* __restrict__ bias,
           __nv_bfloat16* __restrict__ out)
{
    extern __shared__ char dsm[];
    uint32_t sb = smem_u32(dsm);
    uint32_t qs = sb;
    uint32_t bufA = sb + 4352;
    uint32_t bufB = bufA + 34816;
    float* part = (float*)(dsm + 4352);
    float* mrow = (float*)(dsm + 4352 + 2*34816);
    float* srow = mrow + 128;
    float* Sfin = srow + 128;

    int tid = threadIdx.x, wid = tid >> 5, lane = tid & 31;
    int h = blockIdx.y, b = blockIdx.z;
    int q0 = blockIdx.x * 16;
    size_t bh = ((size_t)b * Hh + h) * Nn;
    const __nv_bfloat16* Kbh = Kc + bh * 128;
    const __nv_bfloat16* Vbh = Vc + bh * 128;
    const __half* biasbh = bias + (((size_t)(b*Hh + h)) << 20);

    {
        int r = tid >> 4, s = tid & 15;
        cp_async16(qs + r*272 + s*16, Qc + (bh + q0 + r) * 128 + s * 8);
    }
    CP_COMMIT();
    ld_chunk128(bufA, Kbh, 0); CP_COMMIT();
    ld_chunk128(bufB, Vbh, 0); CP_COMMIT();

    int r_ = lane >> 2, cl = 2*(lane & 3);

    const __half* bb0 = biasbh + (((size_t)(q0 + r_))     << 10) + wid*16;
    const __half* bb1 = biasbh + (((size_t)(q0 + r_ + 8)) << 10) + wid*16;
    __half2 nb00 = *(const __half2*)(bb0 + cl);
    __half2 nb01 = *(const __half2*)(bb0 + cl + 8);
    __half2 nb10 = *(const __half2*)(bb1 + cl);
    __half2 nb11 = *(const __half2*)(bb1 + cl + 8);

    float m0 = -1e30f, m1 = -1e30f, sum0 = 0.f, sum1 = 0.f;
    float acc[8][4];
    #pragma unroll
    for (int i = 0; i < 8; i++)
        #pragma unroll
        for (int r = 0; r < 4; r++) acc[i][r] = 0.f;
    uint32_t afr[8][4];

    for (int c = 0; c < 8; c++) {
        float2 u00 = __half22float2(nb00), u01 = __half22float2(nb01);
        float2 u10 = __half22float2(nb10), u11 = __half22float2(nb11);
        if (c < 7) {
            int o = (c + 1) * 128;
            nb00 = *(const __half2*)(bb0 + o + cl);
            nb01 = *(const __half2*)(bb0 + o + cl + 8);
            nb10 = *(const __half2*)(bb1 + o + cl);
            nb11 = *(const __half2*)(bb1 + o + cl + 8);
        }
        CP_WAIT1();
        __syncthreads();
        if (c == 0) {
            int gq = lane >> 3, lr = lane & 7;
            uint32_t a_off = qs + (uint32_t)((lr + (gq & 1)*8) * 272 + (gq >> 1)*16);
            #pragma unroll
            for (int kt = 0; kt < 8; kt++) ldsm_x4(a_off + kt*32, afr[kt]);
        }

        float dd0[4] = {0.f,0.f,0.f,0.f}, dd1[4] = {0.f,0.f,0.f,0.f};
        #pragma unroll
        for (int nt = 0; nt < 2; nt++) {
            uint32_t base = bufA + (uint32_t)((wid*16 + nt*8 + (lane & 7)) * 272
                                              + ((lane >> 3) & 1) * 16);
            uint32_t kfh[8], kfl[8];
            #pragma unroll
            for (int j = 0; j < 4; j++) ldsm_x2(base + j*32, kfh + 2*j);
            #pragma unroll
            for (int j = 0; j < 4; j++) ldsm_x2(base + 128 + j*32, kfl + 2*j);
            float* d = nt ? dd1 : dd0;
            #pragma unroll
            for (int t = 0; t < 4; t++) mma16816(d, afr[t],   kfh + 2*t);
            #pragma unroll
            for (int t = 0; t < 4; t++) mma16816(d, afr[t],   kfl + 2*t);
            #pragma unroll
            for (int t = 0; t < 4; t++) mma16816(d, afr[4+t], kfh + 2*t);
        }
        dd0[0] = fmaf(dd0[0], 0.125f, u00.x); dd0[1] = fmaf(dd0[1], 0.125f, u00.y);
        dd0[2] = fmaf(dd0[2], 0.125f, u10.x); dd0[3] = fmaf(dd0[3], 0.125f, u10.y);
        dd1[0] = fmaf(dd1[0], 0.125f, u01.x); dd1[1] = fmaf(dd1[1], 0.125f, u01.y);
        dd1[2] = fmaf(dd1[2], 0.125f, u11.x); dd1[3] = fmaf(dd1[3], 0.125f, u11.y);

        float rm0 = fmaxf(fmaxf(dd0[0], dd0[1]), fmaxf(dd1[0], dd1[1]));
        float rm1 = fmaxf(fmaxf(dd0[2], dd0[3]), fmaxf(dd1[2], dd1[3]));
        rm0 = fmaxf(rm0, __shfl_xor_sync(~0u, rm0, 1));
        rm0 = fmaxf(rm0, __shfl_xor_sync(~0u, rm0, 2));
        rm1 = fmaxf(rm1, __shfl_xor_sync(~0u, rm1, 1));
        rm1 = fmaxf(rm1, __shfl_xor_sync(~0u, rm1, 2));
        float M0 = fmaxf(m0, rm0), M1 = fmaxf(m1, rm1);
        float sc0 = fexp(m0 - M0), sc1 = fexp(m1 - M1);
        dd0[0] = fexp(dd0[0] - M0); dd0[1] = fexp(dd0[1] - M0);
        dd0[2] = fexp(dd0[2] - M1); dd0[3] = fexp(dd0[3] - M1);
        dd1[0] = fexp(dd1[0] - M0); dd1[1] = fexp(dd1[1] - M0);
        dd1[2] = fexp(dd1[2] - M1); dd1[3] = fexp(dd1[3] - M1);
        float ps0 = dd0[0] + dd0[1] + dd1[0] + dd1[1];
        float ps1 = dd0[2] + dd0[3] + dd1[2] + dd1[3];
        ps0 += __shfl_xor_sync(~0u, ps0, 1); ps0 += __shfl_xor_sync(~0u, ps0, 2);
        ps1 += __shfl_xor_sync(~0u, ps1, 1); ps1 += __shfl_xor_sync(~0u, ps1, 2);
        sum0 = sum0 * sc0 + ps0;
        sum1 = sum1 * sc1 + ps1;
        m0 = M0; m1 = M1;
        #pragma unroll
        for (int i = 0; i < 8; i++) {
            acc[i][0] *= sc0; acc[i][1] *= sc0;
            acc[i][2] *= sc1; acc[i][3] *= sc1;
        }
        uint32_t phi[4], plo[4];
        psplit(dd0[0], dd0[1], phi[0], plo[0]);
        psplit(dd0[2], dd0[3], phi[1], plo[1]);
        psplit(dd1[0], dd1[1], phi[2], plo[2]);
        psplit(dd1[2], dd1[3], phi[3], plo[3]);

        __syncthreads();
        if (c < 7) { ld_chunk128(bufA, Kbh, (c + 1) * 128); CP_COMMIT(); CP_WAIT1(); }
        else       { CP_WAIT0(); }
        __syncthreads();

        #pragma unroll
        for (int hd = 0; hd < 2; hd++) {
            uint32_t vaddr = bufB + (uint32_t)((wid*16 + ((lane >> 3) & 1)*8 + (lane & 7)) * 272
                                               + ((lane >> 4) & 1) * 16 + hd*64);
            uint32_t vfh[4][2], vfl[4][2];
            #pragma unroll
            for (int p = 0; p < 2; p++) {
                uint32_t r4[4];
                ldsm_x4t(vaddr + p*32, r4);
                vfh[2*p][0] = r4[0]; vfh[2*p][1] = r4[1];
                vfh[2*p+1][0] = r4[2]; vfh[2*p+1][1] = r4[3];
                ldsm_x4t(vaddr + 128 + p*32, r4);
                vfl[2*p][0] = r4[0]; vfl[2*p][1] = r4[1];
                vfl[2*p+1][0] = r4[2]; vfl[2*p+1][1] = r4[3];
            }
            #pragma unroll
            for (int nt = 0; nt < 4; nt++) {
                mma16816(acc[hd*4 + nt], phi, vfh[nt]);
                mma16816(acc[hd*4 + nt], phi, vfl[nt]);
                mma16816(acc[hd*4 + nt], plo, vfh[nt]);
            }
        }
        __syncthreads();
        if (c < 7) { ld_chunk128(bufB, Vbh, (c + 1) * 128); CP_COMMIT(); }
    }

    // ---- flash merge across 8 warps ----
    if ((lane & 3) == 0) {
        mrow[wid*16 + r_]     = m0;  srow[wid*16 + r_]     = sum0;
        mrow[wid*16 + r_ + 8] = m1;  srow[wid*16 + r_ + 8] = sum1;
    }
    __syncthreads();
    float M0g = -1e30f, M1g = -1e30f;
    #pragma unroll
    for (int w = 0; w < 8; w++) {
        M0g = fmaxf(M0g, mrow[w*16 + r_]);
        M1g = fmaxf(M1g, mrow[w*16 + r_ + 8]);
    }
    float S0g = 0.f, S1g = 0.f;
    #pragma unroll
    for (int w = 0; w < 8; w++) {
        S0g += srow[w*16 + r_]     * fexp(mrow[w*16 + r_]     - M0g);
        S1g += srow[w*16 + r_ + 8] * fexp(mrow[w*16 + r_ + 8] - M1g);
    }
    if (wid == 0 && (lane & 3) == 0) { Sfin[r_] = S0g; Sfin[r_ + 8] = S1g; }
    float f0 = fexp(m0 - M0g), f1 = fexp(m1 - M1g);
    #pragma unroll
    for (int i = 0; i < 8; i++) {
        int hd = i >> 2, nt = i & 3;
        int d = hd*32 + nt*8 + cl;
        *(float2*)(part + wid*1024 + r_*64 + d) =
            make_float2(acc[i][0] * f0, acc[i][1] * f0);
        *(float2*)(part + wid*1024 + (r_+8)*64 + d) =
            make_float2(acc[i][2] * f1, acc[i][3] * f1);
    }
    __syncthreads();
    for (int o = tid; o < 1024; o += 256) {
        float s = 0.f;
        #pragma unroll
        for (int w = 0; w < 8; w++) s += part[w*1024 + o];
        int qi = o >> 6, d = o & 63;
        s /= Sfin[qi];
        int col = h * 64 + d;
        split3(out + (size_t)(b * Nn + q0 + qi) * KCAT + col, s);
    }
}

// -------------------- launch --------------------
extern "C" void kernel_launch(void* const* d_in, const int* in_sizes, int n_in,
                              void* d_out, int out_size)
{
    const float* node = (const float*)d_in[0];
    const float* adj  = (const float*)d_in[1];
    const float* wd   = (const float*)d_in[2];
    const float* bear = (const float*)d_in[3];
    const float* Wq   = (const float*)d_in[4];
    const float* Wk   = (const float*)d_in[5];
    const float* Wv   = (const float*)d_in[6];
    const float* Wo   = (const float*)d_in[7];
    const float* lng  = (const float*)d_in[8];
    const float* lnb  = (const float*)d_in[9];
    const float* ww   = (const float*)d_in[10];
    const float* wbv  = (const float*)d_in[11];
    float* out = (float*)d_out;

    __nv_bfloat16 *xcat, *wqkv, *wocat, *aocat, *Qc, *Kc, *Vc;
    __half* biasp;
    float *cosp, *sinp;
    cudaGetSymbolAddress((void**)&xcat,  g_xcat);
    cudaGetSymbolAddress((void**)&wqkv,  g_wqkv);
    cudaGetSymbolAddress((void**)&wocat, g_wocat);
    cudaGetSymbolAddress((void**)&aocat, g_aocat);
    cudaGetSymbolAddress((void**)&Qc,    g_Qc);
    cudaGetSymbolAddress((void**)&Kc,    g_Kc);
    cudaGetSymbolAddress((void**)&Vc,    g_Vc);
    cudaGetSymbolAddress((void**)&biasp, g_bias);
    cudaGetSymbolAddress((void**)&cosp,  g_cos);
    cudaGetSymbolAddress((void**)&sinp,  g_sin);

    const int SMEM_GEMM = 3 * STG;                                // 110592
    const int SMEM_ATTN = 4352 + 2*34816 + (128 + 128 + 16) * 4;  // 75136
    cudaFuncSetAttribute(gemm_mma<0>, cudaFuncAttributeMaxDynamicSharedMemorySize, SMEM_GEMM);
    cudaFuncSetAttribute(gemm_mma<1>, cudaFuncAttributeMaxDynamicSharedMemorySize, SMEM_GEMM);
    cudaFuncSetAttribute(attn_flash,  cudaFuncAttributeMaxDynamicSharedMemorySize, SMEM_ATTN);

    prep_kernel<<<NB_WQKV + NB_WO + NB_ROPE + BN, 256>>>(Wq, Wk, Wv, Wo, node, lng, lnb,
                                                         wqkv, wocat, cosp, sinp, xcat);
    bias_kernel<<<dim3(1024, Bq), 256>>>(bear, wd, adj, ww, wbv, biasp);
    gemm_mma<0><<<dim3(KCAT/128, BN/128), 256, SMEM_GEMM>>>(xcat, wqkv, cosp, sinp,
                                                            nullptr, Qc, Kc, Vc);
    attn_flash<<<dim3(Nn/16, Hh, Bq), 256, SMEM_ATTN>>>(Qc, Kc, Vc, biasp, aocat);
    gemm_mma<1><<<dim3(Dm/128, BN/128), 256, SMEM_GEMM>>>(aocat, wocat, cosp, sinp,
                                                          node, out, nullptr, nullptr);
}

// round 14
// speedup vs baseline: 1.3873x; 1.0321x over previous
#include <cuda_runtime.h>
#include <cuda_bf16.h>
#include <cuda_fp16.h>
#include <math.h>
#include <stdint.h>

#define Bq   8
#define Nn   1024
#define Dm   896
#define Hh   14
#define Dh   64
#define BN   (Bq*Nn)
#define KCAT 2688
#define EPITCH 132
#define APITCH 144          // gemm stage row pitch (64 bf16 + 16B pad)
#define STG   36864         // stage bytes: A 128*144 + B 128*144

__device__ __align__(128) __nv_bfloat16 g_xcat[(size_t)BN*KCAT];
__device__ __align__(128) __nv_bfloat16 g_wqkv[(size_t)KCAT*KCAT];
__device__ __align__(128) __nv_bfloat16 g_wocat[(size_t)Dm*KCAT];
__device__ __align__(128) __nv_bfloat16 g_aocat[(size_t)BN*KCAT];
__device__ __align__(128) __nv_bfloat16 g_Qc[(size_t)Bq*Hh*Nn*128];
__device__ __align__(128) __nv_bfloat16 g_Kc[(size_t)Bq*Hh*Nn*128];
__device__ __align__(128) __nv_bfloat16 g_Vc[(size_t)Bq*Hh*Nn*128];
__device__ __half g_bias[(size_t)Bq*Hh*Nn*Nn];
__device__ float g_cos[Nn*32];
__device__ float g_sin[Nn*32];

__device__ __forceinline__ uint32_t smem_u32(const void* p) {
    uint32_t a;
    asm("{ .reg .u64 t; cvta.to.shared.u64 t, %1; cvt.u32.u64 %0, t; }" : "=r"(a) : "l"(p));
    return a;
}
__device__ __forceinline__ void cp_async16(uint32_t dst, const void* src) {
    asm volatile("cp.async.cg.shared.global [%0], [%1], 16;" :: "r"(dst), "l"(src));
}
#define CP_COMMIT() asm volatile("cp.async.commit_group;" ::: "memory")
#define CP_WAIT0()  asm volatile("cp.async.wait_group 0;" ::: "memory")
#define CP_WAIT1()  asm volatile("cp.async.wait_group 1;" ::: "memory")

__device__ __forceinline__ void ldsm_x4(uint32_t a, uint32_t* r) {
    asm volatile("ldmatrix.sync.aligned.m8n8.x4.shared.b16 {%0,%1,%2,%3}, [%4];"
                 : "=r"(r[0]), "=r"(r[1]), "=r"(r[2]), "=r"(r[3]) : "r"(a));
}
__device__ __forceinline__ void ldsm_x2(uint32_t a, uint32_t* r) {
    asm volatile("ldmatrix.sync.aligned.m8n8.x2.shared.b16 {%0,%1}, [%2];"
                 : "=r"(r[0]), "=r"(r[1]) : "r"(a));
}
__device__ __forceinline__ void ldsm_x4t(uint32_t a, uint32_t* r) {
    asm volatile("ldmatrix.sync.aligned.m8n8.x4.trans.shared.b16 {%0,%1,%2,%3}, [%4];"
                 : "=r"(r[0]), "=r"(r[1]), "=r"(r[2]), "=r"(r[3]) : "r"(a));
}
__device__ __forceinline__ void mma16816(float* c, const uint32_t* a, const uint32_t* b) {
    asm volatile("mma.sync.aligned.m16n8k16.row.col.f32.bf16.bf16.f32 "
                 "{%0,%1,%2,%3},{%4,%5,%6,%7},{%8,%9},{%0,%1,%2,%3};"
                 : "+f"(c[0]), "+f"(c[1]), "+f"(c[2]), "+f"(c[3])
                 : "r"(a[0]), "r"(a[1]), "r"(a[2]), "r"(a[3]), "r"(b[0]), "r"(b[1]));
}
__device__ __forceinline__ uint32_t packbf(float lo, float hi) {
    uint32_t r; asm("cvt.rn.bf16x2.f32 %0, %1, %2;" : "=r"(r) : "f"(hi), "f"(lo)); return r;
}

__device__ __forceinline__ float fexp(float x) {
    x = fmaxf(x, -80.f);
    float y = x * 1.442695041f;
    float n = rintf(y);
    float f = y - n;
    float p =            1.8775767e-3f;
    p = fmaf(p, f, 8.9893397e-3f);
    p = fmaf(p, f, 5.5826318e-2f);
    p = fmaf(p, f, 2.4015361e-1f);
    p = fmaf(p, f, 6.9315308e-1f);
    p = fmaf(p, f, 9.9999994e-1f);
    return __int_as_float(__float_as_int(p) + ((int)n << 23));
}
__device__ __forceinline__ float ftanh(float x) {
    float ax = fabsf(x);
    float e = fexp(-2.f * ax);
    float d = 1.f + e;
    float r = fmaf(-0.5f, d, 1.4571f);
    r = r * fmaf(-d, r, 2.f);
    r = r * fmaf(-d, r, 2.f);
    float t = (1.f - e) * r;
    return (x >= 0.f) ? t : -t;
}
__device__ __forceinline__ void split3(__nv_bfloat16* p, float v) {
    __nv_bfloat16 hi = __float2bfloat16(v);
    __nv_bfloat16 lo = __float2bfloat16(v - __bfloat162float(hi));
    p[0] = hi; p[Dm] = hi; p[2*Dm] = lo;
}
__device__ __forceinline__ void psplit(float x, float y, uint32_t& hi, uint32_t& lo) {
    float hx = __bfloat162float(__float2bfloat16(x));
    float hy = __bfloat162float(__float2bfloat16(y));
    hi = packbf(x, y);
    lo = packbf(x - hx, y - hy);
}

// -------- mega prep: transposed weight packs + rope + layernorm + bias --------
#define NBT_W   2352          // 3 regions x 28x28 tiles
#define NBT_WO  784           // 28x28
#define NBT_ROPE 128
#define NBT_LN  BN            // 8192
#define NBT_BIAS 8192         // 1024 tiles x 8 batches
__global__ void prep_kernel(const float* __restrict__ Wq, const float* __restrict__ Wk,
                            const float* __restrict__ Wv, const float* __restrict__ Wo,
                            const float* __restrict__ x, const float* __restrict__ lng,
                            const float* __restrict__ lnb,
                            const float* __restrict__ bear, const float* __restrict__ wd,
                            const float* __restrict__ adj, const float* __restrict__ ww,
                            const float* __restrict__ wbv,
                            __nv_bfloat16* __restrict__ wqkv, __nv_bfloat16* __restrict__ wocat,
                            float* __restrict__ cc, float* __restrict__ ss,
                            __nv_bfloat16* __restrict__ y, __half* __restrict__ bias)
{
    __shared__ float tile[32][33];
    __shared__ float w0s[Hh], w1s[Hh], wbs[Hh];
    __shared__ float ws[8], ws2[8];

    int bid = blockIdx.x, tid = threadIdx.x;
    int j = tid & 31, i = tid >> 5;

    if (bid < NBT_W) {
        // QKV weight pack via smem transpose: out[n][k] from W[k%Dm][n%Dm]
        int region = bid / 784;
        int tt = bid % 784;
        int k0 = (tt / 28) * 32, c0 = (tt % 28) * 32;
        const float* W = (region == 0) ? Wq : ((region == 1) ? Wk : Wv);
        #pragma unroll
        for (int p = 0; p < 4; p++)
            tile[i + p*8][j] = W[(size_t)(k0 + i + p*8) * Dm + c0 + j];
        __syncthreads();
        #pragma unroll
        for (int p = 0; p < 4; p++) {
            int ii = i + p*8;
            float w = tile[j][ii];                    // = W[k0+j][c0+ii]
            __nv_bfloat16 hi = __float2bfloat16(w);
            __nv_bfloat16 lo = __float2bfloat16(w - __bfloat162float(hi));
            size_t rowo = (size_t)(region*Dm + c0 + ii) * KCAT + (k0 + j);
            wqkv[rowo]          = hi;
            wqkv[rowo + Dm]     = lo;
            wqkv[rowo + 2*Dm]   = hi;
        }
    } else if (bid < NBT_W + NBT_WO) {
        // Wo pack: out[n][k] from Wo[k%Dm][n]
        int tt = bid - NBT_W;
        int k0 = (tt / 28) * 32, c0 = (tt % 28) * 32;
        #pragma unroll
        for (int p = 0; p < 4; p++)
            tile[i + p*8][j] = Wo[(size_t)(k0 + i + p*8) * Dm + c0 + j];
        __syncthreads();
        #pragma unroll
        for (int p = 0; p < 4; p++) {
            int ii = i + p*8;
            float w = tile[j][ii];
            __nv_bfloat16 hi = __float2bfloat16(w);
            __nv_bfloat16 lo = __float2bfloat16(w - __bfloat162float(hi));
            size_t rowo = (size_t)(c0 + ii) * KCAT + (k0 + j);
            wocat[rowo]        = hi;
            wocat[rowo + Dm]   = lo;
            wocat[rowo + 2*Dm] = hi;
        }
    } else if (bid < NBT_W + NBT_WO + NBT_ROPE) {
        int e = (bid - NBT_W - NBT_WO) * 256 + tid;
        int n = e >> 5, d = e & 31;
        float freq = (float)n * powf(10000.f, -(float)(2*d) / 64.f);
        cc[e] = cosf(freq);
        ss[e] = sinf(freq);
    } else if (bid < NBT_W + NBT_WO + NBT_ROPE + NBT_LN) {
        // layernorm + split-pack
        int row = bid - (NBT_W + NBT_WO + NBT_ROPE);
        const float* xr = x + (size_t)row * Dm;
        float s = 0.f, s2 = 0.f;
        for (int e = tid; e < Dm; e += 256) { float v = xr[e]; s += v; s2 += v*v; }
        #pragma unroll
        for (int o = 16; o; o >>= 1) { s += __shfl_xor_sync(~0u, s, o); s2 += __shfl_xor_sync(~0u, s2, o); }
        int w = tid >> 5;
        if ((tid & 31) == 0) { ws[w] = s; ws2[w] = s2; }
        __syncthreads();
        if (tid < 32) {
            s  = (tid < 8) ? ws[tid]  : 0.f;
            s2 = (tid < 8) ? ws2[tid] : 0.f;
            #pragma unroll
            for (int o = 4; o; o >>= 1) { s += __shfl_xor_sync(~0u, s, o); s2 += __shfl_xor_sync(~0u, s2, o); }
            if (tid == 0) { ws[0] = s; ws2[0] = s2; }
        }
        __syncthreads();
        float mu  = ws[0] * (1.f/Dm);
        float var = ws2[0] * (1.f/Dm) - mu*mu;
        float inv = rsqrtf(var + 1e-5f);
        __nv_bfloat16* yr = y + (size_t)row * KCAT;
        for (int e = tid; e < Dm; e += 256) {
            float v = (xr[e] - mu) * inv * lng[e] + lnb[e];
            split3(yr + e, v);
        }
    } else {
        // masked wind bias (f16), all heads
        int t = bid - (NBT_W + NBT_WO + NBT_ROPE + NBT_LN);
        int b = t >> 10;
        t &= 1023;
        int q0 = (t >> 5) * 32, k0 = (t & 31) * 32;
        if (tid < Hh) { w0s[tid] = ww[tid]; w1s[tid] = ww[Hh + tid]; wbs[tid] = wbv[tid]; }
        #pragma unroll
        for (int p = 0; p < 4; p++)
            tile[i + p*8][j] = bear[(size_t)(k0 + i + p*8) * Nn + q0 + j];
        __syncthreads();
        #pragma unroll
        for (int p = 0; p < 4; p++) {
            int qi = i + p*8;
            int q = q0 + qi, k = k0 + j;
            float rb = fmodf(tile[j][qi] + 180.f, 360.f);
            float av = cosf((wd[b*Nn + q] - rb) * 0.017453292519943295f);
            float a  = adj[(size_t)q * Nn + k];
            bool on = (a > 0.f);
            size_t base = ((size_t)q << 10) + k;
            #pragma unroll
            for (int h = 0; h < Hh; h++) {
                float bv = on ? ftanh(fmaf(av, w0s[h], fmaf(a, w1s[h], wbs[h]))) : -1e30f;
                bias[(((size_t)(b*Hh + h)) << 20) + base] = __float2half(bv);
            }
        }
    }
}

// -------- gemm stage loader: A 128x64, B 128x64 bf16 (pitch 144B) --------
__device__ __forceinline__ void load_stage(uint32_t abase,
                                           const __nv_bfloat16* __restrict__ A,
                                           const __nv_bfloat16* __restrict__ Bw,
                                           int m0, int n0, int k0)
{
    int tid = threadIdx.x;
    uint32_t bbase = abase + 128 * APITCH;
    #pragma unroll
    for (int p = 0; p < 4; p++) {
        int e = p * 256 + tid;
        int r = e >> 3, seg = e & 7;
        cp_async16(abase + r * APITCH + seg * 16, A + (size_t)(m0 + r) * KCAT + k0 + seg * 8);
    }
    #pragma unroll
    for (int p = 0; p < 4; p++) {
        int e = p * 256 + tid;
        int r = e >> 3, seg = e & 7;
        cp_async16(bbase + r * APITCH + seg * 16, Bw + (size_t)(n0 + r) * KCAT + k0 + seg * 8);
    }
}

// -------- mma GEMM, 128x128 tile, K-chunk 64, 3-stage, occ 2 --------
template<int MODE>
__global__ void __launch_bounds__(256, 2)
gemm_mma(const __nv_bfloat16* __restrict__ A, const __nv_bfloat16* __restrict__ Bw,
         const float* __restrict__ cosp, const float* __restrict__ sinp,
         const float* __restrict__ res, void* outQ, void* outK, void* outV)
{
    extern __shared__ char dsm[];
    uint32_t sb = smem_u32(dsm);
    float* sep = (float*)dsm;

    int tid = threadIdx.x, wid = tid >> 5, lane = tid & 31;
    int wm = wid >> 2, wn = wid & 3;
    int m0 = blockIdx.y * 128, n0 = blockIdx.x * 128;

    float acc[4][4][4];
    #pragma unroll
    for (int i = 0; i < 4; i++)
        #pragma unroll
        for (int j = 0; j < 4; j++)
            #pragma unroll
            for (int r = 0; r < 4; r++) acc[i][j][r] = 0.f;

    int gq = lane >> 3, lr = lane & 7;
    uint32_t a_off = (uint32_t)((wm*64 + lr + (gq & 1)*8) * APITCH + (gq >> 1)*16);
    uint32_t b_off = (uint32_t)((wn*32 + lr) * APITCH + ((lane & 8) ? 16 : 0) + 128*APITCH);

    load_stage(sb + 0*STG, A, Bw, m0, n0, 0);
    CP_COMMIT();
    load_stage(sb + 1*STG, A, Bw, m0, n0, 64);
    CP_COMMIT();

    const int NT = KCAT / 64;   // 42
    int slot = 0;
    for (int i = 0; i < NT; i++) {
        if (i + 1 < NT) CP_WAIT1(); else CP_WAIT0();
        __syncthreads();
        uint32_t stg = sb + slot * STG;
        #pragma unroll
        for (int ks = 0; ks < 4; ks++) {
            uint32_t afr[4][4], bfr[4][2];
            #pragma unroll
            for (int mt = 0; mt < 4; mt++) ldsm_x4(stg + a_off + mt*(16*APITCH) + ks*32, afr[mt]);
            #pragma unroll
            for (int nt = 0; nt < 4; nt++) ldsm_x2(stg + b_off + nt*(8*APITCH) + ks*32, bfr[nt]);
            #pragma unroll
            for (int mt = 0; mt < 4; mt++)
                #pragma unroll
                for (int nt = 0; nt < 4; nt++)
                    mma16816(acc[mt][nt], afr[mt], bfr[nt]);
        }
        if (i + 2 < NT) {
            int ns = slot + 2; if (ns >= 3) ns -= 3;
            load_stage(sb + ns * STG, A, Bw, m0, n0, (i + 2) * 64);
            CP_COMMIT();
        }
        slot++; if (slot == 3) slot = 0;
    }
    __syncthreads();

    #pragma unroll
    for (int half = 0; half < 2; half++) {
        if (wm == half) {
            #pragma unroll
            for (int mt = 0; mt < 4; mt++)
                #pragma unroll
                for (int nt = 0; nt < 4; nt++)
                    #pragma unroll
                    for (int ri = 0; ri < 4; ri++) {
                        int r = mt*16 + (lane >> 2) + ((ri >> 1) * 8);
                        int n = wn*32 + nt*8 + ((lane & 3) * 2) + (ri & 1);
                        sep[r * EPITCH + n] = acc[mt][nt][ri];
                    }
        }
        __syncthreads();

        if (MODE == 0) {
            int tile = blockIdx.x;
            int region = tile / 7;
            int cbase = (tile % 7) * 128;
            __nv_bfloat16* base = (region == 0) ? (__nv_bfloat16*)outQ
                                : (region == 1) ? (__nv_bfloat16*)outK
                                                : (__nv_bfloat16*)outV;
            for (int idx = tid; idx < 64*128; idx += 256) {
                int r = idx >> 7, c = idx & 127;
                int m = m0 + half*64 + r;
                int bqi = m >> 10, n = m & 1023;
                int ccx = cbase + c;
                int head = ccx >> 6, d = ccx & 63;
                float val;
                if (region < 2) {
                    if (d < 32) {
                        float x1 = sep[r*EPITCH + c], x2 = sep[r*EPITCH + c + 32];
                        val = x1 * cosp[n*32 + d] - x2 * sinp[n*32 + d];
                    } else {
                        float x2 = sep[r*EPITCH + c], x1 = sep[r*EPITCH + c - 32];
                        int dd = d - 32;
                        val = x2 * cosp[n*32 + dd] + x1 * sinp[n*32 + dd];
                    }
                } else {
                    val = sep[r*EPITCH + c];
                }
                __nv_bfloat16 hv = __float2bfloat16(val);
                __nv_bfloat16 lv = __float2bfloat16(val - __bfloat162float(hv));
                size_t row = ((size_t)bqi * Hh + head) * Nn + n;
                base[row*128 + d]      = hv;
                base[row*128 + 64 + d] = lv;
            }
        } else {
            float* outp = (float*)outQ;
            for (int idx = tid; idx < 64*128; idx += 256) {
                int r = idx >> 7, c = idx & 127;
                int m = m0 + half*64 + r;
                size_t o = (size_t)m * Dm + n0 + c;
                outp[o] = sep[r*EPITCH + c] + res[o];
            }
        }
        __syncthreads();
    }
}

// -------- flash attn chunk loader: 128 rows x 256B, pitch 272, 256 threads --------
__device__ __forceinline__ void ld_chunk128(uint32_t dst, const __nv_bfloat16* __restrict__ src,
                                            int tok0)
{
    #pragma unroll
    for (int p = 0; p < 8; p++) {
        int e = p * 256 + threadIdx.x;
        int r = e >> 4, s = e & 15;
        cp_async16(dst + r * 272 + s * 16, src + (size_t)(tok0 + r) * 128 + s * 8);
    }
}

// -------- single-pass flash attention: block (b,h,16q), 256 threads, occ 2 --------
__global__ void __launch_bounds__(256, 2)
attn_flash(const __nv_bfloat16* __restrict__ Qc, const __nv_bfloat16* __restrict__ Kc,
           const __nv_bfloat16* __restrict__ Vc, const __half* __restrict__ bias,
           __nv_bfloat16* __restrict__ out)
{
    extern __shared__ char dsm[];
    uint32_t sb = smem_u32(dsm);
    uint32_t qs = sb;
    uint32_t bufA = sb + 4352;
    uint32_t bufB = bufA + 34816;
    float* part = (float*)(dsm + 4352);
    float* mrow = (float*)(dsm + 4352 + 2*34816);
    float* srow = mrow + 128;
    float* Sfin = srow + 128;

    int tid = threadIdx.x, wid = tid >> 5, lane = tid & 31;
    int h = blockIdx.y, b = blockIdx.z;
    int q0 = blockIdx.x * 16;
    size_t bh = ((size_t)b * Hh + h) * Nn;
    const __nv_bfloat16* Kbh = Kc + bh * 128;
    const __nv_bfloat16* Vbh = Vc + bh * 128;
    const __half* biasbh = bias + (((size_t)(b*Hh + h)) << 20);

    {
        int r = tid >> 4, s = tid & 15;
        cp_async16(qs + r*272 + s*16, Qc + (bh + q0 + r) * 128 + s * 8);
    }
    CP_COMMIT();
    ld_chunk128(bufA, Kbh, 0); CP_COMMIT();
    ld_chunk128(bufB, Vbh, 0); CP_COMMIT();

    int r_ = lane >> 2, cl = 2*(lane & 3);

    const __half* bb0 = biasbh + (((size_t)(q0 + r_))     << 10) + wid*16;
    const __half* bb1 = biasbh + (((size_t)(q0 + r_ + 8)) << 10) + wid*16;
    __half2 nb00 = *(const __half2*)(bb0 + cl);
    __half2 nb01 = *(const __half2*)(bb0 + cl + 8);
    __half2 nb10 = *(const __half2*)(bb1 + cl);
    __half2 nb11 = *(const __half2*)(bb1 + cl + 8);

    float m0 = -1e30f, m1 = -1e30f, sum0 = 0.f, sum1 = 0.f;
    float acc[8][4];
    #pragma unroll
    for (int i = 0; i < 8; i++)
        #pragma unroll
        for (int r = 0; r < 4; r++) acc[i][r] = 0.f;
    uint32_t afr[8][4];

    for (int c = 0; c < 8; c++) {
        float2 u00 = __half22float2(nb00), u01 = __half22float2(nb01);
        float2 u10 = __half22float2(nb10), u11 = __half22float2(nb11);
        if (c < 7) {
            int o = (c + 1) * 128;
            nb00 = *(const __half2*)(bb0 + o + cl);
            nb01 = *(const __half2*)(bb0 + o + cl + 8);
            nb10 = *(const __half2*)(bb1 + o + cl);
            nb11 = *(const __half2*)(bb1 + o + cl + 8);
        }
        CP_WAIT1();
        __syncthreads();
        if (c == 0) {
            int gq = lane >> 3, lr = lane & 7;
            uint32_t a_off = qs + (uint32_t)((lr + (gq & 1)*8) * 272 + (gq >> 1)*16);
            #pragma unroll
            for (int kt = 0; kt < 8; kt++) ldsm_x4(a_off + kt*32, afr[kt]);
        }

        float dd0[4] = {0.f,0.f,0.f,0.f}, dd1[4] = {0.f,0.f,0.f,0.f};
        #pragma unroll
        for (int nt = 0; nt < 2; nt++) {
            uint32_t base = bufA + (uint32_t)((wid*16 + nt*8 + (lane & 7)) * 272
                                              + ((lane >> 3) & 1) * 16);
            uint32_t kfh[8], kfl[8];
            #pragma unroll
            for (int jj = 0; jj < 4; jj++) ldsm_x2(base + jj*32, kfh + 2*jj);
            #pragma unroll
            for (int jj = 0; jj < 4; jj++) ldsm_x2(base + 128 + jj*32, kfl + 2*jj);
            float* d = nt ? dd1 : dd0;
            #pragma unroll
            for (int t = 0; t < 4; t++) mma16816(d, afr[t],   kfh + 2*t);
            #pragma unroll
            for (int t = 0; t < 4; t++) mma16816(d, afr[t],   kfl + 2*t);
            #pragma unroll
            for (int t = 0; t < 4; t++) mma16816(d, afr[4+t], kfh + 2*t);
        }
        dd0[0] = fmaf(dd0[0], 0.125f, u00.x); dd0[1] = fmaf(dd0[1], 0.125f, u00.y);
        dd0[2] = fmaf(dd0[2], 0.125f, u10.x); dd0[3] = fmaf(dd0[3], 0.125f, u10.y);
        dd1[0] = fmaf(dd1[0], 0.125f, u01.x); dd1[1] = fmaf(dd1[1], 0.125f, u01.y);
        dd1[2] = fmaf(dd1[2], 0.125f, u11.x); dd1[3] = fmaf(dd1[3], 0.125f, u11.y);

        float rm0 = fmaxf(fmaxf(dd0[0], dd0[1]), fmaxf(dd1[0], dd1[1]));
        float rm1 = fmaxf(fmaxf(dd0[2], dd0[3]), fmaxf(dd1[2], dd1[3]));
        rm0 = fmaxf(rm0, __shfl_xor_sync(~0u, rm0, 1));
        rm0 = fmaxf(rm0, __shfl_xor_sync(~0u, rm0, 2));
        rm1 = fmaxf(rm1, __shfl_xor_sync(~0u, rm1, 1));
        rm1 = fmaxf(rm1, __shfl_xor_sync(~0u, rm1, 2));
        float M0 = fmaxf(m0, rm0), M1 = fmaxf(m1, rm1);
        float sc0 = fexp(m0 - M0), sc1 = fexp(m1 - M1);
        dd0[0] = fexp(dd0[0] - M0); dd0[1] = fexp(dd0[1] - M0);
        dd0[2] = fexp(dd0[2] - M1); dd0[3] = fexp(dd0[3] - M1);
        dd1[0] = fexp(dd1[0] - M0); dd1[1] = fexp(dd1[1] - M0);
        dd1[2] = fexp(dd1[2] - M1); dd1[3] = fexp(dd1[3] - M1);
        float ps0 = dd0[0] + dd0[1] + dd1[0] + dd1[1];
        float ps1 = dd0[2] + dd0[3] + dd1[2] + dd1[3];
        ps0 += __shfl_xor_sync(~0u, ps0, 1); ps0 += __shfl_xor_sync(~0u, ps0, 2);
        ps1 += __shfl_xor_sync(~0u, ps1, 1); ps1 += __shfl_xor_sync(~0u, ps1, 2);
        sum0 = sum0 * sc0 + ps0;
        sum1 = sum1 * sc1 + ps1;
        m0 = M0; m1 = M1;
        #pragma unroll
        for (int i = 0; i < 8; i++) {
            acc[i][0] *= sc0; acc[i][1] *= sc0;
            acc[i][2] *= sc1; acc[i][3] *= sc1;
        }
        uint32_t phi[4], plo[4];
        psplit(dd0[0], dd0[1], phi[0], plo[0]);
        psplit(dd0[2], dd0[3], phi[1], plo[1]);
        psplit(dd1[0], dd1[1], phi[2], plo[2]);
        psplit(dd1[2], dd1[3], phi[3], plo[3]);

        __syncthreads();
        if (c < 7) { ld_chunk128(bufA, Kbh, (c + 1) * 128); CP_COMMIT(); CP_WAIT1(); }
        else       { CP_WAIT0(); }
        __syncthreads();

        #pragma unroll
        for (int hd = 0; hd < 2; hd++) {
            uint32_t vaddr = bufB + (uint32_t)((wid*16 + ((lane >> 3) & 1)*8 + (lane & 7)) * 272
                                               + ((lane >> 4) & 1) * 16 + hd*64);
            uint32_t vfh[4][2], vfl[4][2];
            #pragma unroll
            for (int p = 0; p < 2; p++) {
                uint32_t r4[4];
                ldsm_x4t(vaddr + p*32, r4);
                vfh[2*p][0] = r4[0]; vfh[2*p][1] = r4[1];
                vfh[2*p+1][0] = r4[2]; vfh[2*p+1][1] = r4[3];
                ldsm_x4t(vaddr + 128 + p*32, r4);
                vfl[2*p][0] = r4[0]; vfl[2*p][1] = r4[1];
                vfl[2*p+1][0] = r4[2]; vfl[2*p+1][1] = r4[3];
            }
            #pragma unroll
            for (int nt = 0; nt < 4; nt++) {
                mma16816(acc[hd*4 + nt], phi, vfh[nt]);
                mma16816(acc[hd*4 + nt], phi, vfl[nt]);
                mma16816(acc[hd*4 + nt], plo, vfh[nt]);
            }
        }
        __syncthreads();
        if (c < 7) { ld_chunk128(bufB, Vbh, (c + 1) * 128); CP_COMMIT(); }
    }

    // ---- flash merge across 8 warps ----
    if ((lane & 3) == 0) {
        mrow[wid*16 + r_]     = m0;  srow[wid*16 + r_]     = sum0;
        mrow[wid*16 + r_ + 8] = m1;  srow[wid*16 + r_ + 8] = sum1;
    }
    __syncthreads();
    float M0g = -1e30f, M1g = -1e30f;
    #pragma unroll
    for (int w = 0; w < 8; w++) {
        M0g = fmaxf(M0g, mrow[w*16 + r_]);
        M1g = fmaxf(M1g, mrow[w*16 + r_ + 8]);
    }
    float S0g = 0.f, S1g = 0.f;
    #pragma unroll
    for (int w = 0; w < 8; w++) {
        S0g += srow[w*16 + r_]     * fexp(mrow[w*16 + r_]     - M0g);
        S1g += srow[w*16 + r_ + 8] * fexp(mrow[w*16 + r_ + 8] - M1g);
    }
    if (wid == 0 && (lane & 3) == 0) { Sfin[r_] = S0g; Sfin[r_ + 8] = S1g; }
    float f0 = fexp(m0 - M0g), f1 = fexp(m1 - M1g);
    #pragma unroll
    for (int i = 0; i < 8; i++) {
        int hd = i >> 2, nt = i & 3;
        int d = hd*32 + nt*8 + cl;
        *(float2*)(part + wid*1024 + r_*64 + d) =
            make_float2(acc[i][0] * f0, acc[i][1] * f0);
        *(float2*)(part + wid*1024 + (r_+8)*64 + d) =
            make_float2(acc[i][2] * f1, acc[i][3] * f1);
    }
    __syncthreads();
    for (int o = tid; o < 1024; o += 256) {
        float s = 0.f;
        #pragma unroll
        for (int w = 0; w < 8; w++) s += part[w*1024 + o];
        int qi = o >> 6, d = o & 63;
        s /= Sfin[qi];
        int col = h * 64 + d;
        split3(out + (size_t)(b * Nn + q0 + qi) * KCAT + col, s);
    }
}

// -------------------- launch --------------------
extern "C" void kernel_launch(void* const* d_in, const int* in_sizes, int n_in,
                              void* d_out, int out_size)
{
    const float* node = (const float*)d_in[0];
    const float* adj  = (const float*)d_in[1];
    const float* wd   = (const float*)d_in[2];
    const float* bear = (const float*)d_in[3];
    const float* Wq   = (const float*)d_in[4];
    const float* Wk   = (const float*)d_in[5];
    const float* Wv   = (const float*)d_in[6];
    const float* Wo   = (const float*)d_in[7];
    const float* lng  = (const float*)d_in[8];
    const float* lnb  = (const float*)d_in[9];
    const float* ww   = (const float*)d_in[10];
    const float* wbv  = (const float*)d_in[11];
    float* out = (float*)d_out;

    __nv_bfloat16 *xcat, *wqkv, *wocat, *aocat, *Qc, *Kc, *Vc;
    __half* biasp;
    float *cosp, *sinp;
    cudaGetSymbolAddress((void**)&xcat,  g_xcat);
    cudaGetSymbolAddress((void**)&wqkv,  g_wqkv);
    cudaGetSymbolAddress((void**)&wocat, g_wocat);
    cudaGetSymbolAddress((void**)&aocat, g_aocat);
    cudaGetSymbolAddress((void**)&Qc,    g_Qc);
    cudaGetSymbolAddress((void**)&Kc,    g_Kc);
    cudaGetSymbolAddress((void**)&Vc,    g_Vc);
    cudaGetSymbolAddress((void**)&biasp, g_bias);
    cudaGetSymbolAddress((void**)&cosp,  g_cos);
    cudaGetSymbolAddress((void**)&sinp,  g_sin);

    const int SMEM_GEMM = 3 * STG;                                // 110592
    const int SMEM_ATTN = 4352 + 2*34816 + (128 + 128 + 16) * 4;  // 75136
    cudaFuncSetAttribute(gemm_mma<0>, cudaFuncAttributeMaxDynamicSharedMemorySize, SMEM_GEMM);
    cudaFuncSetAttribute(gemm_mma<1>, cudaFuncAttributeMaxDynamicSharedMemorySize, SMEM_GEMM);
    cudaFuncSetAttribute(attn_flash,  cudaFuncAttributeMaxDynamicSharedMemorySize, SMEM_ATTN);

    // 1: mega prep (transposed weight packs + rope + layernorm + bias)
    prep_kernel<<<NBT_W + NBT_WO + NBT_ROPE + NBT_LN + NBT_BIAS, 256>>>(
        Wq, Wk, Wv, Wo, node, lng, lnb, bear, wd, adj, ww, wbv,
        wqkv, wocat, cosp, sinp, xcat, biasp);
    // 2: fused QKV GEMM (RoPE + bf16 split rows in epilogue)
    gemm_mma<0><<<dim3(KCAT/128, BN/128), 256, SMEM_GEMM>>>(xcat, wqkv, cosp, sinp,
                                                            nullptr, Qc, Kc, Vc);
    // 3: flash attention
    attn_flash<<<dim3(Nn/16, Hh, Bq), 256, SMEM_ATTN>>>(Qc, Kc, Vc, biasp, aocat);
    // 4: O-proj + residual
    gemm_mma<1><<<dim3(Dm/128, BN/128), 256, SMEM_GEMM>>>(aocat, wocat, cosp, sinp,
                                                          node, out, nullptr, nullptr);
}

// round 15
// speedup vs baseline: 1.5164x; 1.0931x over previous
#include <cuda_runtime.h>
#include <cuda_bf16.h>
#include <cuda_fp16.h>
#include <math.h>
#include <stdint.h>

#define Bq   8
#define Nn   1024
#define Dm   896
#define Hh   14
#define Dh   64
#define BN   (Bq*Nn)
#define KCAT 2688
#define EPITCH 132
#define APITCH 144
#define STG   36864
#define VPITCH 144          // attn V buffer row pitch (128B f16 row + 16B pad)

__device__ __align__(128) __nv_bfloat16 g_xcat[(size_t)BN*KCAT];
__device__ __align__(128) __nv_bfloat16 g_wqkv[(size_t)KCAT*KCAT];
__device__ __align__(128) __nv_bfloat16 g_wocat[(size_t)Dm*KCAT];
__device__ __align__(128) __nv_bfloat16 g_aocat[(size_t)BN*KCAT];
__device__ __align__(128) __nv_bfloat16 g_Qc[(size_t)Bq*Hh*Nn*128];
__device__ __align__(128) __nv_bfloat16 g_Kc[(size_t)Bq*Hh*Nn*128];
__device__ __align__(128) __half       g_Vf[(size_t)Bq*Hh*Nn*64];   // V plain f16
__device__ __half g_bias[(size_t)Bq*Hh*Nn*Nn];
__device__ float g_cos[Nn*32];
__device__ float g_sin[Nn*32];

__device__ __forceinline__ uint32_t smem_u32(const void* p) {
    uint32_t a;
    asm("{ .reg .u64 t; cvta.to.shared.u64 t, %1; cvt.u32.u64 %0, t; }" : "=r"(a) : "l"(p));
    return a;
}
__device__ __forceinline__ void cp_async16(uint32_t dst, const void* src) {
    asm volatile("cp.async.cg.shared.global [%0], [%1], 16;" :: "r"(dst), "l"(src));
}
#define CP_COMMIT() asm volatile("cp.async.commit_group;" ::: "memory")
#define CP_WAIT0()  asm volatile("cp.async.wait_group 0;" ::: "memory")
#define CP_WAIT1()  asm volatile("cp.async.wait_group 1;" ::: "memory")

__device__ __forceinline__ void ldsm_x4(uint32_t a, uint32_t* r) {
    asm volatile("ldmatrix.sync.aligned.m8n8.x4.shared.b16 {%0,%1,%2,%3}, [%4];"
                 : "=r"(r[0]), "=r"(r[1]), "=r"(r[2]), "=r"(r[3]) : "r"(a));
}
__device__ __forceinline__ void ldsm_x2(uint32_t a, uint32_t* r) {
    asm volatile("ldmatrix.sync.aligned.m8n8.x2.shared.b16 {%0,%1}, [%2];"
                 : "=r"(r[0]), "=r"(r[1]) : "r"(a));
}
__device__ __forceinline__ void ldsm_x4t(uint32_t a, uint32_t* r) {
    asm volatile("ldmatrix.sync.aligned.m8n8.x4.trans.shared.b16 {%0,%1,%2,%3}, [%4];"
                 : "=r"(r[0]), "=r"(r[1]), "=r"(r[2]), "=r"(r[3]) : "r"(a));
}
__device__ __forceinline__ void mma16816(float* c, const uint32_t* a, const uint32_t* b) {
    asm volatile("mma.sync.aligned.m16n8k16.row.col.f32.bf16.bf16.f32 "
                 "{%0,%1,%2,%3},{%4,%5,%6,%7},{%8,%9},{%0,%1,%2,%3};"
                 : "+f"(c[0]), "+f"(c[1]), "+f"(c[2]), "+f"(c[3])
                 : "r"(a[0]), "r"(a[1]), "r"(a[2]), "r"(a[3]), "r"(b[0]), "r"(b[1]));
}
__device__ __forceinline__ void mma16816h(float* c, const uint32_t* a, const uint32_t* b) {
    asm volatile("mma.sync.aligned.m16n8k16.row.col.f32.f16.f16.f32 "
                 "{%0,%1,%2,%3},{%4,%5,%6,%7},{%8,%9},{%0,%1,%2,%3};"
                 : "+f"(c[0]), "+f"(c[1]), "+f"(c[2]), "+f"(c[3])
                 : "r"(a[0]), "r"(a[1]), "r"(a[2]), "r"(a[3]), "r"(b[0]), "r"(b[1]));
}
__device__ __forceinline__ uint32_t packbf(float lo, float hi) {
    uint32_t r; asm("cvt.rn.bf16x2.f32 %0, %1, %2;" : "=r"(r) : "f"(hi), "f"(lo)); return r;
}
__device__ __forceinline__ uint32_t packh(float lo, float hi) {
    uint32_t r; asm("cvt.rn.f16x2.f32 %0, %1, %2;" : "=r"(r) : "f"(hi), "f"(lo)); return r;
}

__device__ __forceinline__ float fexp(float x) {
    x = fmaxf(x, -80.f);
    float y = x * 1.442695041f;
    float n = rintf(y);
    float f = y - n;
    float p =            1.8775767e-3f;
    p = fmaf(p, f, 8.9893397e-3f);
    p = fmaf(p, f, 5.5826318e-2f);
    p = fmaf(p, f, 2.4015361e-1f);
    p = fmaf(p, f, 6.9315308e-1f);
    p = fmaf(p, f, 9.9999994e-1f);
    return __int_as_float(__float_as_int(p) + ((int)n << 23));
}
__device__ __forceinline__ float ftanh(float x) {
    float ax = fabsf(x);
    float e = fexp(-2.f * ax);
    float d = 1.f + e;
    float r = fmaf(-0.5f, d, 1.4571f);
    r = r * fmaf(-d, r, 2.f);
    r = r * fmaf(-d, r, 2.f);
    float t = (1.f - e) * r;
    return (x >= 0.f) ? t : -t;
}
__device__ __forceinline__ void split3(__nv_bfloat16* p, float v) {
    __nv_bfloat16 hi = __float2bfloat16(v);
    __nv_bfloat16 lo = __float2bfloat16(v - __bfloat162float(hi));
    p[0] = hi; p[Dm] = hi; p[2*Dm] = lo;
}

// -------- mega prep: transposed weight packs + rope + layernorm + bias --------
#define NBT_W   2352
#define NBT_WO  784
#define NBT_ROPE 128
#define NBT_LN  BN
#define NBT_BIAS 8192
__global__ void prep_kernel(const float* __restrict__ Wq, const float* __restrict__ Wk,
                            const float* __restrict__ Wv, const float* __restrict__ Wo,
                            const float* __restrict__ x, const float* __restrict__ lng,
                            const float* __restrict__ lnb,
                            const float* __restrict__ bear, const float* __restrict__ wd,
                            const float* __restrict__ adj, const float* __restrict__ ww,
                            const float* __restrict__ wbv,
                            __nv_bfloat16* __restrict__ wqkv, __nv_bfloat16* __restrict__ wocat,
                            float* __restrict__ cc, float* __restrict__ ss,
                            __nv_bfloat16* __restrict__ y, __half* __restrict__ bias)
{
    __shared__ float tile[32][33];
    __shared__ float w0s[Hh], w1s[Hh], wbs[Hh];
    __shared__ float ws[8], ws2[8];

    int bid = blockIdx.x, tid = threadIdx.x;
    int j = tid & 31, i = tid >> 5;

    if (bid < NBT_W) {
        int region = bid / 784;
        int tt = bid % 784;
        int k0 = (tt / 28) * 32, c0 = (tt % 28) * 32;
        const float* W = (region == 0) ? Wq : ((region == 1) ? Wk : Wv);
        #pragma unroll
        for (int p = 0; p < 4; p++)
            tile[i + p*8][j] = W[(size_t)(k0 + i + p*8) * Dm + c0 + j];
        __syncthreads();
        #pragma unroll
        for (int p = 0; p < 4; p++) {
            int ii = i + p*8;
            float w = tile[j][ii];
            __nv_bfloat16 hi = __float2bfloat16(w);
            __nv_bfloat16 lo = __float2bfloat16(w - __bfloat162float(hi));
            size_t rowo = (size_t)(region*Dm + c0 + ii) * KCAT + (k0 + j);
            wqkv[rowo]          = hi;
            wqkv[rowo + Dm]     = lo;
            wqkv[rowo + 2*Dm]   = hi;
        }
    } else if (bid < NBT_W + NBT_WO) {
        int tt = bid - NBT_W;
        int k0 = (tt / 28) * 32, c0 = (tt % 28) * 32;
        #pragma unroll
        for (int p = 0; p < 4; p++)
            tile[i + p*8][j] = Wo[(size_t)(k0 + i + p*8) * Dm + c0 + j];
        __syncthreads();
        #pragma unroll
        for (int p = 0; p < 4; p++) {
            int ii = i + p*8;
            float w = tile[j][ii];
            __nv_bfloat16 hi = __float2bfloat16(w);
            __nv_bfloat16 lo = __float2bfloat16(w - __bfloat162float(hi));
            size_t rowo = (size_t)(c0 + ii) * KCAT + (k0 + j);
            wocat[rowo]        = hi;
            wocat[rowo + Dm]   = lo;
            wocat[rowo + 2*Dm] = hi;
        }
    } else if (bid < NBT_W + NBT_WO + NBT_ROPE) {
        int e = (bid - NBT_W - NBT_WO) * 256 + tid;
        int n = e >> 5, d = e & 31;
        float freq = (float)n * powf(10000.f, -(float)(2*d) / 64.f);
        cc[e] = cosf(freq);
        ss[e] = sinf(freq);
    } else if (bid < NBT_W + NBT_WO + NBT_ROPE + NBT_LN) {
        int row = bid - (NBT_W + NBT_WO + NBT_ROPE);
        const float* xr = x + (size_t)row * Dm;
        float s = 0.f, s2 = 0.f;
        for (int e = tid; e < Dm; e += 256) { float v = xr[e]; s += v; s2 += v*v; }
        #pragma unroll
        for (int o = 16; o; o >>= 1) { s += __shfl_xor_sync(~0u, s, o); s2 += __shfl_xor_sync(~0u, s2, o); }
        int w = tid >> 5;
        if ((tid & 31) == 0) { ws[w] = s; ws2[w] = s2; }
        __syncthreads();
        if (tid < 32) {
            s  = (tid < 8) ? ws[tid]  : 0.f;
            s2 = (tid < 8) ? ws2[tid] : 0.f;
            #pragma unroll
            for (int o = 4; o; o >>= 1) { s += __shfl_xor_sync(~0u, s, o); s2 += __shfl_xor_sync(~0u, s2, o); }
            if (tid == 0) { ws[0] = s; ws2[0] = s2; }
        }
        __syncthreads();
        float mu  = ws[0] * (1.f/Dm);
        float var = ws2[0] * (1.f/Dm) - mu*mu;
        float inv = rsqrtf(var + 1e-5f);
        __nv_bfloat16* yr = y + (size_t)row * KCAT;
        for (int e = tid; e < Dm; e += 256) {
            float v = (xr[e] - mu) * inv * lng[e] + lnb[e];
            split3(yr + e, v);
        }
    } else {
        int t = bid - (NBT_W + NBT_WO + NBT_ROPE + NBT_LN);
        int b = t >> 10;
        t &= 1023;
        int q0 = (t >> 5) * 32, k0 = (t & 31) * 32;
        if (tid < Hh) { w0s[tid] = ww[tid]; w1s[tid] = ww[Hh + tid]; wbs[tid] = wbv[tid]; }
        #pragma unroll
        for (int p = 0; p < 4; p++)
            tile[i + p*8][j] = bear[(size_t)(k0 + i + p*8) * Nn + q0 + j];
        __syncthreads();
        #pragma unroll
        for (int p = 0; p < 4; p++) {
            int qi = i + p*8;
            int q = q0 + qi, k = k0 + j;
            float rb = fmodf(tile[j][qi] + 180.f, 360.f);
            float av = cosf((wd[b*Nn + q] - rb) * 0.017453292519943295f);
            float a  = adj[(size_t)q * Nn + k];
            bool on = (a > 0.f);
            size_t base = ((size_t)q << 10) + k;
            #pragma unroll
            for (int h = 0; h < Hh; h++) {
                float bv = on ? ftanh(fmaf(av, w0s[h], fmaf(a, w1s[h], wbs[h]))) : -1e30f;
                bias[(((size_t)(b*Hh + h)) << 20) + base] = __float2half(bv);
            }
        }
    }
}

// -------- gemm stage loader --------
__device__ __forceinline__ void load_stage(uint32_t abase,
                                           const __nv_bfloat16* __restrict__ A,
                                           const __nv_bfloat16* __restrict__ Bw,
                                           int m0, int n0, int k0)
{
    int tid = threadIdx.x;
    uint32_t bbase = abase + 128 * APITCH;
    #pragma unroll
    for (int p = 0; p < 4; p++) {
        int e = p * 256 + tid;
        int r = e >> 3, seg = e & 7;
        cp_async16(abase + r * APITCH + seg * 16, A + (size_t)(m0 + r) * KCAT + k0 + seg * 8);
    }
    #pragma unroll
    for (int p = 0; p < 4; p++) {
        int e = p * 256 + tid;
        int r = e >> 3, seg = e & 7;
        cp_async16(bbase + r * APITCH + seg * 16, Bw + (size_t)(n0 + r) * KCAT + k0 + seg * 8);
    }
}

// -------- mma GEMM, 128x128 tile, K-chunk 64, 3-stage, occ 2 --------
// MODE0 epilogue: Q/K -> bf16 [hi|lo] rows + RoPE; V -> plain f16 rows
template<int MODE>
__global__ void __launch_bounds__(256, 2)
gemm_mma(const __nv_bfloat16* __restrict__ A, const __nv_bfloat16* __restrict__ Bw,
         const float* __restrict__ cosp, const float* __restrict__ sinp,
         const float* __restrict__ res, void* outQ, void* outK, void* outV)
{
    extern __shared__ char dsm[];
    uint32_t sb = smem_u32(dsm);
    float* sep = (float*)dsm;

    int tid = threadIdx.x, wid = tid >> 5, lane = tid & 31;
    int wm = wid >> 2, wn = wid & 3;
    int m0 = blockIdx.y * 128, n0 = blockIdx.x * 128;

    float acc[4][4][4];
    #pragma unroll
    for (int i = 0; i < 4; i++)
        #pragma unroll
        for (int j = 0; j < 4; j++)
            #pragma unroll
            for (int r = 0; r < 4; r++) acc[i][j][r] = 0.f;

    int gq = lane >> 3, lr = lane & 7;
    uint32_t a_off = (uint32_t)((wm*64 + lr + (gq & 1)*8) * APITCH + (gq >> 1)*16);
    uint32_t b_off = (uint32_t)((wn*32 + lr) * APITCH + ((lane & 8) ? 16 : 0) + 128*APITCH);

    load_stage(sb + 0*STG, A, Bw, m0, n0, 0);
    CP_COMMIT();
    load_stage(sb + 1*STG, A, Bw, m0, n0, 64);
    CP_COMMIT();

    const int NT = KCAT / 64;
    int slot = 0;
    for (int i = 0; i < NT; i++) {
        if (i + 1 < NT) CP_WAIT1(); else CP_WAIT0();
        __syncthreads();
        uint32_t stg = sb + slot * STG;
        #pragma unroll
        for (int ks = 0; ks < 4; ks++) {
            uint32_t afr[4][4], bfr[4][2];
            #pragma unroll
            for (int mt = 0; mt < 4; mt++) ldsm_x4(stg + a_off + mt*(16*APITCH) + ks*32, afr[mt]);
            #pragma unroll
            for (int nt = 0; nt < 4; nt++) ldsm_x2(stg + b_off + nt*(8*APITCH) + ks*32, bfr[nt]);
            #pragma unroll
            for (int mt = 0; mt < 4; mt++)
                #pragma unroll
                for (int nt = 0; nt < 4; nt++)
                    mma16816(acc[mt][nt], afr[mt], bfr[nt]);
        }
        if (i + 2 < NT) {
            int ns = slot + 2; if (ns >= 3) ns -= 3;
            load_stage(sb + ns * STG, A, Bw, m0, n0, (i + 2) * 64);
            CP_COMMIT();
        }
        slot++; if (slot == 3) slot = 0;
    }
    __syncthreads();

    #pragma unroll
    for (int half = 0; half < 2; half++) {
        if (wm == half) {
            #pragma unroll
            for (int mt = 0; mt < 4; mt++)
                #pragma unroll
                for (int nt = 0; nt < 4; nt++)
                    #pragma unroll
                    for (int ri = 0; ri < 4; ri++) {
                        int r = mt*16 + (lane >> 2) + ((ri >> 1) * 8);
                        int n = wn*32 + nt*8 + ((lane & 3) * 2) + (ri & 1);
                        sep[r * EPITCH + n] = acc[mt][nt][ri];
                    }
        }
        __syncthreads();

        if (MODE == 0) {
            int tile = blockIdx.x;
            int region = tile / 7;
            int cbase = (tile % 7) * 128;
            for (int idx = tid; idx < 64*128; idx += 256) {
                int r = idx >> 7, c = idx & 127;
                int m = m0 + half*64 + r;
                int bqi = m >> 10, n = m & 1023;
                int ccx = cbase + c;
                int head = ccx >> 6, d = ccx & 63;
                float val;
                if (region < 2) {
                    if (d < 32) {
                        float x1 = sep[r*EPITCH + c], x2 = sep[r*EPITCH + c + 32];
                        val = x1 * cosp[n*32 + d] - x2 * sinp[n*32 + d];
                    } else {
                        float x2 = sep[r*EPITCH + c], x1 = sep[r*EPITCH + c - 32];
                        int dd = d - 32;
                        val = x2 * cosp[n*32 + dd] + x1 * sinp[n*32 + dd];
                    }
                    __nv_bfloat16* base = (region == 0) ? (__nv_bfloat16*)outQ
                                                        : (__nv_bfloat16*)outK;
                    __nv_bfloat16 hv = __float2bfloat16(val);
                    __nv_bfloat16 lv = __float2bfloat16(val - __bfloat162float(hv));
                    size_t row = ((size_t)bqi * Hh + head) * Nn + n;
                    base[row*128 + d]      = hv;
                    base[row*128 + 64 + d] = lv;
                } else {
                    val = sep[r*EPITCH + c];
                    __half* base = (__half*)outV;
                    size_t row = ((size_t)bqi * Hh + head) * Nn + n;
                    base[row*64 + d] = __float2half(val);
                }
            }
        } else {
            float* outp = (float*)outQ;
            for (int idx = tid; idx < 64*128; idx += 256) {
                int r = idx >> 7, c = idx & 127;
                int m = m0 + half*64 + r;
                size_t o = (size_t)m * Dm + n0 + c;
                outp[o] = sep[r*EPITCH + c] + res[o];
            }
        }
        __syncthreads();
    }
}

// -------- attn K loader: 128 rows x 256B (bf16 hi|lo), pitch 272 --------
__device__ __forceinline__ void ld_chunkK(uint32_t dst, const __nv_bfloat16* __restrict__ src,
                                          int tok0)
{
    #pragma unroll
    for (int p = 0; p < 8; p++) {
        int e = p * 256 + threadIdx.x;
        int r = e >> 4, s = e & 15;
        cp_async16(dst + r * 272 + s * 16, src + (size_t)(tok0 + r) * 128 + s * 8);
    }
}
// -------- attn V loader: 128 rows x 128B (f16), pitch 144 --------
__device__ __forceinline__ void ld_chunkV(uint32_t dst, const __half* __restrict__ src,
                                          int tok0)
{
    #pragma unroll
    for (int p = 0; p < 4; p++) {
        int e = p * 256 + threadIdx.x;
        int r = e >> 3, s = e & 7;
        cp_async16(dst + r * VPITCH + s * 16, src + (size_t)(tok0 + r) * 64 + s * 8);
    }
}

// -------- single-pass flash attention: block (b,h,16q), 256 threads, occ 2 --------
// smem: Q 16x272 (4352) | bufA(K) 128x272 (34816) | bufB(V) 128x144 (18432) | merge
__global__ void __launch_bounds__(256, 2)
attn_flash(const __nv_bfloat16* __restrict__ Qc, const __nv_bfloat16* __restrict__ Kc,
           const __half* __restrict__ Vf, const __half* __restrict__ bias,
           __nv_bfloat16* __restrict__ out)
{
    extern __shared__ char dsm[];
    uint32_t sb = smem_u32(dsm);
    uint32_t qs = sb;
    uint32_t bufA = sb + 4352;
    uint32_t bufB = bufA + 34816;
    float* part = (float*)(dsm + 4352);                  // overlays bufA at merge (32KB)
    float* mrow = (float*)(dsm + 4352 + 34816 + 18432);  // [8][16]
    float* srow = mrow + 128;
    float* Sfin = srow + 128;

    int tid = threadIdx.x, wid = tid >> 5, lane = tid & 31;
    int h = blockIdx.y, b = blockIdx.z;
    int q0 = blockIdx.x * 16;
    size_t bh = ((size_t)b * Hh + h) * Nn;
    const __nv_bfloat16* Kbh = Kc + bh * 128;
    const __half* Vbh = Vf + bh * 64;
    const __half* biasbh = bias + (((size_t)(b*Hh + h)) << 20);

    {
        int r = tid >> 4, s = tid & 15;
        cp_async16(qs + r*272 + s*16, Qc + (bh + q0 + r) * 128 + s * 8);
    }
    CP_COMMIT();
    ld_chunkK(bufA, Kbh, 0); CP_COMMIT();
    ld_chunkV(bufB, Vbh, 0); CP_COMMIT();

    int r_ = lane >> 2, cl = 2*(lane & 3);

    const __half* bb0 = biasbh + (((size_t)(q0 + r_))     << 10) + wid*16;
    const __half* bb1 = biasbh + (((size_t)(q0 + r_ + 8)) << 10) + wid*16;
    __half2 nb00 = *(const __half2*)(bb0 + cl);
    __half2 nb01 = *(const __half2*)(bb0 + cl + 8);
    __half2 nb10 = *(const __half2*)(bb1 + cl);
    __half2 nb11 = *(const __half2*)(bb1 + cl + 8);

    float m0 = -1e30f, m1 = -1e30f, sum0 = 0.f, sum1 = 0.f;
    float acc[8][4];
    #pragma unroll
    for (int i = 0; i < 8; i++)
        #pragma unroll
        for (int r = 0; r < 4; r++) acc[i][r] = 0.f;
    uint32_t afr[8][4];

    for (int c = 0; c < 8; c++) {
        float2 u00 = __half22float2(nb00), u01 = __half22float2(nb01);
        float2 u10 = __half22float2(nb10), u11 = __half22float2(nb11);
        if (c < 7) {
            int o = (c + 1) * 128;
            nb00 = *(const __half2*)(bb0 + o + cl);
            nb01 = *(const __half2*)(bb0 + o + cl + 8);
            nb10 = *(const __half2*)(bb1 + o + cl);
            nb11 = *(const __half2*)(bb1 + o + cl + 8);
        }
        CP_WAIT1();              // K_c ready (V_c pending)
        __syncthreads();
        if (c == 0) {
            int gq = lane >> 3, lr = lane & 7;
            uint32_t a_off = qs + (uint32_t)((lr + (gq & 1)*8) * 272 + (gq >> 1)*16);
            #pragma unroll
            for (int kt = 0; kt < 8; kt++) ldsm_x4(a_off + kt*32, afr[kt]);
        }

        // ---- scores (bf16 3-term split) ----
        float dd0[4] = {0.f,0.f,0.f,0.f}, dd1[4] = {0.f,0.f,0.f,0.f};
        #pragma unroll
        for (int nt = 0; nt < 2; nt++) {
            uint32_t base = bufA + (uint32_t)((wid*16 + nt*8 + (lane & 7)) * 272
                                              + ((lane >> 3) & 1) * 16);
            uint32_t kfh[8], kfl[8];
            #pragma unroll
            for (int jj = 0; jj < 4; jj++) ldsm_x2(base + jj*32, kfh + 2*jj);
            #pragma unroll
            for (int jj = 0; jj < 4; jj++) ldsm_x2(base + 128 + jj*32, kfl + 2*jj);
            float* d = nt ? dd1 : dd0;
            #pragma unroll
            for (int t = 0; t < 4; t++) mma16816(d, afr[t],   kfh + 2*t);
            #pragma unroll
            for (int t = 0; t < 4; t++) mma16816(d, afr[t],   kfl + 2*t);
            #pragma unroll
            for (int t = 0; t < 4; t++) mma16816(d, afr[4+t], kfh + 2*t);
        }
        dd0[0] = fmaf(dd0[0], 0.125f, u00.x); dd0[1] = fmaf(dd0[1], 0.125f, u00.y);
        dd0[2] = fmaf(dd0[2], 0.125f, u10.x); dd0[3] = fmaf(dd0[3], 0.125f, u10.y);
        dd1[0] = fmaf(dd1[0], 0.125f, u01.x); dd1[1] = fmaf(dd1[1], 0.125f, u01.y);
        dd1[2] = fmaf(dd1[2], 0.125f, u11.x); dd1[3] = fmaf(dd1[3], 0.125f, u11.y);

        // ---- online softmax ----
        float rm0 = fmaxf(fmaxf(dd0[0], dd0[1]), fmaxf(dd1[0], dd1[1]));
        float rm1 = fmaxf(fmaxf(dd0[2], dd0[3]), fmaxf(dd1[2], dd1[3]));
        rm0 = fmaxf(rm0, __shfl_xor_sync(~0u, rm0, 1));
        rm0 = fmaxf(rm0, __shfl_xor_sync(~0u, rm0, 2));
        rm1 = fmaxf(rm1, __shfl_xor_sync(~0u, rm1, 1));
        rm1 = fmaxf(rm1, __shfl_xor_sync(~0u, rm1, 2));
        float M0 = fmaxf(m0, rm0), M1 = fmaxf(m1, rm1);
        float sc0 = fexp(m0 - M0), sc1 = fexp(m1 - M1);
        dd0[0] = fexp(dd0[0] - M0); dd0[1] = fexp(dd0[1] - M0);
        dd0[2] = fexp(dd0[2] - M1); dd0[3] = fexp(dd0[3] - M1);
        dd1[0] = fexp(dd1[0] - M0); dd1[1] = fexp(dd1[1] - M0);
        dd1[2] = fexp(dd1[2] - M1); dd1[3] = fexp(dd1[3] - M1);
        float ps0 = dd0[0] + dd0[1] + dd1[0] + dd1[1];
        float ps1 = dd0[2] + dd0[3] + dd1[2] + dd1[3];
        ps0 += __shfl_xor_sync(~0u, ps0, 1); ps0 += __shfl_xor_sync(~0u, ps0, 2);
        ps1 += __shfl_xor_sync(~0u, ps1, 1); ps1 += __shfl_xor_sync(~0u, ps1, 2);
        sum0 = sum0 * sc0 + ps0;
        sum1 = sum1 * sc1 + ps1;
        m0 = M0; m1 = M1;
        #pragma unroll
        for (int i = 0; i < 8; i++) {
            acc[i][0] *= sc0; acc[i][1] *= sc0;
            acc[i][2] *= sc1; acc[i][3] *= sc1;
        }
        // P as f16 fragments (single term)
        uint32_t pf[4];
        pf[0] = packh(dd0[0], dd0[1]);
        pf[1] = packh(dd0[2], dd0[3]);
        pf[2] = packh(dd1[0], dd1[1]);
        pf[3] = packh(dd1[2], dd1[3]);

        __syncthreads();                                   // done reading bufA (K_c)
        if (c < 7) { ld_chunkK(bufA, Kbh, (c + 1) * 128); CP_COMMIT(); CP_WAIT1(); }
        else       { CP_WAIT0(); }                         // V_c ready
        __syncthreads();

        // ---- PV (f16 single term) ----
        #pragma unroll
        for (int hd = 0; hd < 2; hd++) {
            uint32_t vaddr = bufB + (uint32_t)((wid*16 + ((lane >> 3) & 1)*8 + (lane & 7)) * VPITCH
                                               + ((lane >> 4) & 1) * 16 + hd*64);
            uint32_t vf[4][2];
            #pragma unroll
            for (int p = 0; p < 2; p++) {
                uint32_t r4[4];
                ldsm_x4t(vaddr + p*32, r4);
                vf[2*p][0] = r4[0]; vf[2*p][1] = r4[1];
                vf[2*p+1][0] = r4[2]; vf[2*p+1][1] = r4[3];
            }
            #pragma unroll
            for (int nt = 0; nt < 4; nt++)
                mma16816h(acc[hd*4 + nt], pf, vf[nt]);
        }
        __syncthreads();                                   // done reading bufB (V_c)
        if (c < 7) { ld_chunkV(bufB, Vbh, (c + 1) * 128); CP_COMMIT(); }
    }

    // ---- flash merge across 8 warps ----
    if ((lane & 3) == 0) {
        mrow[wid*16 + r_]     = m0;  srow[wid*16 + r_]     = sum0;
        mrow[wid*16 + r_ + 8] = m1;  srow[wid*16 + r_ + 8] = sum1;
    }
    __syncthreads();
    float M0g = -1e30f, M1g = -1e30f;
    #pragma unroll
    for (int w = 0; w < 8; w++) {
        M0g = fmaxf(M0g, mrow[w*16 + r_]);
        M1g = fmaxf(M1g, mrow[w*16 + r_ + 8]);
    }
    float S0g = 0.f, S1g = 0.f;
    #pragma unroll
    for (int w = 0; w < 8; w++) {
        S0g += srow[w*16 + r_]     * fexp(mrow[w*16 + r_]     - M0g);
        S1g += srow[w*16 + r_ + 8] * fexp(mrow[w*16 + r_ + 8] - M1g);
    }
    if (wid == 0 && (lane & 3) == 0) { Sfin[r_] = S0g; Sfin[r_ + 8] = S1g; }
    float f0 = fexp(m0 - M0g), f1 = fexp(m1 - M1g);
    #pragma unroll
    for (int i = 0; i < 8; i++) {
        int hd = i >> 2, nt = i & 3;
        int d = hd*32 + nt*8 + cl;
        *(float2*)(part + wid*1024 + r_*64 + d) =
            make_float2(acc[i][0] * f0, acc[i][1] * f0);
        *(float2*)(part + wid*1024 + (r_+8)*64 + d) =
            make_float2(acc[i][2] * f1, acc[i][3] * f1);
    }
    __syncthreads();
    for (int o = tid; o < 1024; o += 256) {
        float s = 0.f;
        #pragma unroll
        for (int w = 0; w < 8; w++) s += part[w*1024 + o];
        int qi = o >> 6, d = o & 63;
        s /= Sfin[qi];
        int col = h * 64 + d;
        split3(out + (size_t)(b * Nn + q0 + qi) * KCAT + col, s);
    }
}

// -------------------- launch --------------------
extern "C" void kernel_launch(void* const* d_in, const int* in_sizes, int n_in,
                              void* d_out, int out_size)
{
    const float* node = (const float*)d_in[0];
    const float* adj  = (const float*)d_in[1];
    const float* wd   = (const float*)d_in[2];
    const float* bear = (const float*)d_in[3];
    const float* Wq   = (const float*)d_in[4];
    const float* Wk   = (const float*)d_in[5];
    const float* Wv   = (const float*)d_in[6];
    const float* Wo   = (const float*)d_in[7];
    const float* lng  = (const float*)d_in[8];
    const float* lnb  = (const float*)d_in[9];
    const float* ww   = (const float*)d_in[10];
    const float* wbv  = (const float*)d_in[11];
    float* out = (float*)d_out;

    __nv_bfloat16 *xcat, *wqkv, *wocat, *aocat, *Qc, *Kc;
    __half *Vf, *biasp;
    float *cosp, *sinp;
    cudaGetSymbolAddress((void**)&xcat,  g_xcat);
    cudaGetSymbolAddress((void**)&wqkv,  g_wqkv);
    cudaGetSymbolAddress((void**)&wocat, g_wocat);
    cudaGetSymbolAddress((void**)&aocat, g_aocat);
    cudaGetSymbolAddress((void**)&Qc,    g_Qc);
    cudaGetSymbolAddress((void**)&Kc,    g_Kc);
    cudaGetSymbolAddress((void**)&Vf,    g_Vf);
    cudaGetSymbolAddress((void**)&biasp, g_bias);
    cudaGetSymbolAddress((void**)&cosp,  g_cos);
    cudaGetSymbolAddress((void**)&sinp,  g_sin);

    const int SMEM_GEMM = 3 * STG;                                   // 110592
    const int SMEM_ATTN = 4352 + 34816 + 18432 + (128+128+16)*4;     // 58688
    cudaFuncSetAttribute(gemm_mma<0>, cudaFuncAttributeMaxDynamicSharedMemorySize, SMEM_GEMM);
    cudaFuncSetAttribute(gemm_mma<1>, cudaFuncAttributeMaxDynamicSharedMemorySize, SMEM_GEMM);
    cudaFuncSetAttribute(attn_flash,  cudaFuncAttributeMaxDynamicSharedMemorySize, SMEM_ATTN);

    prep_kernel<<<NBT_W + NBT_WO + NBT_ROPE + NBT_LN + NBT_BIAS, 256>>>(
        Wq, Wk, Wv, Wo, node, lng, lnb, bear, wd, adj, ww, wbv,
        wqkv, wocat, cosp, sinp, xcat, biasp);
    gemm_mma<0><<<dim3(KCAT/128, BN/128), 256, SMEM_GEMM>>>(xcat, wqkv, cosp, sinp,
                                                            nullptr, Qc, Kc, Vf);
    attn_flash<<<dim3(Nn/16, Hh, Bq), 256, SMEM_ATTN>>>(Qc, Kc, Vf, biasp, aocat);
    gemm_mma<1><<<dim3(Dm/128, BN/128), 256, SMEM_GEMM>>>(aocat, wocat, cosp, sinp,
                                                          node, out, nullptr, nullptr);
}

// round 16
// speedup vs baseline: 1.6931x; 1.1165x over previous
#include <cuda_runtime.h>
#include <cuda_bf16.h>
#include <cuda_fp16.h>
#include <math.h>
#include <stdint.h>

#define Bq   8
#define Nn   1024
#define Dm   896
#define Hh   14
#define Dh   64
#define BN   (Bq*Nn)
#define KCAT 2688
#define EPITCH 132
#define APITCH 144
#define STG   36864
#define VPITCH 144          // attn K/V/Q buffer row pitch (128B f16 row + 16B pad)

__device__ __align__(128) __nv_bfloat16 g_xcat[(size_t)BN*KCAT];
__device__ __align__(128) __nv_bfloat16 g_wqkv[(size_t)KCAT*KCAT];
__device__ __align__(128) __nv_bfloat16 g_wocat[(size_t)Dm*KCAT];
__device__ __align__(128) __nv_bfloat16 g_aocat[(size_t)BN*KCAT];
__device__ __align__(128) __half g_Qf[(size_t)Bq*Hh*Nn*64];   // Q plain f16 (RoPE'd)
__device__ __align__(128) __half g_Kf[(size_t)Bq*Hh*Nn*64];   // K plain f16 (RoPE'd)
__device__ __align__(128) __half g_Vf[(size_t)Bq*Hh*Nn*64];   // V plain f16
__device__ __half g_bias[(size_t)Bq*Hh*Nn*Nn];
__device__ float g_cos[Nn*32];
__device__ float g_sin[Nn*32];

__device__ __forceinline__ uint32_t smem_u32(const void* p) {
    uint32_t a;
    asm("{ .reg .u64 t; cvta.to.shared.u64 t, %1; cvt.u32.u64 %0, t; }" : "=r"(a) : "l"(p));
    return a;
}
__device__ __forceinline__ void cp_async16(uint32_t dst, const void* src) {
    asm volatile("cp.async.cg.shared.global [%0], [%1], 16;" :: "r"(dst), "l"(src));
}
#define CP_COMMIT() asm volatile("cp.async.commit_group;" ::: "memory")
#define CP_WAIT0()  asm volatile("cp.async.wait_group 0;" ::: "memory")
#define CP_WAIT1()  asm volatile("cp.async.wait_group 1;" ::: "memory")

__device__ __forceinline__ void ldsm_x4(uint32_t a, uint32_t* r) {
    asm volatile("ldmatrix.sync.aligned.m8n8.x4.shared.b16 {%0,%1,%2,%3}, [%4];"
                 : "=r"(r[0]), "=r"(r[1]), "=r"(r[2]), "=r"(r[3]) : "r"(a));
}
__device__ __forceinline__ void ldsm_x2(uint32_t a, uint32_t* r) {
    asm volatile("ldmatrix.sync.aligned.m8n8.x2.shared.b16 {%0,%1}, [%2];"
                 : "=r"(r[0]), "=r"(r[1]) : "r"(a));
}
__device__ __forceinline__ void ldsm_x4t(uint32_t a, uint32_t* r) {
    asm volatile("ldmatrix.sync.aligned.m8n8.x4.trans.shared.b16 {%0,%1,%2,%3}, [%4];"
                 : "=r"(r[0]), "=r"(r[1]), "=r"(r[2]), "=r"(r[3]) : "r"(a));
}
__device__ __forceinline__ void mma16816(float* c, const uint32_t* a, const uint32_t* b) {
    asm volatile("mma.sync.aligned.m16n8k16.row.col.f32.bf16.bf16.f32 "
                 "{%0,%1,%2,%3},{%4,%5,%6,%7},{%8,%9},{%0,%1,%2,%3};"
                 : "+f"(c[0]), "+f"(c[1]), "+f"(c[2]), "+f"(c[3])
                 : "r"(a[0]), "r"(a[1]), "r"(a[2]), "r"(a[3]), "r"(b[0]), "r"(b[1]));
}
__device__ __forceinline__ void mma16816h(float* c, const uint32_t* a, const uint32_t* b) {
    asm volatile("mma.sync.aligned.m16n8k16.row.col.f32.f16.f16.f32 "
                 "{%0,%1,%2,%3},{%4,%5,%6,%7},{%8,%9},{%0,%1,%2,%3};"
                 : "+f"(c[0]), "+f"(c[1]), "+f"(c[2]), "+f"(c[3])
                 : "r"(a[0]), "r"(a[1]), "r"(a[2]), "r"(a[3]), "r"(b[0]), "r"(b[1]));
}
__device__ __forceinline__ uint32_t packh(float lo, float hi) {
    uint32_t r; asm("cvt.rn.f16x2.f32 %0, %1, %2;" : "=r"(r) : "f"(hi), "f"(lo)); return r;
}

__device__ __forceinline__ float fexp(float x) {
    x = fmaxf(x, -80.f);
    float y = x * 1.442695041f;
    float n = rintf(y);
    float f = y - n;
    float p =            1.8775767e-3f;
    p = fmaf(p, f, 8.9893397e-3f);
    p = fmaf(p, f, 5.5826318e-2f);
    p = fmaf(p, f, 2.4015361e-1f);
    p = fmaf(p, f, 6.9315308e-1f);
    p = fmaf(p, f, 9.9999994e-1f);
    return __int_as_float(__float_as_int(p) + ((int)n << 23));
}
__device__ __forceinline__ float ftanh(float x) {
    float ax = fabsf(x);
    float e = fexp(-2.f * ax);
    float d = 1.f + e;
    float r = fmaf(-0.5f, d, 1.4571f);
    r = r * fmaf(-d, r, 2.f);
    r = r * fmaf(-d, r, 2.f);
    float t = (1.f - e) * r;
    return (x >= 0.f) ? t : -t;
}
__device__ __forceinline__ void split3(__nv_bfloat16* p, float v) {
    __nv_bfloat16 hi = __float2bfloat16(v);
    __nv_bfloat16 lo = __float2bfloat16(v - __bfloat162float(hi));
    p[0] = hi; p[Dm] = hi; p[2*Dm] = lo;
}

// -------- mega prep: transposed weight packs + rope + layernorm + bias --------
#define NBT_W   2352
#define NBT_WO  784
#define NBT_ROPE 128
#define NBT_LN  BN
#define NBT_BIAS 8192
__global__ void prep_kernel(const float* __restrict__ Wq, const float* __restrict__ Wk,
                            const float* __restrict__ Wv, const float* __restrict__ Wo,
                            const float* __restrict__ x, const float* __restrict__ lng,
                            const float* __restrict__ lnb,
                            const float* __restrict__ bear, const float* __restrict__ wd,
                            const float* __restrict__ adj, const float* __restrict__ ww,
                            const float* __restrict__ wbv,
                            __nv_bfloat16* __restrict__ wqkv, __nv_bfloat16* __restrict__ wocat,
                            float* __restrict__ cc, float* __restrict__ ss,
                            __nv_bfloat16* __restrict__ y, __half* __restrict__ bias)
{
    __shared__ float tile[32][33];
    __shared__ float w0s[Hh], w1s[Hh], wbs[Hh];
    __shared__ float ws[8], ws2[8];

    int bid = blockIdx.x, tid = threadIdx.x;
    int j = tid & 31, i = tid >> 5;

    if (bid < NBT_W) {
        int region = bid / 784;
        int tt = bid % 784;
        int k0 = (tt / 28) * 32, c0 = (tt % 28) * 32;
        const float* W = (region == 0) ? Wq : ((region == 1) ? Wk : Wv);
        #pragma unroll
        for (int p = 0; p < 4; p++)
            tile[i + p*8][j] = W[(size_t)(k0 + i + p*8) * Dm + c0 + j];
        __syncthreads();
        #pragma unroll
        for (int p = 0; p < 4; p++) {
            int ii = i + p*8;
            float w = tile[j][ii];
            __nv_bfloat16 hi = __float2bfloat16(w);
            __nv_bfloat16 lo = __float2bfloat16(w - __bfloat162float(hi));
            size_t rowo = (size_t)(region*Dm + c0 + ii) * KCAT + (k0 + j);
            wqkv[rowo]          = hi;
            wqkv[rowo + Dm]     = lo;
            wqkv[rowo + 2*Dm]   = hi;
        }
    } else if (bid < NBT_W + NBT_WO) {
        int tt = bid - NBT_W;
        int k0 = (tt / 28) * 32, c0 = (tt % 28) * 32;
        #pragma unroll
        for (int p = 0; p < 4; p++)
            tile[i + p*8][j] = Wo[(size_t)(k0 + i + p*8) * Dm + c0 + j];
        __syncthreads();
        #pragma unroll
        for (int p = 0; p < 4; p++) {
            int ii = i + p*8;
            float w = tile[j][ii];
            __nv_bfloat16 hi = __float2bfloat16(w);
            __nv_bfloat16 lo = __float2bfloat16(w - __bfloat162float(hi));
            size_t rowo = (size_t)(c0 + ii) * KCAT + (k0 + j);
            wocat[rowo]        = hi;
            wocat[rowo + Dm]   = lo;
            wocat[rowo + 2*Dm] = hi;
        }
    } else if (bid < NBT_W + NBT_WO + NBT_ROPE) {
        int e = (bid - NBT_W - NBT_WO) * 256 + tid;
        int n = e >> 5, d = e & 31;
        float freq = (float)n * powf(10000.f, -(float)(2*d) / 64.f);
        cc[e] = cosf(freq);
        ss[e] = sinf(freq);
    } else if (bid < NBT_W + NBT_WO + NBT_ROPE + NBT_LN) {
        int row = bid - (NBT_W + NBT_WO + NBT_ROPE);
        const float* xr = x + (size_t)row * Dm;
        float s = 0.f, s2 = 0.f;
        for (int e = tid; e < Dm; e += 256) { float v = xr[e]; s += v; s2 += v*v; }
        #pragma unroll
        for (int o = 16; o; o >>= 1) { s += __shfl_xor_sync(~0u, s, o); s2 += __shfl_xor_sync(~0u, s2, o); }
        int w = tid >> 5;
        if ((tid & 31) == 0) { ws[w] = s; ws2[w] = s2; }
        __syncthreads();
        if (tid < 32) {
            s  = (tid < 8) ? ws[tid]  : 0.f;
            s2 = (tid < 8) ? ws2[tid] : 0.f;
            #pragma unroll
            for (int o = 4; o; o >>= 1) { s += __shfl_xor_sync(~0u, s, o); s2 += __shfl_xor_sync(~0u, s2, o); }
            if (tid == 0) { ws[0] = s; ws2[0] = s2; }
        }
        __syncthreads();
        float mu  = ws[0] * (1.f/Dm);
        float var = ws2[0] * (1.f/Dm) - mu*mu;
        float inv = rsqrtf(var + 1e-5f);
        __nv_bfloat16* yr = y + (size_t)row * KCAT;
        for (int e = tid; e < Dm; e += 256) {
            float v = (xr[e] - mu) * inv * lng[e] + lnb[e];
            split3(yr + e, v);
        }
    } else {
        int t = bid - (NBT_W + NBT_WO + NBT_ROPE + NBT_LN);
        int b = t >> 10;
        t &= 1023;
        int q0 = (t >> 5) * 32, k0 = (t & 31) * 32;
        if (tid < Hh) { w0s[tid] = ww[tid]; w1s[tid] = ww[Hh + tid]; wbs[tid] = wbv[tid]; }
        #pragma unroll
        for (int p = 0; p < 4; p++)
            tile[i + p*8][j] = bear[(size_t)(k0 + i + p*8) * Nn + q0 + j];
        __syncthreads();
        #pragma unroll
        for (int p = 0; p < 4; p++) {
            int qi = i + p*8;
            int q = q0 + qi, k = k0 + j;
            float rb = fmodf(tile[j][qi] + 180.f, 360.f);
            float av = cosf((wd[b*Nn + q] - rb) * 0.017453292519943295f);
            float a  = adj[(size_t)q * Nn + k];
            bool on = (a > 0.f);
            size_t base = ((size_t)q << 10) + k;
            #pragma unroll
            for (int h = 0; h < Hh; h++) {
                float bv = on ? ftanh(fmaf(av, w0s[h], fmaf(a, w1s[h], wbs[h]))) : -1e30f;
                bias[(((size_t)(b*Hh + h)) << 20) + base] = __float2half(bv);
            }
        }
    }
}

// -------- gemm stage loader --------
__device__ __forceinline__ void load_stage(uint32_t abase,
                                           const __nv_bfloat16* __restrict__ A,
                                           const __nv_bfloat16* __restrict__ Bw,
                                           int m0, int n0, int k0)
{
    int tid = threadIdx.x;
    uint32_t bbase = abase + 128 * APITCH;
    #pragma unroll
    for (int p = 0; p < 4; p++) {
        int e = p * 256 + tid;
        int r = e >> 3, seg = e & 7;
        cp_async16(abase + r * APITCH + seg * 16, A + (size_t)(m0 + r) * KCAT + k0 + seg * 8);
    }
    #pragma unroll
    for (int p = 0; p < 4; p++) {
        int e = p * 256 + tid;
        int r = e >> 3, seg = e & 7;
        cp_async16(bbase + r * APITCH + seg * 16, Bw + (size_t)(n0 + r) * KCAT + k0 + seg * 8);
    }
}

// -------- mma GEMM, 128x128 tile, K-chunk 64, 3-stage, occ 2 --------
// MODE0 epilogue: Q/K/V -> plain f16 rows (RoPE on Q,K)
template<int MODE>
__global__ void __launch_bounds__(256, 2)
gemm_mma(const __nv_bfloat16* __restrict__ A, const __nv_bfloat16* __restrict__ Bw,
         const float* __restrict__ cosp, const float* __restrict__ sinp,
         const float* __restrict__ res, void* outQ, void* outK, void* outV)
{
    extern __shared__ char dsm[];
    uint32_t sb = smem_u32(dsm);
    float* sep = (float*)dsm;

    int tid = threadIdx.x, wid = tid >> 5, lane = tid & 31;
    int wm = wid >> 2, wn = wid & 3;
    int m0 = blockIdx.y * 128, n0 = blockIdx.x * 128;

    float acc[4][4][4];
    #pragma unroll
    for (int i = 0; i < 4; i++)
        #pragma unroll
        for (int j = 0; j < 4; j++)
            #pragma unroll
            for (int r = 0; r < 4; r++) acc[i][j][r] = 0.f;

    int gq = lane >> 3, lr = lane & 7;
    uint32_t a_off = (uint32_t)((wm*64 + lr + (gq & 1)*8) * APITCH + (gq >> 1)*16);
    uint32_t b_off = (uint32_t)((wn*32 + lr) * APITCH + ((lane & 8) ? 16 : 0) + 128*APITCH);

    load_stage(sb + 0*STG, A, Bw, m0, n0, 0);
    CP_COMMIT();
    load_stage(sb + 1*STG, A, Bw, m0, n0, 64);
    CP_COMMIT();

    const int NT = KCAT / 64;
    int slot = 0;
    for (int i = 0; i < NT; i++) {
        if (i + 1 < NT) CP_WAIT1(); else CP_WAIT0();
        __syncthreads();
        uint32_t stg = sb + slot * STG;
        #pragma unroll
        for (int ks = 0; ks < 4; ks++) {
            uint32_t afr[4][4], bfr[4][2];
            #pragma unroll
            for (int mt = 0; mt < 4; mt++) ldsm_x4(stg + a_off + mt*(16*APITCH) + ks*32, afr[mt]);
            #pragma unroll
            for (int nt = 0; nt < 4; nt++) ldsm_x2(stg + b_off + nt*(8*APITCH) + ks*32, bfr[nt]);
            #pragma unroll
            for (int mt = 0; mt < 4; mt++)
                #pragma unroll
                for (int nt = 0; nt < 4; nt++)
                    mma16816(acc[mt][nt], afr[mt], bfr[nt]);
        }
        if (i + 2 < NT) {
            int ns = slot + 2; if (ns >= 3) ns -= 3;
            load_stage(sb + ns * STG, A, Bw, m0, n0, (i + 2) * 64);
            CP_COMMIT();
        }
        slot++; if (slot == 3) slot = 0;
    }
    __syncthreads();

    #pragma unroll
    for (int half = 0; half < 2; half++) {
        if (wm == half) {
            #pragma unroll
            for (int mt = 0; mt < 4; mt++)
                #pragma unroll
                for (int nt = 0; nt < 4; nt++)
                    #pragma unroll
                    for (int ri = 0; ri < 4; ri++) {
                        int r = mt*16 + (lane >> 2) + ((ri >> 1) * 8);
                        int n = wn*32 + nt*8 + ((lane & 3) * 2) + (ri & 1);
                        sep[r * EPITCH + n] = acc[mt][nt][ri];
                    }
        }
        __syncthreads();

        if (MODE == 0) {
            int tile = blockIdx.x;
            int region = tile / 7;
            int cbase = (tile % 7) * 128;
            __half* base = (region == 0) ? (__half*)outQ
                         : (region == 1) ? (__half*)outK
                                         : (__half*)outV;
            for (int idx = tid; idx < 64*128; idx += 256) {
                int r = idx >> 7, c = idx & 127;
                int m = m0 + half*64 + r;
                int bqi = m >> 10, n = m & 1023;
                int ccx = cbase + c;
                int head = ccx >> 6, d = ccx & 63;
                float val;
                if (region < 2) {
                    if (d < 32) {
                        float x1 = sep[r*EPITCH + c], x2 = sep[r*EPITCH + c + 32];
                        val = x1 * cosp[n*32 + d] - x2 * sinp[n*32 + d];
                    } else {
                        float x2 = sep[r*EPITCH + c], x1 = sep[r*EPITCH + c - 32];
                        int dd = d - 32;
                        val = x2 * cosp[n*32 + dd] + x1 * sinp[n*32 + dd];
                    }
                } else {
                    val = sep[r*EPITCH + c];
                }
                size_t row = ((size_t)bqi * Hh + head) * Nn + n;
                base[row*64 + d] = __float2half(val);
            }
        } else {
            float* outp = (float*)outQ;
            for (int idx = tid; idx < 64*128; idx += 256) {
                int r = idx >> 7, c = idx & 127;
                int m = m0 + half*64 + r;
                size_t o = (size_t)m * Dm + n0 + c;
                outp[o] = sep[r*EPITCH + c] + res[o];
            }
        }
        __syncthreads();
    }
}

// -------- attn chunk loader: 128 rows x 128B f16, pitch 144 --------
__device__ __forceinline__ void ld_chunkF(uint32_t dst, const __half* __restrict__ src,
                                          int tok0)
{
    #pragma unroll
    for (int p = 0; p < 4; p++) {
        int e = p * 256 + threadIdx.x;
        int r = e >> 3, s = e & 7;
        cp_async16(dst + r * VPITCH + s * 16, src + (size_t)(tok0 + r) * 64 + s * 8);
    }
}

// -------- single-pass flash attention: block (b,h,16q), 256 threads, occ 2 --------
// smem: Q 16x144 (2304) | bufA(K) 128x144 (18432) | bufB(V) 128x144 | merge (1088)
__global__ void __launch_bounds__(256, 2)
attn_flash(const __half* __restrict__ Qf, const __half* __restrict__ Kf,
           const __half* __restrict__ Vf, const __half* __restrict__ bias,
           __nv_bfloat16* __restrict__ out)
{
    extern __shared__ char dsm[];
    uint32_t sb = smem_u32(dsm);
    uint32_t qs = sb;
    uint32_t bufA = sb + 2304;
    uint32_t bufB = bufA + 18432;
    float* part = (float*)(dsm + 2304);                  // overlays bufA+bufB at merge (32KB)
    float* mrow = (float*)(dsm + 2304 + 2*18432);        // [8][16]
    float* srow = mrow + 128;
    float* Sfin = srow + 128;

    int tid = threadIdx.x, wid = tid >> 5, lane = tid & 31;
    int h = blockIdx.y, b = blockIdx.z;
    int q0 = blockIdx.x * 16;
    size_t bh = ((size_t)b * Hh + h) * Nn;
    const __half* Qbh = Qf + bh * 64;
    const __half* Kbh = Kf + bh * 64;
    const __half* Vbh = Vf + bh * 64;
    const __half* biasbh = bias + (((size_t)(b*Hh + h)) << 20);

    if (tid < 128) {   // Q tile: 16 rows x 8 segs
        int r = tid >> 3, s = tid & 7;
        cp_async16(qs + r*VPITCH + s*16, Qbh + (size_t)(q0 + r) * 64 + s * 8);
    }
    CP_COMMIT();
    ld_chunkF(bufA, Kbh, 0); CP_COMMIT();
    ld_chunkF(bufB, Vbh, 0); CP_COMMIT();

    int r_ = lane >> 2, cl = 2*(lane & 3);

    const __half* bb0 = biasbh + (((size_t)(q0 + r_))     << 10) + wid*16;
    const __half* bb1 = biasbh + (((size_t)(q0 + r_ + 8)) << 10) + wid*16;
    __half2 nb00 = *(const __half2*)(bb0 + cl);
    __half2 nb01 = *(const __half2*)(bb0 + cl + 8);
    __half2 nb10 = *(const __half2*)(bb1 + cl);
    __half2 nb11 = *(const __half2*)(bb1 + cl + 8);

    float m0 = -1e30f, m1 = -1e30f, sum0 = 0.f, sum1 = 0.f;
    float acc[8][4];
    #pragma unroll
    for (int i = 0; i < 8; i++)
        #pragma unroll
        for (int r = 0; r < 4; r++) acc[i][r] = 0.f;
    uint32_t afr[4][4];

    for (int c = 0; c < 8; c++) {
        float2 u00 = __half22float2(nb00), u01 = __half22float2(nb01);
        float2 u10 = __half22float2(nb10), u11 = __half22float2(nb11);
        if (c < 7) {
            int o = (c + 1) * 128;
            nb00 = *(const __half2*)(bb0 + o + cl);
            nb01 = *(const __half2*)(bb0 + o + cl + 8);
            nb10 = *(const __half2*)(bb1 + o + cl);
            nb11 = *(const __half2*)(bb1 + o + cl + 8);
        }
        CP_WAIT1();              // K_c ready (V_c pending)
        __syncthreads();
        if (c == 0) {            // hoist Q fragments (f16, 4 k-steps)
            int gq = lane >> 3, lr = lane & 7;
            uint32_t a_off = qs + (uint32_t)((lr + (gq & 1)*8) * VPITCH + (gq >> 1)*16);
            #pragma unroll
            for (int kt = 0; kt < 4; kt++) ldsm_x4(a_off + kt*32, afr[kt]);
        }

        // ---- scores (f16 single-term, 8 mma) ----
        float dd0[4] = {0.f,0.f,0.f,0.f}, dd1[4] = {0.f,0.f,0.f,0.f};
        #pragma unroll
        for (int nt = 0; nt < 2; nt++) {
            uint32_t base = bufA + (uint32_t)((wid*16 + nt*8 + (lane & 7)) * VPITCH
                                              + ((lane >> 3) & 1) * 16);
            uint32_t kf[8];
            #pragma unroll
            for (int jj = 0; jj < 4; jj++) ldsm_x2(base + jj*32, kf + 2*jj);
            float* d = nt ? dd1 : dd0;
            #pragma unroll
            for (int t = 0; t < 4; t++) mma16816h(d, afr[t], kf + 2*t);
        }
        dd0[0] = fmaf(dd0[0], 0.125f, u00.x); dd0[1] = fmaf(dd0[1], 0.125f, u00.y);
        dd0[2] = fmaf(dd0[2], 0.125f, u10.x); dd0[3] = fmaf(dd0[3], 0.125f, u10.y);
        dd1[0] = fmaf(dd1[0], 0.125f, u01.x); dd1[1] = fmaf(dd1[1], 0.125f, u01.y);
        dd1[2] = fmaf(dd1[2], 0.125f, u11.x); dd1[3] = fmaf(dd1[3], 0.125f, u11.y);

        // ---- online softmax ----
        float rm0 = fmaxf(fmaxf(dd0[0], dd0[1]), fmaxf(dd1[0], dd1[1]));
        float rm1 = fmaxf(fmaxf(dd0[2], dd0[3]), fmaxf(dd1[2], dd1[3]));
        rm0 = fmaxf(rm0, __shfl_xor_sync(~0u, rm0, 1));
        rm0 = fmaxf(rm0, __shfl_xor_sync(~0u, rm0, 2));
        rm1 = fmaxf(rm1, __shfl_xor_sync(~0u, rm1, 1));
        rm1 = fmaxf(rm1, __shfl_xor_sync(~0u, rm1, 2));
        float M0 = fmaxf(m0, rm0), M1 = fmaxf(m1, rm1);
        float sc0 = fexp(m0 - M0), sc1 = fexp(m1 - M1);
        dd0[0] = fexp(dd0[0] - M0); dd0[1] = fexp(dd0[1] - M0);
        dd0[2] = fexp(dd0[2] - M1); dd0[3] = fexp(dd0[3] - M1);
        dd1[0] = fexp(dd1[0] - M0); dd1[1] = fexp(dd1[1] - M0);
        dd1[2] = fexp(dd1[2] - M1); dd1[3] = fexp(dd1[3] - M1);
        float ps0 = dd0[0] + dd0[1] + dd1[0] + dd1[1];
        float ps1 = dd0[2] + dd0[3] + dd1[2] + dd1[3];
        ps0 += __shfl_xor_sync(~0u, ps0, 1); ps0 += __shfl_xor_sync(~0u, ps0, 2);
        ps1 += __shfl_xor_sync(~0u, ps1, 1); ps1 += __shfl_xor_sync(~0u, ps1, 2);
        sum0 = sum0 * sc0 + ps0;
        sum1 = sum1 * sc1 + ps1;
        m0 = M0; m1 = M1;
        #pragma unroll
        for (int i = 0; i < 8; i++) {
            acc[i][0] *= sc0; acc[i][1] *= sc0;
            acc[i][2] *= sc1; acc[i][3] *= sc1;
        }
        uint32_t pf[4];
        pf[0] = packh(dd0[0], dd0[1]);
        pf[1] = packh(dd0[2], dd0[3]);
        pf[2] = packh(dd1[0], dd1[1]);
        pf[3] = packh(dd1[2], dd1[3]);

        __syncthreads();                                   // done reading bufA (K_c)
        if (c < 7) { ld_chunkF(bufA, Kbh, (c + 1) * 128); CP_COMMIT(); CP_WAIT1(); }
        else       { CP_WAIT0(); }                         // V_c ready
        __syncthreads();

        // ---- PV (f16 single term) ----
        #pragma unroll
        for (int hd = 0; hd < 2; hd++) {
            uint32_t vaddr = bufB + (uint32_t)((wid*16 + ((lane >> 3) & 1)*8 + (lane & 7)) * VPITCH
                                               + ((lane >> 4) & 1) * 16 + hd*64);
            uint32_t vf[4][2];
            #pragma unroll
            for (int p = 0; p < 2; p++) {
                uint32_t r4[4];
                ldsm_x4t(vaddr + p*32, r4);
                vf[2*p][0] = r4[0]; vf[2*p][1] = r4[1];
                vf[2*p+1][0] = r4[2]; vf[2*p+1][1] = r4[3];
            }
            #pragma unroll
            for (int nt = 0; nt < 4; nt++)
                mma16816h(acc[hd*4 + nt], pf, vf[nt]);
        }
        __syncthreads();                                   // done reading bufB (V_c)
        if (c < 7) { ld_chunkF(bufB, Vbh, (c + 1) * 128); CP_COMMIT(); }
    }

    // ---- flash merge across 8 warps ----
    if ((lane & 3) == 0) {
        mrow[wid*16 + r_]     = m0;  srow[wid*16 + r_]     = sum0;
        mrow[wid*16 + r_ + 8] = m1;  srow[wid*16 + r_ + 8] = sum1;
    }
    __syncthreads();
    float M0g = -1e30f, M1g = -1e30f;
    #pragma unroll
    for (int w = 0; w < 8; w++) {
        M0g = fmaxf(M0g, mrow[w*16 + r_]);
        M1g = fmaxf(M1g, mrow[w*16 + r_ + 8]);
    }
    float S0g = 0.f, S1g = 0.f;
    #pragma unroll
    for (int w = 0; w < 8; w++) {
        S0g += srow[w*16 + r_]     * fexp(mrow[w*16 + r_]     - M0g);
        S1g += srow[w*16 + r_ + 8] * fexp(mrow[w*16 + r_ + 8] - M1g);
    }
    if (wid == 0 && (lane & 3) == 0) { Sfin[r_] = S0g; Sfin[r_ + 8] = S1g; }
    float f0 = fexp(m0 - M0g), f1 = fexp(m1 - M1g);
    #pragma unroll
    for (int i = 0; i < 8; i++) {
        int hd = i >> 2, nt = i & 3;
        int d = hd*32 + nt*8 + cl;
        *(float2*)(part + wid*1024 + r_*64 + d) =
            make_float2(acc[i][0] * f0, acc[i][1] * f0);
        *(float2*)(part + wid*1024 + (r_+8)*64 + d) =
            make_float2(acc[i][2] * f1, acc[i][3] * f1);
    }
    __syncthreads();
    for (int o = tid; o < 1024; o += 256) {
        float s = 0.f;
        #pragma unroll
        for (int w = 0; w < 8; w++) s += part[w*1024 + o];
        int qi = o >> 6, d = o & 63;
        s /= Sfin[qi];
        int col = h * 64 + d;
        split3(out + (size_t)(b * Nn + q0 + qi) * KCAT + col, s);
    }
}

// -------------------- launch --------------------
extern "C" void kernel_launch(void* const* d_in, const int* in_sizes, int n_in,
                              void* d_out, int out_size)
{
    const float* node = (const float*)d_in[0];
    const float* adj  = (const float*)d_in[1];
    const float* wd   = (const float*)d_in[2];
    const float* bear = (const float*)d_in[3];
    const float* Wq   = (const float*)d_in[4];
    const float* Wk   = (const float*)d_in[5];
    const float* Wv   = (const float*)d_in[6];
    const float* Wo   = (const float*)d_in[7];
    const float* lng  = (const float*)d_in[8];
    const float* lnb  = (const float*)d_in[9];
    const float* ww   = (const float*)d_in[10];
    const float* wbv  = (const float*)d_in[11];
    float* out = (float*)d_out;

    __nv_bfloat16 *xcat, *wqkv, *wocat, *aocat;
    __half *Qfp, *Kfp, *Vfp, *biasp;
    float *cosp, *sinp;
    cudaGetSymbolAddress((void**)&xcat,  g_xcat);
    cudaGetSymbolAddress((void**)&wqkv,  g_wqkv);
    cudaGetSymbolAddress((void**)&wocat, g_wocat);
    cudaGetSymbolAddress((void**)&aocat, g_aocat);
    cudaGetSymbolAddress((void**)&Qfp,   g_Qf);
    cudaGetSymbolAddress((void**)&Kfp,   g_Kf);
    cudaGetSymbolAddress((void**)&Vfp,   g_Vf);
    cudaGetSymbolAddress((void**)&biasp, g_bias);
    cudaGetSymbolAddress((void**)&cosp,  g_cos);
    cudaGetSymbolAddress((void**)&sinp,  g_sin);

    const int SMEM_GEMM = 3 * STG;                                   // 110592
    const int SMEM_ATTN = 2304 + 2*18432 + (128+128+16)*4;           // 40256
    cudaFuncSetAttribute(gemm_mma<0>, cudaFuncAttributeMaxDynamicSharedMemorySize, SMEM_GEMM);
    cudaFuncSetAttribute(gemm_mma<1>, cudaFuncAttributeMaxDynamicSharedMemorySize, SMEM_GEMM);
    cudaFuncSetAttribute(attn_flash,  cudaFuncAttributeMaxDynamicSharedMemorySize, SMEM_ATTN);

    prep_kernel<<<NBT_W + NBT_WO + NBT_ROPE + NBT_LN + NBT_BIAS, 256>>>(
        Wq, Wk, Wv, Wo, node, lng, lnb, bear, wd, adj, ww, wbv,
        wqkv, wocat, cosp, sinp, xcat, biasp);
    gemm_mma<0><<<dim3(KCAT/128, BN/128), 256, SMEM_GEMM>>>(xcat, wqkv, cosp, sinp,
                                                            nullptr, Qfp, Kfp, Vfp);
    attn_flash<<<dim3(Nn/16, Hh, Bq), 256, SMEM_ATTN>>>(Qfp, Kfp, Vfp, biasp, aocat);
    gemm_mma<1><<<dim3(Dm/128, BN/128), 256, SMEM_GEMM>>>(aocat, wocat, cosp, sinp,
                                                          node, out, nullptr, nullptr);
}

// round 17
// speedup vs baseline: 2.3099x; 1.3643x over previous
#include <cuda_runtime.h>
#include <cuda_bf16.h>
#include <cuda_fp16.h>
#include <math.h>
#include <stdint.h>

#define Bq   8
#define Nn   1024
#define Dm   896
#define Hh   14
#define Dh   64
#define BN   (Bq*Nn)
#define NCAT 2688           // QKV fused output width
#define EPITCH 132
#define APITCH 144          // gemm stage row pitch (64 f16 = 128B + 16B pad)
#define STG   36864
#define VPITCH 144

__device__ __align__(128) __half g_xcat[(size_t)BN*Dm];       // LN(x), f16
__device__ __align__(128) __half g_wqkv[(size_t)NCAT*Dm];     // [n][k], f16
__device__ __align__(128) __half g_wocat[(size_t)Dm*Dm];      // [n][k], f16
__device__ __align__(128) __half g_aocat[(size_t)BN*Dm];      // attn out, f16
__device__ __align__(128) __half g_Qf[(size_t)Bq*Hh*Nn*64];
__device__ __align__(128) __half g_Kf[(size_t)Bq*Hh*Nn*64];
__device__ __align__(128) __half g_Vf[(size_t)Bq*Hh*Nn*64];
__device__ __half g_bias[(size_t)Bq*Hh*Nn*Nn];
__device__ float g_cos[Nn*32];
__device__ float g_sin[Nn*32];

__device__ __forceinline__ uint32_t smem_u32(const void* p) {
    uint32_t a;
    asm("{ .reg .u64 t; cvta.to.shared.u64 t, %1; cvt.u32.u64 %0, t; }" : "=r"(a) : "l"(p));
    return a;
}
__device__ __forceinline__ void cp_async16(uint32_t dst, const void* src) {
    asm volatile("cp.async.cg.shared.global [%0], [%1], 16;" :: "r"(dst), "l"(src));
}
#define CP_COMMIT() asm volatile("cp.async.commit_group;" ::: "memory")
#define CP_WAIT0()  asm volatile("cp.async.wait_group 0;" ::: "memory")
#define CP_WAIT1()  asm volatile("cp.async.wait_group 1;" ::: "memory")

__device__ __forceinline__ void ldsm_x4(uint32_t a, uint32_t* r) {
    asm volatile("ldmatrix.sync.aligned.m8n8.x4.shared.b16 {%0,%1,%2,%3}, [%4];"
                 : "=r"(r[0]), "=r"(r[1]), "=r"(r[2]), "=r"(r[3]) : "r"(a));
}
__device__ __forceinline__ void ldsm_x2(uint32_t a, uint32_t* r) {
    asm volatile("ldmatrix.sync.aligned.m8n8.x2.shared.b16 {%0,%1}, [%2];"
                 : "=r"(r[0]), "=r"(r[1]) : "r"(a));
}
__device__ __forceinline__ void ldsm_x4t(uint32_t a, uint32_t* r) {
    asm volatile("ldmatrix.sync.aligned.m8n8.x4.trans.shared.b16 {%0,%1,%2,%3}, [%4];"
                 : "=r"(r[0]), "=r"(r[1]), "=r"(r[2]), "=r"(r[3]) : "r"(a));
}
__device__ __forceinline__ void mma16816h(float* c, const uint32_t* a, const uint32_t* b) {
    asm volatile("mma.sync.aligned.m16n8k16.row.col.f32.f16.f16.f32 "
                 "{%0,%1,%2,%3},{%4,%5,%6,%7},{%8,%9},{%0,%1,%2,%3};"
                 : "+f"(c[0]), "+f"(c[1]), "+f"(c[2]), "+f"(c[3])
                 : "r"(a[0]), "r"(a[1]), "r"(a[2]), "r"(a[3]), "r"(b[0]), "r"(b[1]));
}
__device__ __forceinline__ uint32_t packh(float lo, float hi) {
    uint32_t r; asm("cvt.rn.f16x2.f32 %0, %1, %2;" : "=r"(r) : "f"(hi), "f"(lo)); return r;
}

__device__ __forceinline__ float fexp(float x) {
    x = fmaxf(x, -80.f);
    float y = x * 1.442695041f;
    float n = rintf(y);
    float f = y - n;
    float p =            1.8775767e-3f;
    p = fmaf(p, f, 8.9893397e-3f);
    p = fmaf(p, f, 5.5826318e-2f);
    p = fmaf(p, f, 2.4015361e-1f);
    p = fmaf(p, f, 6.9315308e-1f);
    p = fmaf(p, f, 9.9999994e-1f);
    return __int_as_float(__float_as_int(p) + ((int)n << 23));
}
__device__ __forceinline__ float ftanh(float x) {
    float ax = fabsf(x);
    float e = fexp(-2.f * ax);
    float d = 1.f + e;
    float r = fmaf(-0.5f, d, 1.4571f);
    r = r * fmaf(-d, r, 2.f);
    r = r * fmaf(-d, r, 2.f);
    float t = (1.f - e) * r;
    return (x >= 0.f) ? t : -t;
}

// -------- mega prep: transposed weight packs + rope + layernorm + bias --------
#define NBT_W   2352
#define NBT_WO  784
#define NBT_ROPE 128
#define NBT_LN  BN
#define NBT_BIAS 8192
__global__ void prep_kernel(const float* __restrict__ Wq, const float* __restrict__ Wk,
                            const float* __restrict__ Wv, const float* __restrict__ Wo,
                            const float* __restrict__ x, const float* __restrict__ lng,
                            const float* __restrict__ lnb,
                            const float* __restrict__ bear, const float* __restrict__ wd,
                            const float* __restrict__ adj, const float* __restrict__ ww,
                            const float* __restrict__ wbv,
                            __half* __restrict__ wqkv, __half* __restrict__ wocat,
                            float* __restrict__ cc, float* __restrict__ ss,
                            __half* __restrict__ y, __half* __restrict__ bias)
{
    __shared__ float tile[32][33];
    __shared__ float w0s[Hh], w1s[Hh], wbs[Hh];
    __shared__ float ws[8], ws2[8];

    int bid = blockIdx.x, tid = threadIdx.x;
    int j = tid & 31, i = tid >> 5;

    if (bid < NBT_W) {
        int region = bid / 784;
        int tt = bid % 784;
        int k0 = (tt / 28) * 32, c0 = (tt % 28) * 32;
        const float* W = (region == 0) ? Wq : ((region == 1) ? Wk : Wv);
        #pragma unroll
        for (int p = 0; p < 4; p++)
            tile[i + p*8][j] = W[(size_t)(k0 + i + p*8) * Dm + c0 + j];
        __syncthreads();
        #pragma unroll
        for (int p = 0; p < 4; p++) {
            int ii = i + p*8;
            wqkv[(size_t)(region*Dm + c0 + ii) * Dm + (k0 + j)] = __float2half(tile[j][ii]);
        }
    } else if (bid < NBT_W + NBT_WO) {
        int tt = bid - NBT_W;
        int k0 = (tt / 28) * 32, c0 = (tt % 28) * 32;
        #pragma unroll
        for (int p = 0; p < 4; p++)
            tile[i + p*8][j] = Wo[(size_t)(k0 + i + p*8) * Dm + c0 + j];
        __syncthreads();
        #pragma unroll
        for (int p = 0; p < 4; p++) {
            int ii = i + p*8;
            wocat[(size_t)(c0 + ii) * Dm + (k0 + j)] = __float2half(tile[j][ii]);
        }
    } else if (bid < NBT_W + NBT_WO + NBT_ROPE) {
        int e = (bid - NBT_W - NBT_WO) * 256 + tid;
        int n = e >> 5, d = e & 31;
        float freq = (float)n * powf(10000.f, -(float)(2*d) / 64.f);
        cc[e] = cosf(freq);
        ss[e] = sinf(freq);
    } else if (bid < NBT_W + NBT_WO + NBT_ROPE + NBT_LN) {
        int row = bid - (NBT_W + NBT_WO + NBT_ROPE);
        const float* xr = x + (size_t)row * Dm;
        float s = 0.f, s2 = 0.f;
        for (int e = tid; e < Dm; e += 256) { float v = xr[e]; s += v; s2 += v*v; }
        #pragma unroll
        for (int o = 16; o; o >>= 1) { s += __shfl_xor_sync(~0u, s, o); s2 += __shfl_xor_sync(~0u, s2, o); }
        int w = tid >> 5;
        if ((tid & 31) == 0) { ws[w] = s; ws2[w] = s2; }
        __syncthreads();
        if (tid < 32) {
            s  = (tid < 8) ? ws[tid]  : 0.f;
            s2 = (tid < 8) ? ws2[tid] : 0.f;
            #pragma unroll
            for (int o = 4; o; o >>= 1) { s += __shfl_xor_sync(~0u, s, o); s2 += __shfl_xor_sync(~0u, s2, o); }
            if (tid == 0) { ws[0] = s; ws2[0] = s2; }
        }
        __syncthreads();
        float mu  = ws[0] * (1.f/Dm);
        float var = ws2[0] * (1.f/Dm) - mu*mu;
        float inv = rsqrtf(var + 1e-5f);
        __half* yr = y + (size_t)row * Dm;
        for (int e = tid; e < Dm; e += 256) {
            float v = (xr[e] - mu) * inv * lng[e] + lnb[e];
            yr[e] = __float2half(v);
        }
    } else {
        int t = bid - (NBT_W + NBT_WO + NBT_ROPE + NBT_LN);
        int b = t >> 10;
        t &= 1023;
        int q0 = (t >> 5) * 32, k0 = (t & 31) * 32;
        if (tid < Hh) { w0s[tid] = ww[tid]; w1s[tid] = ww[Hh + tid]; wbs[tid] = wbv[tid]; }
        #pragma unroll
        for (int p = 0; p < 4; p++)
            tile[i + p*8][j] = bear[(size_t)(k0 + i + p*8) * Nn + q0 + j];
        __syncthreads();
        #pragma unroll
        for (int p = 0; p < 4; p++) {
            int qi = i + p*8;
            int q = q0 + qi, k = k0 + j;
            float rb = fmodf(tile[j][qi] + 180.f, 360.f);
            float av = cosf((wd[b*Nn + q] - rb) * 0.017453292519943295f);
            float a  = adj[(size_t)q * Nn + k];
            bool on = (a > 0.f);
            size_t base = ((size_t)q << 10) + k;
            #pragma unroll
            for (int h = 0; h < Hh; h++) {
                float bv = on ? ftanh(fmaf(av, w0s[h], fmaf(a, w1s[h], wbs[h]))) : -1e30f;
                bias[(((size_t)(b*Hh + h)) << 20) + base] = __float2half(bv);
            }
        }
    }
}

// -------- gemm stage loader: A 128x64, B 128x64 f16 (pitch 144B), K stride Dm --------
__device__ __forceinline__ void load_stage(uint32_t abase,
                                           const __half* __restrict__ A,
                                           const __half* __restrict__ Bw,
                                           int m0, int n0, int k0)
{
    int tid = threadIdx.x;
    uint32_t bbase = abase + 128 * APITCH;
    #pragma unroll
    for (int p = 0; p < 4; p++) {
        int e = p * 256 + tid;
        int r = e >> 3, seg = e & 7;
        cp_async16(abase + r * APITCH + seg * 16, A + (size_t)(m0 + r) * Dm + k0 + seg * 8);
    }
    #pragma unroll
    for (int p = 0; p < 4; p++) {
        int e = p * 256 + tid;
        int r = e >> 3, seg = e & 7;
        cp_async16(bbase + r * APITCH + seg * 16, Bw + (size_t)(n0 + r) * Dm + k0 + seg * 8);
    }
}

// -------- f16 mma GEMM, 128x128 tile, K=896 (14 chunks of 64), 3-stage, occ 2 --------
// MODE0 epilogue: Q/K/V -> plain f16 rows (RoPE on Q,K)
// MODE1 epilogue: + residual, f32 store
template<int MODE>
__global__ void __launch_bounds__(256, 2)
gemm_mma(const __half* __restrict__ A, const __half* __restrict__ Bw,
         const float* __restrict__ cosp, const float* __restrict__ sinp,
         const float* __restrict__ res, void* outQ, void* outK, void* outV)
{
    extern __shared__ char dsm[];
    uint32_t sb = smem_u32(dsm);
    float* sep = (float*)dsm;

    int tid = threadIdx.x, wid = tid >> 5, lane = tid & 31;
    int wm = wid >> 2, wn = wid & 3;
    int m0 = blockIdx.y * 128, n0 = blockIdx.x * 128;

    float acc[4][4][4];
    #pragma unroll
    for (int i = 0; i < 4; i++)
        #pragma unroll
        for (int j = 0; j < 4; j++)
            #pragma unroll
            for (int r = 0; r < 4; r++) acc[i][j][r] = 0.f;

    int gq = lane >> 3, lr = lane & 7;
    uint32_t a_off = (uint32_t)((wm*64 + lr + (gq & 1)*8) * APITCH + (gq >> 1)*16);
    uint32_t b_off = (uint32_t)((wn*32 + lr) * APITCH + ((lane & 8) ? 16 : 0) + 128*APITCH);

    load_stage(sb + 0*STG, A, Bw, m0, n0, 0);
    CP_COMMIT();
    load_stage(sb + 1*STG, A, Bw, m0, n0, 64);
    CP_COMMIT();

    const int NT = Dm / 64;     // 14
    int slot = 0;
    for (int i = 0; i < NT; i++) {
        if (i + 1 < NT) CP_WAIT1(); else CP_WAIT0();
        __syncthreads();
        uint32_t stg = sb + slot * STG;
        #pragma unroll
        for (int ks = 0; ks < 4; ks++) {
            uint32_t afr[4][4], bfr[4][2];
            #pragma unroll
            for (int mt = 0; mt < 4; mt++) ldsm_x4(stg + a_off + mt*(16*APITCH) + ks*32, afr[mt]);
            #pragma unroll
            for (int nt = 0; nt < 4; nt++) ldsm_x2(stg + b_off + nt*(8*APITCH) + ks*32, bfr[nt]);
            #pragma unroll
            for (int mt = 0; mt < 4; mt++)
                #pragma unroll
                for (int nt = 0; nt < 4; nt++)
                    mma16816h(acc[mt][nt], afr[mt], bfr[nt]);
        }
        if (i + 2 < NT) {
            int ns = slot + 2; if (ns >= 3) ns -= 3;
            load_stage(sb + ns * STG, A, Bw, m0, n0, (i + 2) * 64);
            CP_COMMIT();
        }
        slot++; if (slot == 3) slot = 0;
    }
    __syncthreads();

    #pragma unroll
    for (int half = 0; half < 2; half++) {
        if (wm == half) {
            #pragma unroll
            for (int mt = 0; mt < 4; mt++)
                #pragma unroll
                for (int nt = 0; nt < 4; nt++)
                    #pragma unroll
                    for (int ri = 0; ri < 4; ri++) {
                        int r = mt*16 + (lane >> 2) + ((ri >> 1) * 8);
                        int n = wn*32 + nt*8 + ((lane & 3) * 2) + (ri & 1);
                        sep[r * EPITCH + n] = acc[mt][nt][ri];
                    }
        }
        __syncthreads();

        if (MODE == 0) {
            int tile = blockIdx.x;          // 0..20
            int region = tile / 7;
            int cbase = (tile % 7) * 128;
            __half* base = (region == 0) ? (__half*)outQ
                         : (region == 1) ? (__half*)outK
                                         : (__half*)outV;
            for (int idx = tid; idx < 64*128; idx += 256) {
                int r = idx >> 7, c = idx & 127;
                int m = m0 + half*64 + r;
                int bqi = m >> 10, n = m & 1023;
                int ccx = cbase + c;
                int head = ccx >> 6, d = ccx & 63;
                float val;
                if (region < 2) {
                    if (d < 32) {
                        float x1 = sep[r*EPITCH + c], x2 = sep[r*EPITCH + c + 32];
                        val = x1 * cosp[n*32 + d] - x2 * sinp[n*32 + d];
                    } else {
                        float x2 = sep[r*EPITCH + c], x1 = sep[r*EPITCH + c - 32];
                        int dd = d - 32;
                        val = x2 * cosp[n*32 + dd] + x1 * sinp[n*32 + dd];
                    }
                } else {
                    val = sep[r*EPITCH + c];
                }
                size_t row = ((size_t)bqi * Hh + head) * Nn + n;
                base[row*64 + d] = __float2half(val);
            }
        } else {
            float* outp = (float*)outQ;
            for (int idx = tid; idx < 64*128; idx += 256) {
                int r = idx >> 7, c = idx & 127;
                int m = m0 + half*64 + r;
                size_t o = (size_t)m * Dm + n0 + c;
                outp[o] = sep[r*EPITCH + c] + res[o];
            }
        }
        __syncthreads();
    }
}

// -------- attn chunk loader: 128 rows x 128B f16, pitch 144 --------
__device__ __forceinline__ void ld_chunkF(uint32_t dst, const __half* __restrict__ src,
                                          int tok0)
{
    #pragma unroll
    for (int p = 0; p < 4; p++) {
        int e = p * 256 + threadIdx.x;
        int r = e >> 3, s = e & 7;
        cp_async16(dst + r * VPITCH + s * 16, src + (size_t)(tok0 + r) * 64 + s * 8);
    }
}

// -------- single-pass flash attention: block (b,h,16q), 256 threads, occ 2 --------
__global__ void __launch_bounds__(256, 2)
attn_flash(const __half* __restrict__ Qf, const __half* __restrict__ Kf,
           const __half* __restrict__ Vf, const __half* __restrict__ bias,
           __half* __restrict__ out)
{
    extern __shared__ char dsm[];
    uint32_t sb = smem_u32(dsm);
    uint32_t qs = sb;
    uint32_t bufA = sb + 2304;
    uint32_t bufB = bufA + 18432;
    float* part = (float*)(dsm + 2304);                  // overlays bufA+bufB at merge
    float* mrow = (float*)(dsm + 2304 + 2*18432);
    float* srow = mrow + 128;
    float* Sfin = srow + 128;

    int tid = threadIdx.x, wid = tid >> 5, lane = tid & 31;
    int h = blockIdx.y, b = blockIdx.z;
    int q0 = blockIdx.x * 16;
    size_t bh = ((size_t)b * Hh + h) * Nn;
    const __half* Qbh = Qf + bh * 64;
    const __half* Kbh = Kf + bh * 64;
    const __half* Vbh = Vf + bh * 64;
    const __half* biasbh = bias + (((size_t)(b*Hh + h)) << 20);

    if (tid < 128) {
        int r = tid >> 3, s = tid & 7;
        cp_async16(qs + r*VPITCH + s*16, Qbh + (size_t)(q0 + r) * 64 + s * 8);
    }
    CP_COMMIT();
    ld_chunkF(bufA, Kbh, 0); CP_COMMIT();
    ld_chunkF(bufB, Vbh, 0); CP_COMMIT();

    int r_ = lane >> 2, cl = 2*(lane & 3);

    const __half* bb0 = biasbh + (((size_t)(q0 + r_))     << 10) + wid*16;
    const __half* bb1 = biasbh + (((size_t)(q0 + r_ + 8)) << 10) + wid*16;
    __half2 nb00 = *(const __half2*)(bb0 + cl);
    __half2 nb01 = *(const __half2*)(bb0 + cl + 8);
    __half2 nb10 = *(const __half2*)(bb1 + cl);
    __half2 nb11 = *(const __half2*)(bb1 + cl + 8);

    float m0 = -1e30f, m1 = -1e30f, sum0 = 0.f, sum1 = 0.f;
    float acc[8][4];
    #pragma unroll
    for (int i = 0; i < 8; i++)
        #pragma unroll
        for (int r = 0; r < 4; r++) acc[i][r] = 0.f;
    uint32_t afr[4][4];

    for (int c = 0; c < 8; c++) {
        float2 u00 = __half22float2(nb00), u01 = __half22float2(nb01);
        float2 u10 = __half22float2(nb10), u11 = __half22float2(nb11);
        if (c < 7) {
            int o = (c + 1) * 128;
            nb00 = *(const __half2*)(bb0 + o + cl);
            nb01 = *(const __half2*)(bb0 + o + cl + 8);
            nb10 = *(const __half2*)(bb1 + o + cl);
            nb11 = *(const __half2*)(bb1 + o + cl + 8);
        }
        CP_WAIT1();
        __syncthreads();
        if (c == 0) {
            int gq = lane >> 3, lr = lane & 7;
            uint32_t a_off = qs + (uint32_t)((lr + (gq & 1)*8) * VPITCH + (gq >> 1)*16);
            #pragma unroll
            for (int kt = 0; kt < 4; kt++) ldsm_x4(a_off + kt*32, afr[kt]);
        }

        float dd0[4] = {0.f,0.f,0.f,0.f}, dd1[4] = {0.f,0.f,0.f,0.f};
        #pragma unroll
        for (int nt = 0; nt < 2; nt++) {
            uint32_t base = bufA + (uint32_t)((wid*16 + nt*8 + (lane & 7)) * VPITCH
                                              + ((lane >> 3) & 1) * 16);
            uint32_t kf[8];
            #pragma unroll
            for (int jj = 0; jj < 4; jj++) ldsm_x2(base + jj*32, kf + 2*jj);
            float* d = nt ? dd1 : dd0;
            #pragma unroll
            for (int t = 0; t < 4; t++) mma16816h(d, afr[t], kf + 2*t);
        }
        dd0[0] = fmaf(dd0[0], 0.125f, u00.x); dd0[1] = fmaf(dd0[1], 0.125f, u00.y);
        dd0[2] = fmaf(dd0[2], 0.125f, u10.x); dd0[3] = fmaf(dd0[3], 0.125f, u10.y);
        dd1[0] = fmaf(dd1[0], 0.125f, u01.x); dd1[1] = fmaf(dd1[1], 0.125f, u01.y);
        dd1[2] = fmaf(dd1[2], 0.125f, u11.x); dd1[3] = fmaf(dd1[3], 0.125f, u11.y);

        float rm0 = fmaxf(fmaxf(dd0[0], dd0[1]), fmaxf(dd1[0], dd1[1]));
        float rm1 = fmaxf(fmaxf(dd0[2], dd0[3]), fmaxf(dd1[2], dd1[3]));
        rm0 = fmaxf(rm0, __shfl_xor_sync(~0u, rm0, 1));
        rm0 = fmaxf(rm0, __shfl_xor_sync(~0u, rm0, 2));
        rm1 = fmaxf(rm1, __shfl_xor_sync(~0u, rm1, 1));
        rm1 = fmaxf(rm1, __shfl_xor_sync(~0u, rm1, 2));
        float M0 = fmaxf(m0, rm0), M1 = fmaxf(m1, rm1);
        float sc0 = fexp(m0 - M0), sc1 = fexp(m1 - M1);
        dd0[0] = fexp(dd0[0] - M0); dd0[1] = fexp(dd0[1] - M0);
        dd0[2] = fexp(dd0[2] - M1); dd0[3] = fexp(dd0[3] - M1);
        dd1[0] = fexp(dd1[0] - M0); dd1[1] = fexp(dd1[1] - M0);
        dd1[2] = fexp(dd1[2] - M1); dd1[3] = fexp(dd1[3] - M1);
        float ps0 = dd0[0] + dd0[1] + dd1[0] + dd1[1];
        float ps1 = dd0[2] + dd0[3] + dd1[2] + dd1[3];
        ps0 += __shfl_xor_sync(~0u, ps0, 1); ps0 += __shfl_xor_sync(~0u, ps0, 2);
        ps1 += __shfl_xor_sync(~0u, ps1, 1); ps1 += __shfl_xor_sync(~0u, ps1, 2);
        sum0 = sum0 * sc0 + ps0;
        sum1 = sum1 * sc1 + ps1;
        m0 = M0; m1 = M1;
        #pragma unroll
        for (int i = 0; i < 8; i++) {
            acc[i][0] *= sc0; acc[i][1] *= sc0;
            acc[i][2] *= sc1; acc[i][3] *= sc1;
        }
        uint32_t pf[4];
        pf[0] = packh(dd0[0], dd0[1]);
        pf[1] = packh(dd0[2], dd0[3]);
        pf[2] = packh(dd1[0], dd1[1]);
        pf[3] = packh(dd1[2], dd1[3]);

        __syncthreads();
        if (c < 7) { ld_chunkF(bufA, Kbh, (c + 1) * 128); CP_COMMIT(); CP_WAIT1(); }
        else       { CP_WAIT0(); }
        __syncthreads();

        #pragma unroll
        for (int hd = 0; hd < 2; hd++) {
            uint32_t vaddr = bufB + (uint32_t)((wid*16 + ((lane >> 3) & 1)*8 + (lane & 7)) * VPITCH
                                               + ((lane >> 4) & 1) * 16 + hd*64);
            uint32_t vf[4][2];
            #pragma unroll
            for (int p = 0; p < 2; p++) {
                uint32_t r4[4];
                ldsm_x4t(vaddr + p*32, r4);
                vf[2*p][0] = r4[0]; vf[2*p][1] = r4[1];
                vf[2*p+1][0] = r4[2]; vf[2*p+1][1] = r4[3];
            }
            #pragma unroll
            for (int nt = 0; nt < 4; nt++)
                mma16816h(acc[hd*4 + nt], pf, vf[nt]);
        }
        __syncthreads();
        if (c < 7) { ld_chunkF(bufB, Vbh, (c + 1) * 128); CP_COMMIT(); }
    }

    // ---- flash merge across 8 warps ----
    if ((lane & 3) == 0) {
        mrow[wid*16 + r_]     = m0;  srow[wid*16 + r_]     = sum0;
        mrow[wid*16 + r_ + 8] = m1;  srow[wid*16 + r_ + 8] = sum1;
    }
    __syncthreads();
    float M0g = -1e30f, M1g = -1e30f;
    #pragma unroll
    for (int w = 0; w < 8; w++) {
        M0g = fmaxf(M0g, mrow[w*16 + r_]);
        M1g = fmaxf(M1g, mrow[w*16 + r_ + 8]);
    }
    float S0g = 0.f, S1g = 0.f;
    #pragma unroll
    for (int w = 0; w < 8; w++) {
        S0g += srow[w*16 + r_]     * fexp(mrow[w*16 + r_]     - M0g);
        S1g += srow[w*16 + r_ + 8] * fexp(mrow[w*16 + r_ + 8] - M1g);
    }
    if (wid == 0 && (lane & 3) == 0) { Sfin[r_] = S0g; Sfin[r_ + 8] = S1g; }
    float f0 = fexp(m0 - M0g), f1 = fexp(m1 - M1g);
    #pragma unroll
    for (int i = 0; i < 8; i++) {
        int hd = i >> 2, nt = i & 3;
        int d = hd*32 + nt*8 + cl;
        *(float2*)(part + wid*1024 + r_*64 + d) =
            make_float2(acc[i][0] * f0, acc[i][1] * f0);
        *(float2*)(part + wid*1024 + (r_+8)*64 + d) =
            make_float2(acc[i][2] * f1, acc[i][3] * f1);
    }
    __syncthreads();
    for (int o = tid; o < 1024; o += 256) {
        float s = 0.f;
        #pragma unroll
        for (int w = 0; w < 8; w++) s += part[w*1024 + o];
        int qi = o >> 6, d = o & 63;
        s /= Sfin[qi];
        int col = h * 64 + d;
        out[(size_t)(b * Nn + q0 + qi) * Dm + col] = __float2half(s);
    }
}

// -------------------- launch --------------------
extern "C" void kernel_launch(void* const* d_in, const int* in_sizes, int n_in,
                              void* d_out, int out_size)
{
    const float* node = (const float*)d_in[0];
    const float* adj  = (const float*)d_in[1];
    const float* wd   = (const float*)d_in[2];
    const float* bear = (const float*)d_in[3];
    const float* Wq   = (const float*)d_in[4];
    const float* Wk   = (const float*)d_in[5];
    const float* Wv   = (const float*)d_in[6];
    const float* Wo   = (const float*)d_in[7];
    const float* lng  = (const float*)d_in[8];
    const float* lnb  = (const float*)d_in[9];
    const float* ww   = (const float*)d_in[10];
    const float* wbv  = (const float*)d_in[11];
    float* out = (float*)d_out;

    __half *xcat, *wqkv, *wocat, *aocat, *Qfp, *Kfp, *Vfp, *biasp;
    float *cosp, *sinp;
    cudaGetSymbolAddress((void**)&xcat,  g_xcat);
    cudaGetSymbolAddress((void**)&wqkv,  g_wqkv);
    cudaGetSymbolAddress((void**)&wocat, g_wocat);
    cudaGetSymbolAddress((void**)&aocat, g_aocat);
    cudaGetSymbolAddress((void**)&Qfp,   g_Qf);
    cudaGetSymbolAddress((void**)&Kfp,   g_Kf);
    cudaGetSymbolAddress((void**)&Vfp,   g_Vf);
    cudaGetSymbolAddress((void**)&biasp, g_bias);
    cudaGetSymbolAddress((void**)&cosp,  g_cos);
    cudaGetSymbolAddress((void**)&sinp,  g_sin);

    const int SMEM_GEMM = 3 * STG;                                   // 110592
    const int SMEM_ATTN = 2304 + 2*18432 + (128+128+16)*4;           // 40256
    cudaFuncSetAttribute(gemm_mma<0>, cudaFuncAttributeMaxDynamicSharedMemorySize, SMEM_GEMM);
    cudaFuncSetAttribute(gemm_mma<1>, cudaFuncAttributeMaxDynamicSharedMemorySize, SMEM_GEMM);
    cudaFuncSetAttribute(attn_flash,  cudaFuncAttributeMaxDynamicSharedMemorySize, SMEM_ATTN);

    prep_kernel<<<NBT_W + NBT_WO + NBT_ROPE + NBT_LN + NBT_BIAS, 256>>>(
        Wq, Wk, Wv, Wo, node, lng, lnb, bear, wd, adj, ww, wbv,
        wqkv, wocat, cosp, sinp, xcat, biasp);
    gemm_mma<0><<<dim3(NCAT/128, BN/128), 256, SMEM_GEMM>>>(xcat, wqkv, cosp, sinp,
                                                            nullptr, Qfp, Kfp, Vfp);
    attn_flash<<<dim3(Nn/16, Hh, Bq), 256, SMEM_ATTN>>>(Qfp, Kfp, Vfp, biasp, aocat);
    gemm_mma<1><<<dim3(Dm/128, BN/128), 256, SMEM_GEMM>>>(aocat, wocat, cosp, sinp,
                                                          node, out, nullptr, nullptr);
}